// round 8
// baseline (speedup 1.0000x reference)
#include <cuda_runtime.h>
#include <cuda_bf16.h>
#include <math.h>
#include <stdint.h>

#define SEQ   2048
#define HID   2048
#define HQ    16
#define HKV   4
#define DH    128
#define QBN   32
#define BSZ   64
#define GHD   128
#define INTER 5632
#define NQKV  3072
#define NGU   11264

#define SCALE_INV_SQRT_128 0.08838834764831845f

// ================= helpers =================
__device__ __forceinline__ uint32_t smem_u32(const void* p) {
    uint32_t a;
    asm("{ .reg .u64 t; cvta.to.shared.u64 t, %1; cvt.u32.u64 %0, t; }" : "=r"(a) : "l"(p));
    return a;
}
__device__ __forceinline__ void cp_async16(uint32_t saddr, const void* gptr) {
    asm volatile("cp.async.cg.shared.global [%0], [%1], 16;" :: "r"(saddr), "l"(gptr));
}
__device__ __forceinline__ void cp_commit() { asm volatile("cp.async.commit_group;"); }

#define LDSM_X4(r0, r1, r2, r3, addr) \
    asm volatile("ldmatrix.sync.aligned.m8n8.x4.shared.b16 {%0,%1,%2,%3}, [%4];" \
        : "=r"(r0), "=r"(r1), "=r"(r2), "=r"(r3) : "r"(addr))

#define MMAS8(c, a, b0r, b1r) \
    asm volatile("mma.sync.aligned.m16n8k32.row.col.s32.s8.s8.s32 " \
        "{%0,%1,%2,%3}, {%4,%5,%6,%7}, {%8,%9}, {%0,%1,%2,%3};" \
        : "+r"((c)[0]), "+r"((c)[1]), "+r"((c)[2]), "+r"((c)[3]) \
        : "r"((a)[0]), "r"((a)[1]), "r"((a)[2]), "r"((a)[3]), "r"(b0r), "r"(b1r))

#define MMATF32(c, a, b0r, b1r) \
    asm volatile("mma.sync.aligned.m16n8k8.row.col.f32.tf32.tf32.f32 " \
        "{%0,%1,%2,%3}, {%4,%5,%6,%7}, {%8,%9}, {%0,%1,%2,%3};" \
        : "+f"((c)[0]), "+f"((c)[1]), "+f"((c)[2]), "+f"((c)[3]) \
        : "r"((a)[0]), "r"((a)[1]), "r"((a)[2]), "r"((a)[3]), "r"(b0r), "r"(b1r))

static __device__ __forceinline__ uint32_t sw128(uint32_t o) { return o ^ ((o >> 3) & 0x70); }

__device__ __forceinline__ float tf32r(float v) {
    float r;
    asm("cvt.rna.tf32.f32 %0, %1;" : "=f"(r) : "f"(v));
    return r;
}

__device__ __forceinline__ void quant2(float Q, int8_t* q1o, int8_t* q0o) {
    float q1 = fminf(fmaxf(rintf(Q * 0.0078125f), -127.f), 127.f);
    float q0 = fminf(fmaxf(rintf(Q - 128.f * q1), -127.f), 127.f);
    *q1o = (int8_t)(int)q1;
    *q0o = (int8_t)(int)q0;
}

// ================= device scratch =================
__device__ float g_qkv [SEQ*NQKV];
__device__ float g_qp  [QBN*HQ*DH];
__device__ float g_kp  [QBN*HKV*DH];
__device__ float g_qg  [QBN*HQ*GHD];
__device__ float g_kg  [QBN*HKV*GHD];
__device__ unsigned char g_keep[HQ*QBN*QBN];
__device__ float g_o   [SEQ*HID];
__device__ float g_h2  [SEQ*HID];
__device__ float g_gu  [SEQ*NGU];

// int8 limb buffers ([.., 2K] = [q1 | q0]) + scales
__device__ int8_t g_Wqkv8[NQKV*2*HID];   __device__ float g_sWqkv[NQKV];
__device__ int8_t g_Wo8  [HID*2*HID];    __device__ float g_sWo  [HID];
__device__ int8_t g_Wgu8 [NGU*2*HID];    __device__ float g_sWgu [NGU];
__device__ int8_t g_Wd8  [HID*2*INTER];  __device__ float g_sWd  [HID];
__device__ int8_t g_ha8  [SEQ*2*HID];    __device__ float g_sHA  [SEQ];
__device__ int8_t g_oa8  [SEQ*2*HID];    __device__ float g_sO   [SEQ];
__device__ int8_t g_h38  [SEQ*2*HID];    __device__ float g_sH3  [SEQ];
__device__ int8_t g_gt8  [SEQ*2*INTER];  __device__ float g_sGT  [SEQ];

// ===== side-stream resources (created pre-main in static init) =====
struct AuxRes {
    cudaStream_t s2;
    cudaEvent_t root, evQKV, evWo, evGU, evWd;
    AuxRes() {
        cudaStreamCreateWithFlags(&s2, cudaStreamNonBlocking);
        cudaEventCreateWithFlags(&root,  cudaEventDisableTiming);
        cudaEventCreateWithFlags(&evQKV, cudaEventDisableTiming);
        cudaEventCreateWithFlags(&evWo,  cudaEventDisableTiming);
        cudaEventCreateWithFlags(&evGU,  cudaEventDisableTiming);
        cudaEventCreateWithFlags(&evWd,  cudaEventDisableTiming);
    }
};
static AuxRes g_aux;

// ================= weight quantization: W[K,N] -> Y[N,2K] int8 + SB[N] =====
__global__ void wquant_kernel(const float* __restrict__ W, int8_t* __restrict__ Y,
                              float* __restrict__ SB, int K, int N) {
    __shared__ float red[8][32];
    __shared__ float sinv[32];
    __shared__ int8_t sq1[32][32];
    __shared__ int8_t sq0[32][32];
    const int tx = threadIdx.x, ty = threadIdx.y;
    const int n0 = blockIdx.x * 32;
    const int n = n0 + tx;

    float m = 0.f;
    for (int k = ty; k < K; k += 8) m = fmaxf(m, fabsf(W[(size_t)k * N + n]));
    red[ty][tx] = m; __syncthreads();
    if (ty == 0) {
        for (int j = 1; j < 8; j++) m = fmaxf(m, red[j][tx]);
        m = fmaxf(m, 1e-30f);
        SB[n] = m / 16256.f;
        sinv[tx] = 16256.f / m;
    }
    __syncthreads();
    const float inv = sinv[tx];

    for (int k0 = 0; k0 < K; k0 += 32) {
#pragma unroll
        for (int j = 0; j < 4; j++) {
            int k = k0 + ty + j * 8;
            float Q = W[(size_t)k * N + n] * inv;
            quant2(Q, &sq1[tx][ty + j * 8], &sq0[tx][ty + j * 8]);
        }
        __syncthreads();
        int t = ty * 32 + tx;
        int nr = t >> 3, kw = t & 7;
        uchar4 p1 = *(uchar4*)&sq1[nr][kw * 4];
        uchar4 p0 = *(uchar4*)&sq0[nr][kw * 4];
        *(uchar4*)(Y + (size_t)(n0 + nr) * 2 * K + k0 + kw * 4) = p1;
        *(uchar4*)(Y + (size_t)(n0 + nr) * 2 * K + K + k0 + kw * 4) = p0;
        __syncthreads();
    }
}

// fused Q|K|V weight quantization (N = 3072, K = HID)
__global__ void wquant3_kernel(const float* __restrict__ Wq, const float* __restrict__ Wk,
                               const float* __restrict__ Wv,
                               int8_t* __restrict__ Y, float* __restrict__ SB) {
    __shared__ float red[8][32];
    __shared__ float sinv[32];
    __shared__ int8_t sq1[32][32];
    __shared__ int8_t sq0[32][32];
    const int tx = threadIdx.x, ty = threadIdx.y;
    const int n0 = blockIdx.x * 32;
    const float* W; int sN, c0;
    if (n0 < 2048)      { W = Wq; sN = 2048; c0 = n0; }
    else if (n0 < 2560) { W = Wk; sN = 512;  c0 = n0 - 2048; }
    else                { W = Wv; sN = 512;  c0 = n0 - 2560; }
    const int n = c0 + tx;
    const int K = HID;

    float m = 0.f;
    for (int k = ty; k < K; k += 8) m = fmaxf(m, fabsf(W[(size_t)k * sN + n]));
    red[ty][tx] = m; __syncthreads();
    if (ty == 0) {
        for (int j = 1; j < 8; j++) m = fmaxf(m, red[j][tx]);
        m = fmaxf(m, 1e-30f);
        SB[n0 + tx] = m / 16256.f;
        sinv[tx] = 16256.f / m;
    }
    __syncthreads();
    const float inv = sinv[tx];

    for (int k0 = 0; k0 < K; k0 += 32) {
#pragma unroll
        for (int j = 0; j < 4; j++) {
            int k = k0 + ty + j * 8;
            float Q = W[(size_t)k * sN + n] * inv;
            quant2(Q, &sq1[tx][ty + j * 8], &sq0[tx][ty + j * 8]);
        }
        __syncthreads();
        int t = ty * 32 + tx;
        int nr = t >> 3, kw = t & 7;
        uchar4 p1 = *(uchar4*)&sq1[nr][kw * 4];
        uchar4 p0 = *(uchar4*)&sq0[nr][kw * 4];
        *(uchar4*)(Y + (size_t)(n0 + nr) * 2 * K + k0 + kw * 4) = p1;
        *(uchar4*)(Y + (size_t)(n0 + nr) * 2 * K + K + k0 + kw * 4) = p0;
        __syncthreads();
    }
}

// ================= RMSNorm fused with int8 row quantization =================
__global__ void rmsq_kernel(const float* __restrict__ x, const float* __restrict__ w,
                            int8_t* __restrict__ y, float* __restrict__ sA) {
    int row = blockIdx.x;
    const float* xr = x + (size_t)row * HID;
    __shared__ float red[256];
    float s = 0.f;
    for (int i = threadIdx.x; i < HID; i += 256) { float v = xr[i]; s += v * v; }
    red[threadIdx.x] = s; __syncthreads();
    for (int st = 128; st > 0; st >>= 1) {
        if (threadIdx.x < st) red[threadIdx.x] += red[threadIdx.x + st];
        __syncthreads();
    }
    float r = rsqrtf(red[0] / (float)HID + 1e-6f);
    __syncthreads();

    float m = 0.f;
    for (int i = threadIdx.x; i < HID; i += 256)
        m = fmaxf(m, fabsf(w[i] * xr[i] * r));
    red[threadIdx.x] = m; __syncthreads();
    for (int st = 128; st > 0; st >>= 1) {
        if (threadIdx.x < st) red[threadIdx.x] = fmaxf(red[threadIdx.x], red[threadIdx.x + st]);
        __syncthreads();
    }
    float mm = fmaxf(red[0], 1e-30f);
    if (threadIdx.x == 0) sA[row] = mm / 16256.f;
    float inv = 16256.f / mm;
    size_t base = (size_t)row * 2 * HID;
    for (int i = threadIdx.x; i < HID; i += 256) {
        float Q = w[i] * xr[i] * r * inv;
        int8_t q1, q0;
        quant2(Q, &q1, &q0);
        y[base + i] = q1;
        y[base + HID + i] = q0;
    }
}

// ================= generic row quantization: x[M,W] -> y[M,2W] ==============
__global__ void rowquant_kernel(const float* __restrict__ x, int W,
                                int8_t* __restrict__ y, float* __restrict__ sA) {
    int row = blockIdx.x;
    const float* xr = x + (size_t)row * W;
    __shared__ float red[256];
    float m = 0.f;
    for (int i = threadIdx.x; i < W; i += 256) m = fmaxf(m, fabsf(xr[i]));
    red[threadIdx.x] = m; __syncthreads();
    for (int st = 128; st > 0; st >>= 1) {
        if (threadIdx.x < st) red[threadIdx.x] = fmaxf(red[threadIdx.x], red[threadIdx.x + st]);
        __syncthreads();
    }
    float mm = fmaxf(red[0], 1e-30f);
    if (threadIdx.x == 0) sA[row] = mm / 16256.f;
    float inv = 16256.f / mm;
    size_t base = (size_t)row * 2 * W;
    for (int i = threadIdx.x; i < W; i += 256) {
        int8_t q1, q0;
        quant2(xr[i] * inv, &q1, &q0);
        y[base + i] = q1;
        y[base + W + i] = q0;
    }
}

// ================= SiLU(gate)*up fused with int8 row quantization ============
__global__ void siluquant_kernel(const float* __restrict__ gu,
                                 int8_t* __restrict__ y, float* __restrict__ sA) {
    int row = blockIdx.x;
    const float* g = gu + (size_t)row * NGU;
    const float* u = g + INTER;
    __shared__ float red[256];
    float m = 0.f;
    for (int i = threadIdx.x; i < INTER; i += 256) {
        float x = g[i];
        float v = (x / (1.f + __expf(-x))) * u[i];
        m = fmaxf(m, fabsf(v));
    }
    red[threadIdx.x] = m; __syncthreads();
    for (int st = 128; st > 0; st >>= 1) {
        if (threadIdx.x < st) red[threadIdx.x] = fmaxf(red[threadIdx.x], red[threadIdx.x + st]);
        __syncthreads();
    }
    float mm = fmaxf(red[0], 1e-30f);
    if (threadIdx.x == 0) sA[row] = mm / 16256.f;
    float inv = 16256.f / mm;
    size_t base = (size_t)row * 2 * INTER;
    for (int i = threadIdx.x; i < INTER; i += 256) {
        float x = g[i];
        float v = (x / (1.f + __expf(-x))) * u[i];
        int8_t q1, q0;
        quant2(v * inv, &q1, &q0);
        y[base + i] = q1;
        y[base + INTER + i] = q0;
    }
}

// ================= int8 IMMA GEMM (3-segment fixed-point) =================
// C = sA (.) [A8 x B8^T] (.) sB ; A8[M,2K]=[a1|a0], B8[N,2K]=[b1|b0]
// segments: (a1,b1)*16384, then {(a1,b0)+(a0,b1)}*128 ; a0b0 dropped.
// CTA tile 128x128, 512 threads (16 warps, 4x4), warp 32x32, K-chunk 128.
#define IG_SMEM 65536

__global__ void __launch_bounds__(512, 1) igemm_kernel(
    const int8_t* __restrict__ A, const int8_t* __restrict__ B,
    const float* __restrict__ sA, const float* __restrict__ sB,
    const float* __restrict__ b1, const float* __restrict__ b2, const float* __restrict__ b3,
    int n1, int n2,
    const float* __restrict__ res,
    float* __restrict__ C, int N, int K)
{
    extern __shared__ char smraw[];
    const uint32_t smu = smem_u32(smraw);
    const int tid = threadIdx.x;
    const int lane = tid & 31, wid = tid >> 5;
    const int wm = wid >> 2, wn = wid & 3;
    const size_t lda = 2 * (size_t)K;
    const int kpseg = K >> 7;           // chunks of 128 int8
    const int nch = 3 * kpseg;
    const size_t arow0 = (size_t)blockIdx.x * 128;
    const size_t brow0 = (size_t)blockIdx.y * 128;

    const uint32_t xm = (uint32_t)((lane & 7) << 4);
    uint32_t kbx[4];
#pragma unroll
    for (int ks = 0; ks < 4; ks++)
        kbx[ks] = ((uint32_t)(ks * 32 + ((lane >> 4) << 4))) ^ xm;
    uint32_t rowA[2], rowB[2];
#pragma unroll
    for (int mt = 0; mt < 2; mt++) rowA[mt] = (uint32_t)(wm * 32 + (lane & 15) + mt * 16) * 128u;
#pragma unroll
    for (int nt2 = 0; nt2 < 2; nt2++) rowB[nt2] = (uint32_t)(wn * 32 + (lane & 15) + nt2 * 16) * 128u;

    float facc[2][4][4];
    int   iacc[2][4][4];
#pragma unroll
    for (int i = 0; i < 2; i++)
#pragma unroll
        for (int j = 0; j < 4; j++)
#pragma unroll
            for (int t = 0; t < 4; t++) { facc[i][j][t] = 0.f; iacc[i][j][t] = 0; }

    auto issue = [&](int ch, int b) {
        int seg = ch / kpseg;
        int kk = (ch - seg * kpseg) << 7;
        const int8_t* Ab = A + (seg == 2 ? K : 0) + kk;
        const int8_t* Bb = B + (seg == 1 ? K : 0) + kk;
        uint32_t abase = smu + b * 32768;
        uint32_t bbase = abase + 16384;
#pragma unroll
        for (int i = 0; i < 2; i++) {
            int u = i * 512 + tid;
            int r = u >> 3, c = u & 7;
            uint32_t so = sw128((uint32_t)(r * 128 + c * 16));
            cp_async16(abase + so, Ab + (arow0 + r) * lda + c * 16);
            cp_async16(bbase + so, Bb + (brow0 + r) * lda + c * 16);
        }
        cp_commit();
    };

    issue(0, 0);

    for (int ch = 0; ch < nch; ch++) {
        const int b = ch & 1;
        if (ch + 1 < nch) {
            issue(ch + 1, b ^ 1);
            asm volatile("cp.async.wait_group 1;");
        } else {
            asm volatile("cp.async.wait_group 0;");
        }
        __syncthreads();

        const uint32_t abuf = smu + b * 32768;
        const uint32_t bbuf = abuf + 16384;

#pragma unroll
        for (int ks = 0; ks < 4; ks++) {
            uint32_t a[2][4];
#pragma unroll
            for (int mt = 0; mt < 2; mt++)
                LDSM_X4(a[mt][0], a[mt][1], a[mt][2], a[mt][3],
                        abuf + rowA[mt] + kbx[ks]);
            uint32_t bf[4][2];
#pragma unroll
            for (int nt2 = 0; nt2 < 2; nt2++) {
                uint32_t t0, t1, t2, t3;
                LDSM_X4(t0, t1, t2, t3, bbuf + rowB[nt2] + kbx[ks]);
                bf[nt2 * 2 + 0][0] = t0; bf[nt2 * 2 + 0][1] = t2;
                bf[nt2 * 2 + 1][0] = t1; bf[nt2 * 2 + 1][1] = t3;
            }
#pragma unroll
            for (int mt = 0; mt < 2; mt++)
#pragma unroll
                for (int nt = 0; nt < 4; nt++)
                    MMAS8(iacc[mt][nt], a[mt], bf[nt][0], bf[nt][1]);
        }
        __syncthreads();

        if (ch == kpseg - 1) {     // end of (a1,b1) segment: bank into fp32 with weight 16384
#pragma unroll
            for (int i = 0; i < 2; i++)
#pragma unroll
                for (int j = 0; j < 4; j++)
#pragma unroll
                    for (int t = 0; t < 4; t++) {
                        facc[i][j][t] = 16384.f * (float)iacc[i][j][t];
                        iacc[i][j][t] = 0;
                    }
        }
    }

    // epilogue
    const int rb = (int)arow0 + wm * 32 + (lane >> 2);
    const int cb = (int)brow0 + wn * 32 + ((lane & 3) << 1);
#pragma unroll
    for (int mt = 0; mt < 2; mt++) {
        const int row = rb + mt * 16;
        const float sa0 = sA[row], sa1 = sA[row + 8];
#pragma unroll
        for (int nt = 0; nt < 4; nt++) {
            const int col = cb + nt * 8;
            const float sb0 = sB[col], sb1 = sB[col + 1];
            float bv0 = 0.f, bv1 = 0.f;
            if (b1) {
                if (col < n1)      { bv0 = b1[col];      bv1 = b1[col + 1]; }
                else if (col < n2) { bv0 = b2[col - n1]; bv1 = b2[col - n1 + 1]; }
                else               { bv0 = b3[col - n2]; bv1 = b3[col - n2 + 1]; }
            }
            float f0 = facc[mt][nt][0] + 128.f * (float)iacc[mt][nt][0];
            float f1 = facc[mt][nt][1] + 128.f * (float)iacc[mt][nt][1];
            float f2 = facc[mt][nt][2] + 128.f * (float)iacc[mt][nt][2];
            float f3 = facc[mt][nt][3] + 128.f * (float)iacc[mt][nt][3];
            size_t gi = (size_t)row * N + col;
            float v0 = sa0 * sb0 * f0 + bv0, v1 = sa0 * sb1 * f1 + bv1;
            if (res) { v0 += res[gi]; v1 += res[gi + 1]; }
            *(float2*)(C + gi) = make_float2(v0, v1);
            size_t gi2 = gi + (size_t)8 * N;
            float v2 = sa1 * sb0 * f2 + bv0, v3 = sa1 * sb1 * f3 + bv1;
            if (res) { v2 += res[gi2]; v3 += res[gi2 + 1]; }
            *(float2*)(C + gi2) = make_float2(v2, v3);
        }
    }
}

// ================= small fp32 SGEMM (gate path only) =================
__global__ void __launch_bounds__(256) sgemm_kernel(
    const float* __restrict__ A, const float* __restrict__ B,
    float* __restrict__ C, int M, int N, int K)
{
    __shared__ float As[8][128];
    __shared__ float Bs[8][128];
    const int tid = threadIdx.x;
    const int bx = blockIdx.x * 128;
    const int by = blockIdx.y * 128;
    const int tx = tid & 15;
    const int ty = tid >> 4;
    const int arow = tid >> 1;
    const int acol = (tid & 1) << 2;
    const int brow = tid >> 5;
    const int bcol = (tid & 31) << 2;

    const float* Ap = A + (size_t)(by + arow) * K + acol;
    const float* Bp = B + (size_t)brow * N + bx + bcol;

    float acc[8][8];
#pragma unroll
    for (int i = 0; i < 8; i++)
#pragma unroll
        for (int j = 0; j < 8; j++) acc[i][j] = 0.f;

    for (int k0 = 0; k0 < K; k0 += 8) {
        float4 av = *(const float4*)Ap;
        As[acol + 0][arow] = av.x;
        As[acol + 1][arow] = av.y;
        As[acol + 2][arow] = av.z;
        As[acol + 3][arow] = av.w;
        *(float4*)&Bs[brow][bcol] = *(const float4*)Bp;
        __syncthreads();
#pragma unroll
        for (int kk = 0; kk < 8; kk++) {
            float a[8], bb[8];
            *(float4*)&a[0] = *(const float4*)&As[kk][ty * 8];
            *(float4*)&a[4] = *(const float4*)&As[kk][ty * 8 + 4];
            *(float4*)&bb[0] = *(const float4*)&Bs[kk][tx * 8];
            *(float4*)&bb[4] = *(const float4*)&Bs[kk][tx * 8 + 4];
#pragma unroll
            for (int i = 0; i < 8; i++)
#pragma unroll
                for (int j = 0; j < 8; j++)
                    acc[i][j] += a[i] * bb[j];
        }
        __syncthreads();
        Ap += 8;
        Bp += (size_t)8 * N;
    }

    const int row0 = by + ty * 8;
    const int col0 = bx + tx * 8;
#pragma unroll
    for (int i = 0; i < 8; i++)
#pragma unroll
        for (int j = 0; j < 8; j++)
            C[(size_t)(row0 + i) * N + col0 + j] = acc[i][j];
}

// ================= pooling / gate / rope =================
__global__ void pool_kernel(const float* __restrict__ x, int stride,
                            float* __restrict__ out, int H) {
    int qb = blockIdx.x, h = blockIdx.y, d = threadIdx.x;
    float s = 0.f;
    for (int i = 0; i < BSZ; i++)
        s += x[(size_t)(qb * BSZ + i) * stride + h * DH + d];
    out[((size_t)qb * H + h) * DH + d] = s * (1.f / (float)BSZ);
}

__global__ void gate_kernel(const float* __restrict__ qg, const float* __restrict__ kg,
                            unsigned char* __restrict__ keep) {
    int h = blockIdx.x, qb = blockIdx.y, kb = threadIdx.x;
    const float* qv = qg + ((size_t)qb * HQ + h) * GHD;
    const float* kv = kg + ((size_t)kb * HKV + (h >> 2)) * GHD;
    float s = 0.f;
    for (int d = 0; d < GHD; d++) s += qv[d] * kv[d];
    s *= SCALE_INV_SQRT_128;
    if (kb > qb) s = -1e30f;
    float m = s;
    for (int off = 16; off > 0; off >>= 1)
        m = fmaxf(m, __shfl_xor_sync(0xffffffffu, m, off));
    float e = expf(s - m);
    float sum = e;
    for (int off = 16; off > 0; off >>= 1)
        sum += __shfl_xor_sync(0xffffffffu, sum, off);
    float gate = e / sum;
    bool kp = (kb <= qb) && ((gate >= 0.004f) || (kb == qb));
    keep[((size_t)h * QBN + qb) * QBN + kb] = kp ? 1 : 0;
}

__global__ void rope_kernel(float* __restrict__ x, int stride,
                            const float* __restrict__ cs, const float* __restrict__ sn, int H) {
    int idx = blockIdx.x * blockDim.x + threadIdx.x;
    int d = idx & 63;
    int h = (idx >> 6) % H;
    int s = idx / (64 * H);
    float* p = x + (size_t)s * stride + h * DH;
    float x1 = p[d], x2 = p[d + 64];
    float c1 = cs[(size_t)s * DH + d],      s1 = sn[(size_t)s * DH + d];
    float c2 = cs[(size_t)s * DH + d + 64], s2 = sn[(size_t)s * DH + d + 64];
    p[d]      = x1 * c1 - x2 * s1;
    p[d + 64] = x2 * c2 + x1 * s2;
}

// ================= tf32 tensor-core block-sparse flash attention =================
#define ATP 132
#define APP 68
#define AQ_OFF   0
#define AK_OFF   (64*ATP)
#define AV_OFF   (2*64*ATP)
#define AP_OFF   (3*64*ATP)
#define ARM_OFF  (AP_OFF + 64*APP)
#define ARL_OFF  (ARM_OFF + 128)
#define AROWM    (ARL_OFF + 128)
#define AROWL    (AROWM + 64)
#define AALF     (AROWL + 64)
#define ATTN_SM_FLOATS (AALF + 64)

__global__ void __launch_bounds__(256, 1) attn_kernel(
    const float* __restrict__ qkv,
    const unsigned char* __restrict__ keep, float* __restrict__ o)
{
    extern __shared__ float sm[];
    const uint32_t* smu = (const uint32_t*)sm;

    const int qb = QBN - 1 - blockIdx.x;
    const int h = blockIdx.y;
    const int hk = h >> 2;
    const int tid = threadIdx.x;
    const int lane = tid & 31, wid = tid >> 5;
    const int rw = wid & 3, cw = wid >> 2;
    const int g = lane >> 2, qd = lane & 3;
    const int r0 = rw * 16 + g;
    const int r1 = r0 + 8;

    for (int i = tid; i < 64 * 32; i += 256) {
        int t = i >> 5, d4 = (i & 31) << 2;
        float4 qv = *(const float4*)&qkv[(size_t)(qb * 64 + t) * NQKV + h * DH + d4];
        float* dst = sm + AQ_OFF + t * ATP + d4;
        dst[0] = tf32r(qv.x * SCALE_INV_SQRT_128);
        dst[1] = tf32r(qv.y * SCALE_INV_SQRT_128);
        dst[2] = tf32r(qv.z * SCALE_INV_SQRT_128);
        dst[3] = tf32r(qv.w * SCALE_INV_SQRT_128);
    }
    if (tid < 64) { sm[AROWM + tid] = -1e30f; sm[AROWL + tid] = 0.f; }

    float oacc[8][4];
#pragma unroll
    for (int i = 0; i < 8; i++)
#pragma unroll
        for (int j = 0; j < 4; j++) oacc[i][j] = 0.f;

    const unsigned char* krow = keep + ((size_t)h * QBN + qb) * QBN;

    for (int kb = 0; kb <= qb; kb++) {
        if (!krow[kb]) continue;
        __syncthreads();

        for (int i = tid; i < 64 * 32; i += 256) {
            int t = i >> 5, d4 = (i & 31) << 2;
            size_t gi = (size_t)(kb * 64 + t) * NQKV + hk * DH + d4;
            float4 kvv = *(const float4*)&qkv[gi + 2048];
            float* kd = sm + AK_OFF + t * ATP + d4;
            kd[0] = tf32r(kvv.x); kd[1] = tf32r(kvv.y); kd[2] = tf32r(kvv.z); kd[3] = tf32r(kvv.w);
            float4 vvv = *(const float4*)&qkv[gi + 2560];
            float* vd = sm + AV_OFF + t * ATP + d4;
            vd[0] = tf32r(vvv.x); vd[1] = tf32r(vvv.y); vd[2] = tf32r(vvv.z); vd[3] = tf32r(vvv.w);
        }
        __syncthreads();

        float sacc[4][4];
#pragma unroll
        for (int i = 0; i < 4; i++)
#pragma unroll
            for (int j = 0; j < 4; j++) sacc[i][j] = 0.f;

#pragma unroll
        for (int ks = 0; ks < 16; ks++) {
            const int k0 = ks * 8;
            uint32_t a[4];
            a[0] = smu[AQ_OFF + r0 * ATP + k0 + qd];
            a[1] = smu[AQ_OFF + r1 * ATP + k0 + qd];
            a[2] = smu[AQ_OFF + r0 * ATP + k0 + qd + 4];
            a[3] = smu[AQ_OFF + r1 * ATP + k0 + qd + 4];
#pragma unroll
            for (int nt = 0; nt < 4; nt++) {
                const int n = cw * 32 + nt * 8 + g;
                uint32_t b0 = smu[AK_OFF + n * ATP + k0 + qd];
                uint32_t b1 = smu[AK_OFF + n * ATP + k0 + qd + 4];
                MMATF32(sacc[nt], a, b0, b1);
            }
        }

        if (kb == qb) {
#pragma unroll
            for (int nt = 0; nt < 4; nt++) {
                const int c0 = cw * 32 + nt * 8 + qd * 2;
                if (c0 > r0)     sacc[nt][0] = -1e30f;
                if (c0 + 1 > r0) sacc[nt][1] = -1e30f;
                if (c0 > r1)     sacc[nt][2] = -1e30f;
                if (c0 + 1 > r1) sacc[nt][3] = -1e30f;
            }
        }

        float m0 = -1e30f, m1 = -1e30f;
#pragma unroll
        for (int nt = 0; nt < 4; nt++) {
            m0 = fmaxf(m0, fmaxf(sacc[nt][0], sacc[nt][1]));
            m1 = fmaxf(m1, fmaxf(sacc[nt][2], sacc[nt][3]));
        }
        m0 = fmaxf(m0, __shfl_xor_sync(0xffffffffu, m0, 1));
        m0 = fmaxf(m0, __shfl_xor_sync(0xffffffffu, m0, 2));
        m1 = fmaxf(m1, __shfl_xor_sync(0xffffffffu, m1, 1));
        m1 = fmaxf(m1, __shfl_xor_sync(0xffffffffu, m1, 2));
        if (qd == 0) {
            sm[ARM_OFF + cw * 64 + r0] = m0;
            sm[ARM_OFF + cw * 64 + r1] = m1;
        }
        __syncthreads();

        if (tid < 64) {
            float newm = fmaxf(sm[AROWM + tid],
                               fmaxf(sm[ARM_OFF + tid], sm[ARM_OFF + 64 + tid]));
            sm[AALF + tid] = __expf(sm[AROWM + tid] - newm);
            sm[AROWM + tid] = newm;
        }
        __syncthreads();

        const float nm0 = sm[AROWM + r0];
        const float nm1 = sm[AROWM + r1];
        float l0 = 0.f, l1 = 0.f;
#pragma unroll
        for (int nt = 0; nt < 4; nt++) {
            const int c0 = cw * 32 + nt * 8 + qd * 2;
            float p0 = __expf(sacc[nt][0] - nm0);
            float p1 = __expf(sacc[nt][1] - nm0);
            float p2 = __expf(sacc[nt][2] - nm1);
            float p3 = __expf(sacc[nt][3] - nm1);
            l0 += p0 + p1; l1 += p2 + p3;
            sm[AP_OFF + r0 * APP + c0]     = tf32r(p0);
            sm[AP_OFF + r0 * APP + c0 + 1] = tf32r(p1);
            sm[AP_OFF + r1 * APP + c0]     = tf32r(p2);
            sm[AP_OFF + r1 * APP + c0 + 1] = tf32r(p3);
        }
        l0 += __shfl_xor_sync(0xffffffffu, l0, 1);
        l0 += __shfl_xor_sync(0xffffffffu, l0, 2);
        l1 += __shfl_xor_sync(0xffffffffu, l1, 1);
        l1 += __shfl_xor_sync(0xffffffffu, l1, 2);
        if (qd == 0) {
            sm[ARL_OFF + cw * 64 + r0] = l0;
            sm[ARL_OFF + cw * 64 + r1] = l1;
        }
        const float al0 = sm[AALF + r0];
        const float al1 = sm[AALF + r1];
#pragma unroll
        for (int nt = 0; nt < 8; nt++) {
            oacc[nt][0] *= al0; oacc[nt][1] *= al0;
            oacc[nt][2] *= al1; oacc[nt][3] *= al1;
        }
        __syncthreads();

        if (tid < 64)
            sm[AROWL + tid] = sm[AROWL + tid] * sm[AALF + tid]
                            + sm[ARL_OFF + tid] + sm[ARL_OFF + 64 + tid];

#pragma unroll
        for (int ks = 0; ks < 8; ks++) {
            const int k0 = ks * 8;
            uint32_t a[4];
            a[0] = smu[AP_OFF + r0 * APP + k0 + qd];
            a[1] = smu[AP_OFF + r1 * APP + k0 + qd];
            a[2] = smu[AP_OFF + r0 * APP + k0 + qd + 4];
            a[3] = smu[AP_OFF + r1 * APP + k0 + qd + 4];
#pragma unroll
            for (int nt = 0; nt < 8; nt++) {
                const int n = cw * 64 + nt * 8 + g;
                uint32_t b0 = smu[AV_OFF + (k0 + qd) * ATP + n];
                uint32_t b1 = smu[AV_OFF + (k0 + qd + 4) * ATP + n];
                MMATF32(oacc[nt], a, b0, b1);
            }
        }
    }

    __syncthreads();
    const float inv0 = 1.f / sm[AROWL + r0];
    const float inv1 = 1.f / sm[AROWL + r1];
    const size_t grow0 = (size_t)(qb * 64 + r0);
    const size_t grow1 = (size_t)(qb * 64 + r1);
#pragma unroll
    for (int nt = 0; nt < 8; nt++) {
        const int col = h * DH + cw * 64 + nt * 8 + qd * 2;
        *(float2*)(o + grow0 * HID + col) = make_float2(oacc[nt][0] * inv0, oacc[nt][1] * inv0);
        *(float2*)(o + grow1 * HID + col) = make_float2(oacc[nt][2] * inv1, oacc[nt][3] * inv1);
    }
}

// ================= launch =================
extern "C" void kernel_launch(void* const* d_in, const int* in_sizes, int n_in,
                              void* d_out, int out_size) {
    const float* hidden = (const float*)d_in[0];
    const float* cosp   = (const float*)d_in[1];
    const float* sinp   = (const float*)d_in[2];
    const float* ln1    = (const float*)d_in[3];
    const float* ln2    = (const float*)d_in[4];
    const float* Wq     = (const float*)d_in[5];
    const float* bq     = (const float*)d_in[6];
    const float* Wk     = (const float*)d_in[7];
    const float* bk     = (const float*)d_in[8];
    const float* Wv     = (const float*)d_in[9];
    const float* bv     = (const float*)d_in[10];
    const float* Wo     = (const float*)d_in[11];
    const float* gWq    = (const float*)d_in[12];
    const float* gWk    = (const float*)d_in[13];
    const float* Wgate  = (const float*)d_in[14];
    const float* Wup    = (const float*)d_in[15];
    const float* Wdown  = (const float*)d_in[16];
    float* out = (float*)d_out;

    float *qkv, *qp, *kp, *qg, *kg, *o, *h2, *gu;
    unsigned char* keep;
    int8_t *Wqkv8, *Wo8, *Wgu8, *Wd8, *ha8, *oa8, *h38, *gt8;
    float *sWqkv, *sWo, *sWgu, *sWd, *sHA, *sO, *sH3, *sGT;
    cudaGetSymbolAddress((void**)&qkv,  g_qkv);
    cudaGetSymbolAddress((void**)&qp,   g_qp);
    cudaGetSymbolAddress((void**)&kp,   g_kp);
    cudaGetSymbolAddress((void**)&qg,   g_qg);
    cudaGetSymbolAddress((void**)&kg,   g_kg);
    cudaGetSymbolAddress((void**)&keep, g_keep);
    cudaGetSymbolAddress((void**)&o,    g_o);
    cudaGetSymbolAddress((void**)&h2,   g_h2);
    cudaGetSymbolAddress((void**)&gu,   g_gu);
    cudaGetSymbolAddress((void**)&Wqkv8, g_Wqkv8); cudaGetSymbolAddress((void**)&sWqkv, g_sWqkv);
    cudaGetSymbolAddress((void**)&Wo8,  g_Wo8);    cudaGetSymbolAddress((void**)&sWo,  g_sWo);
    cudaGetSymbolAddress((void**)&Wgu8, g_Wgu8);   cudaGetSymbolAddress((void**)&sWgu, g_sWgu);
    cudaGetSymbolAddress((void**)&Wd8,  g_Wd8);    cudaGetSymbolAddress((void**)&sWd,  g_sWd);
    cudaGetSymbolAddress((void**)&ha8,  g_ha8);    cudaGetSymbolAddress((void**)&sHA,  g_sHA);
    cudaGetSymbolAddress((void**)&oa8,  g_oa8);    cudaGetSymbolAddress((void**)&sO,   g_sO);
    cudaGetSymbolAddress((void**)&h38,  g_h38);    cudaGetSymbolAddress((void**)&sH3,  g_sH3);
    cudaGetSymbolAddress((void**)&gt8,  g_gt8);    cudaGetSymbolAddress((void**)&sGT,  g_sGT);

    cudaFuncSetAttribute(igemm_kernel, cudaFuncAttributeMaxDynamicSharedMemorySize, IG_SMEM);
    cudaFuncSetAttribute(attn_kernel, cudaFuncAttributeMaxDynamicSharedMemorySize,
                         ATTN_SM_FLOATS * (int)sizeof(float));

    dim3 w328(32, 8);
    cudaStream_t s2 = g_aux.s2;

    // main: RMS+quant of hidden
    rmsq_kernel<<<SEQ, 256>>>(hidden, ln1, ha8, sHA);

    // side stream: weight quantizations
    cudaEventRecord(g_aux.root, 0);
    cudaStreamWaitEvent(s2, g_aux.root, 0);
    wquant3_kernel<<<NQKV/32, w328, 0, s2>>>(Wq, Wk, Wv, Wqkv8, sWqkv);
    cudaEventRecord(g_aux.evQKV, s2);
    wquant_kernel<<<HID/32, w328, 0, s2>>>(Wo, Wo8, sWo, HID, HID);
    cudaEventRecord(g_aux.evWo, s2);
    wquant_kernel<<<INTER/32, w328, 0, s2>>>(Wgate, Wgu8, sWgu, HID, INTER);
    wquant_kernel<<<INTER/32, w328, 0, s2>>>(Wup, Wgu8 + (size_t)INTER*2*HID, sWgu + INTER, HID, INTER);
    cudaEventRecord(g_aux.evGU, s2);
    wquant_kernel<<<HID/32, w328, 0, s2>>>(Wdown, Wd8, sWd, INTER, HID);
    cudaEventRecord(g_aux.evWd, s2);

    // QKV projection (int8)
    cudaStreamWaitEvent(0, g_aux.evQKV, 0);
    igemm_kernel<<<dim3(SEQ/128, NQKV/128), 512, IG_SMEM>>>(
        ha8, Wqkv8, sHA, sWqkv, bq, bk, bv, 2048, 2560, nullptr, qkv, NQKV, HID);

    // gate path
    pool_kernel<<<dim3(QBN, HQ), DH>>>(qkv, NQKV, qp, HQ);
    pool_kernel<<<dim3(QBN, HKV), DH>>>(qkv + 2048, NQKV, kp, HKV);
    sgemm_kernel<<<dim3(GHD/128, (QBN*HQ)/128), 256>>>(qp, gWq, qg, QBN*HQ, GHD, DH);
    sgemm_kernel<<<dim3(GHD/128, (QBN*HKV)/128), 256>>>(kp, gWk, kg, QBN*HKV, GHD, DH);
    gate_kernel<<<dim3(HQ, QBN), 32>>>(qg, kg, keep);

    // RoPE in place
    rope_kernel<<<(SEQ*HQ*64)/256, 256>>>(qkv, NQKV, cosp, sinp, HQ);
    rope_kernel<<<(SEQ*HKV*64)/256, 256>>>(qkv + 2048, NQKV, cosp, sinp, HKV);

    // block-sparse flash attention -> o (fp32), then row quant
    attn_kernel<<<dim3(QBN, HQ), 256, ATTN_SM_FLOATS * (int)sizeof(float)>>>(qkv, keep, o);
    rowquant_kernel<<<SEQ, 256>>>(o, HID, oa8, sO);

    // h2 = o @ Wo + hidden
    cudaStreamWaitEvent(0, g_aux.evWo, 0);
    igemm_kernel<<<dim3(SEQ/128, HID/128), 512, IG_SMEM>>>(
        oa8, Wo8, sO, sWo, nullptr, nullptr, nullptr, HID, HID, hidden, h2, HID, HID);

    // h3 = rms(h2)*ln2 -> int8
    rmsq_kernel<<<SEQ, 256>>>(h2, ln2, h38, sH3);

    // MLP up+gate
    cudaStreamWaitEvent(0, g_aux.evGU, 0);
    igemm_kernel<<<dim3(SEQ/128, NGU/128), 512, IG_SMEM>>>(
        h38, Wgu8, sH3, sWgu, nullptr, nullptr, nullptr, NGU, NGU, nullptr, gu, NGU, HID);

    siluquant_kernel<<<SEQ, 256>>>(gu, gt8, sGT);

    // out = silu_mul @ Wdown + h2
    cudaStreamWaitEvent(0, g_aux.evWd, 0);
    igemm_kernel<<<dim3(SEQ/128, HID/128), 512, IG_SMEM>>>(
        gt8, Wd8, sGT, sWd, nullptr, nullptr, nullptr, HID, HID, h2, out, HID, INTER);
}

// round 9
// speedup vs baseline: 2.1417x; 2.1417x over previous
#include <cuda_runtime.h>
#include <cuda_bf16.h>
#include <math.h>
#include <stdint.h>

#define SEQ   2048
#define HID   2048
#define HQ    16
#define HKV   4
#define DH    128
#define QBN   32
#define BSZ   64
#define GHD   128
#define INTER 5632
#define NQKV  3072
#define NGU   11264

#define SCALE_INV_SQRT_128 0.08838834764831845f

// ================= helpers =================
__device__ __forceinline__ uint32_t smem_u32(const void* p) {
    uint32_t a;
    asm("{ .reg .u64 t; cvta.to.shared.u64 t, %1; cvt.u32.u64 %0, t; }" : "=r"(a) : "l"(p));
    return a;
}
__device__ __forceinline__ void cp_async16(uint32_t saddr, const void* gptr) {
    asm volatile("cp.async.cg.shared.global [%0], [%1], 16;" :: "r"(saddr), "l"(gptr));
}
__device__ __forceinline__ void cp_commit() { asm volatile("cp.async.commit_group;"); }

#define LDSM_X4(r0, r1, r2, r3, addr) \
    asm volatile("ldmatrix.sync.aligned.m8n8.x4.shared.b16 {%0,%1,%2,%3}, [%4];" \
        : "=r"(r0), "=r"(r1), "=r"(r2), "=r"(r3) : "r"(addr))

#define MMA16816(c, a, b0r, b1r) \
    asm volatile("mma.sync.aligned.m16n8k16.row.col.f32.bf16.bf16.f32 " \
        "{%0,%1,%2,%3}, {%4,%5,%6,%7}, {%8,%9}, {%0,%1,%2,%3};" \
        : "+f"((c)[0]), "+f"((c)[1]), "+f"((c)[2]), "+f"((c)[3]) \
        : "r"((a)[0]), "r"((a)[1]), "r"((a)[2]), "r"((a)[3]), "r"(b0r), "r"(b1r))

#define MMATF32(c, a, b0r, b1r) \
    asm volatile("mma.sync.aligned.m16n8k8.row.col.f32.tf32.tf32.f32 " \
        "{%0,%1,%2,%3}, {%4,%5,%6,%7}, {%8,%9}, {%0,%1,%2,%3};" \
        : "+f"((c)[0]), "+f"((c)[1]), "+f"((c)[2]), "+f"((c)[3]) \
        : "r"((a)[0]), "r"((a)[1]), "r"((a)[2]), "r"((a)[3]), "r"(b0r), "r"(b1r))

static __device__ __forceinline__ uint32_t sw128(uint32_t o) { return o ^ ((o >> 3) & 0x70); }

__device__ __forceinline__ float tf32r(float v) {
    float r;
    asm("cvt.rna.tf32.f32 %0, %1;" : "=f"(r) : "f"(v));
    return r;
}

// ================= device scratch =================
__device__ float g_qkv [SEQ*NQKV];
__device__ float g_qp  [QBN*HQ*DH];
__device__ float g_kp  [QBN*HKV*DH];
__device__ float g_qg  [QBN*HQ*GHD];
__device__ float g_kg  [QBN*HKV*GHD];
__device__ unsigned char g_keep[HQ*QBN*QBN];
__device__ float g_h2  [SEQ*HID];
__device__ float g_gu  [SEQ*NGU];

__device__ __nv_bfloat16 g_Wqkv2[NQKV*4096];
__device__ __nv_bfloat16 g_Wo2  [2048*4096];
__device__ __nv_bfloat16 g_Wgu2 [NGU*4096];
__device__ __nv_bfloat16 g_Wd2  [2048*11264];
__device__ __nv_bfloat16 g_ha2  [2048*4096];
__device__ __nv_bfloat16 g_oa2  [2048*4096];
__device__ __nv_bfloat16 g_h3a2 [2048*4096];
__device__ __nv_bfloat16 g_gt2  [2048*11264];

// ===== side-stream resources (created pre-main in static init) =====
struct AuxRes {
    cudaStream_t s2;
    cudaEvent_t root, evQKV, evWo, evGU, evWd, evPool, evGate;
    AuxRes() {
        cudaStreamCreateWithFlags(&s2, cudaStreamNonBlocking);
        cudaEventCreateWithFlags(&root,   cudaEventDisableTiming);
        cudaEventCreateWithFlags(&evQKV,  cudaEventDisableTiming);
        cudaEventCreateWithFlags(&evWo,   cudaEventDisableTiming);
        cudaEventCreateWithFlags(&evGU,   cudaEventDisableTiming);
        cudaEventCreateWithFlags(&evWd,   cudaEventDisableTiming);
        cudaEventCreateWithFlags(&evPool, cudaEventDisableTiming);
        cudaEventCreateWithFlags(&evGate, cudaEventDisableTiming);
    }
};
static AuxRes g_aux;

// ===== fused QKV weight conversion =====
__global__ void wconv3_kernel(const float* __restrict__ Wq, const float* __restrict__ Wk,
                              const float* __restrict__ Wv, __nv_bfloat16* __restrict__ y) {
    __shared__ float tile[32][33];
    int n0 = blockIdx.x * 32, k0 = blockIdx.y * 32;
    const float* W; int sN, c0;
    if (n0 < 2048)      { W = Wq; sN = 2048; c0 = n0; }
    else if (n0 < 2560) { W = Wk; sN = 512;  c0 = n0 - 2048; }
    else                { W = Wv; sN = 512;  c0 = n0 - 2560; }
    for (int i = threadIdx.y; i < 32; i += 8)
        tile[i][threadIdx.x] = W[(size_t)(k0 + i) * sN + c0 + threadIdx.x];
    __syncthreads();
    for (int i = threadIdx.y; i < 32; i += 8) {
        int n = n0 + i, k = k0 + threadIdx.x;
        float v = tile[threadIdx.x][i];
        __nv_bfloat16 h = __float2bfloat16(v);
        size_t base = (size_t)n * 2 * HID;
        y[base + k]       = h;
        y[base + HID + k] = __float2bfloat16(v - __bfloat162float(h));
    }
}

__global__ void wconv_kernel(const float* __restrict__ W, __nv_bfloat16* __restrict__ y,
                             int K, int N) {
    __shared__ float tile[32][33];
    int n0 = blockIdx.x * 32, k0 = blockIdx.y * 32;
    for (int i = threadIdx.y; i < 32; i += 8)
        tile[i][threadIdx.x] = W[(size_t)(k0 + i) * N + n0 + threadIdx.x];
    __syncthreads();
    for (int i = threadIdx.y; i < 32; i += 8) {
        int n = n0 + i, k = k0 + threadIdx.x;
        float v = tile[threadIdx.x][i];
        __nv_bfloat16 h = __float2bfloat16(v);
        size_t base = (size_t)n * 2 * K;
        y[base + k]     = h;
        y[base + K + k] = __float2bfloat16(v - __bfloat162float(h));
    }
}

__global__ void rmsconv_kernel(const float* __restrict__ x, const float* __restrict__ w,
                               __nv_bfloat16* __restrict__ y) {
    int row = blockIdx.x;
    const float* xr = x + (size_t)row * HID;
    float s = 0.f;
    for (int i = threadIdx.x; i < HID; i += 256) { float v = xr[i]; s += v * v; }
    __shared__ float red[256];
    red[threadIdx.x] = s; __syncthreads();
    for (int st = 128; st > 0; st >>= 1) {
        if (threadIdx.x < st) red[threadIdx.x] += red[threadIdx.x + st];
        __syncthreads();
    }
    float r = rsqrtf(red[0] / (float)HID + 1e-6f);
    size_t base = (size_t)row * 2 * HID;
    for (int i = threadIdx.x; i < HID; i += 256) {
        float v = w[i] * xr[i] * r;
        __nv_bfloat16 h = __float2bfloat16(v);
        y[base + i] = h;
        y[base + HID + i] = __float2bfloat16(v - __bfloat162float(h));
    }
}

// ====== bf16 HMMA GEMM (3-segment hi/lo compensated), 128x256 tile ======
// 8 warps (wm 0..1, wn 0..3), warp tile 64x64, K-chunk 64, double buffer.
// smem: per buffer A 16KB + B 32KB = 48KB; two buffers = 96KB. 1 CTA/SM.
#define HG_SMEM 98304

__global__ void __launch_bounds__(256, 1) hgemm_kernel(
    const __nv_bfloat16* __restrict__ A, const __nv_bfloat16* __restrict__ B,
    const float* __restrict__ b1, const float* __restrict__ b2, const float* __restrict__ b3,
    int n1, int n2,
    const float* __restrict__ res,
    float* __restrict__ C, int N, int K)
{
    extern __shared__ char smraw[];
    const uint32_t smu = smem_u32(smraw);
    const int tid = threadIdx.x;
    const int lane = tid & 31, wid = tid >> 5;
    const int wm = wid >> 2, wn = wid & 3;
    const size_t lda = 2 * (size_t)K;
    const int kpseg = K >> 6;
    const int nch = 3 * kpseg;
    const size_t arow0 = (size_t)blockIdx.x * 128;
    const size_t brow0 = (size_t)blockIdx.y * 256;

    // decomposed swizzle: sw128(row*128+cb) = row*128 + (cb ^ ((lane&7)<<4))
    const uint32_t xm = (uint32_t)((lane & 7) << 4);
    uint32_t kbx[4];
#pragma unroll
    for (int ks = 0; ks < 4; ks++)
        kbx[ks] = ((uint32_t)(ks * 32 + ((lane >> 4) << 4))) ^ xm;
    uint32_t rowA[4], rowB[4];
#pragma unroll
    for (int mt = 0; mt < 4; mt++)
        rowA[mt] = (uint32_t)(wm * 64 + (lane & 15) + mt * 16) * 128u;
#pragma unroll
    for (int nt2 = 0; nt2 < 4; nt2++)
        rowB[nt2] = (uint32_t)(wn * 64 + (lane & 15) + nt2 * 16) * 128u;

    float acc[4][8][4];
#pragma unroll
    for (int i = 0; i < 4; i++)
#pragma unroll
        for (int j = 0; j < 8; j++)
#pragma unroll
            for (int t = 0; t < 4; t++) acc[i][j][t] = 0.f;

    auto issue = [&](int ch, int b) {
        int seg = ch / kpseg;
        int kk = (ch - seg * kpseg) << 6;
        const __nv_bfloat16* Ab = A + (seg == 1 ? K : 0) + kk;
        const __nv_bfloat16* Bb = B + (seg == 2 ? K : 0) + kk;
        uint32_t abase = smu + b * 49152;
        uint32_t bbase = abase + 16384;
#pragma unroll
        for (int i = 0; i < 4; i++) {          // A: 128 rows x 8 segs
            int u = i * 256 + tid;
            int r = u >> 3, c = u & 7;
            cp_async16(abase + sw128((uint32_t)(r * 128 + c * 16)),
                       Ab + (arow0 + r) * lda + c * 8);
        }
#pragma unroll
        for (int i = 0; i < 8; i++) {          // B: 256 rows x 8 segs
            int u = i * 256 + tid;
            int r = u >> 3, c = u & 7;
            cp_async16(bbase + sw128((uint32_t)(r * 128 + c * 16)),
                       Bb + (brow0 + r) * lda + c * 8);
        }
        cp_commit();
    };

    issue(0, 0);

    for (int ch = 0; ch < nch; ch++) {
        const int b = ch & 1;
        if (ch + 1 < nch) {
            issue(ch + 1, b ^ 1);
            asm volatile("cp.async.wait_group 1;");
        } else {
            asm volatile("cp.async.wait_group 0;");
        }
        __syncthreads();

        const uint32_t abuf = smu + b * 49152;
        const uint32_t bbuf = abuf + 16384;

#pragma unroll
        for (int ks = 0; ks < 4; ks++) {
            uint32_t a[4][4];
#pragma unroll
            for (int mt = 0; mt < 4; mt++)
                LDSM_X4(a[mt][0], a[mt][1], a[mt][2], a[mt][3],
                        abuf + rowA[mt] + kbx[ks]);
            uint32_t bf[8][2];
#pragma unroll
            for (int nt2 = 0; nt2 < 4; nt2++) {
                uint32_t t0, t1, t2, t3;
                LDSM_X4(t0, t1, t2, t3, bbuf + rowB[nt2] + kbx[ks]);
                bf[nt2 * 2 + 0][0] = t0; bf[nt2 * 2 + 0][1] = t2;
                bf[nt2 * 2 + 1][0] = t1; bf[nt2 * 2 + 1][1] = t3;
            }
#pragma unroll
            for (int mt = 0; mt < 4; mt++)
#pragma unroll
                for (int nt = 0; nt < 8; nt++)
                    MMA16816(acc[mt][nt], a[mt], bf[nt][0], bf[nt][1]);
        }
        __syncthreads();
    }

    // epilogue
    const int rbase = (int)arow0 + wm * 64 + (lane >> 2);
    const int cbase = (int)brow0 + wn * 64 + ((lane & 3) << 1);
#pragma unroll
    for (int nt = 0; nt < 8; nt++) {
        const int col = cbase + (nt << 3);
        float bv0 = 0.f, bv1 = 0.f;
        if (b1) {
            if (col < n1)       { bv0 = b1[col];      bv1 = b1[col + 1]; }
            else if (col < n2)  { bv0 = b2[col - n1]; bv1 = b2[col - n1 + 1]; }
            else                { bv0 = b3[col - n2]; bv1 = b3[col - n2 + 1]; }
        }
#pragma unroll
        for (int mt = 0; mt < 4; mt++) {
            const int row = rbase + (mt << 4);
            size_t gi = (size_t)row * N + col;
            float v0 = acc[mt][nt][0] + bv0, v1 = acc[mt][nt][1] + bv1;
            if (res) { v0 += res[gi]; v1 += res[gi + 1]; }
            *(float2*)(C + gi) = make_float2(v0, v1);
            size_t gi2 = gi + (size_t)8 * N;
            float v2 = acc[mt][nt][2] + bv0, v3 = acc[mt][nt][3] + bv1;
            if (res) { v2 += res[gi2]; v3 += res[gi2 + 1]; }
            *(float2*)(C + gi2) = make_float2(v2, v3);
        }
    }
}

// ================= small fp32 SGEMM (gate path only) =================
__global__ void __launch_bounds__(256) sgemm_kernel(
    const float* __restrict__ A, const float* __restrict__ B,
    float* __restrict__ C, int M, int N, int K)
{
    __shared__ float As[8][128];
    __shared__ float Bs[8][128];
    const int tid = threadIdx.x;
    const int bx = blockIdx.x * 128;
    const int by = blockIdx.y * 128;
    const int tx = tid & 15;
    const int ty = tid >> 4;
    const int arow = tid >> 1;
    const int acol = (tid & 1) << 2;
    const int brow = tid >> 5;
    const int bcol = (tid & 31) << 2;

    const float* Ap = A + (size_t)(by + arow) * K + acol;
    const float* Bp = B + (size_t)brow * N + bx + bcol;

    float acc[8][8];
#pragma unroll
    for (int i = 0; i < 8; i++)
#pragma unroll
        for (int j = 0; j < 8; j++) acc[i][j] = 0.f;

    for (int k0 = 0; k0 < K; k0 += 8) {
        float4 av = *(const float4*)Ap;
        As[acol + 0][arow] = av.x;
        As[acol + 1][arow] = av.y;
        As[acol + 2][arow] = av.z;
        As[acol + 3][arow] = av.w;
        *(float4*)&Bs[brow][bcol] = *(const float4*)Bp;
        __syncthreads();
#pragma unroll
        for (int kk = 0; kk < 8; kk++) {
            float a[8], bb[8];
            *(float4*)&a[0] = *(const float4*)&As[kk][ty * 8];
            *(float4*)&a[4] = *(const float4*)&As[kk][ty * 8 + 4];
            *(float4*)&bb[0] = *(const float4*)&Bs[kk][tx * 8];
            *(float4*)&bb[4] = *(const float4*)&Bs[kk][tx * 8 + 4];
#pragma unroll
            for (int i = 0; i < 8; i++)
#pragma unroll
                for (int j = 0; j < 8; j++)
                    acc[i][j] += a[i] * bb[j];
        }
        __syncthreads();
        Ap += 8;
        Bp += (size_t)8 * N;
    }

    const int row0 = by + ty * 8;
    const int col0 = bx + tx * 8;
#pragma unroll
    for (int i = 0; i < 8; i++)
#pragma unroll
        for (int j = 0; j < 8; j++)
            C[(size_t)(row0 + i) * N + col0 + j] = acc[i][j];
}

// ================= pooling / gate / rope =================
__global__ void pool_kernel(const float* __restrict__ x, int stride,
                            float* __restrict__ out, int H) {
    int qb = blockIdx.x, h = blockIdx.y, d = threadIdx.x;
    float s = 0.f;
    for (int i = 0; i < BSZ; i++)
        s += x[(size_t)(qb * BSZ + i) * stride + h * DH + d];
    out[((size_t)qb * H + h) * DH + d] = s * (1.f / (float)BSZ);
}

__global__ void gate_kernel(const float* __restrict__ qg, const float* __restrict__ kg,
                            unsigned char* __restrict__ keep) {
    int h = blockIdx.x, qb = blockIdx.y, kb = threadIdx.x;
    const float* qv = qg + ((size_t)qb * HQ + h) * GHD;
    const float* kv = kg + ((size_t)kb * HKV + (h >> 2)) * GHD;
    float s = 0.f;
    for (int d = 0; d < GHD; d++) s += qv[d] * kv[d];
    s *= SCALE_INV_SQRT_128;
    if (kb > qb) s = -1e30f;
    float m = s;
    for (int off = 16; off > 0; off >>= 1)
        m = fmaxf(m, __shfl_xor_sync(0xffffffffu, m, off));
    float e = expf(s - m);
    float sum = e;
    for (int off = 16; off > 0; off >>= 1)
        sum += __shfl_xor_sync(0xffffffffu, sum, off);
    float gate = e / sum;
    bool kp = (kb <= qb) && ((gate >= 0.004f) || (kb == qb));
    keep[((size_t)h * QBN + qb) * QBN + kb] = kp ? 1 : 0;
}

__global__ void rope_kernel(float* __restrict__ x, int stride,
                            const float* __restrict__ cs, const float* __restrict__ sn, int H) {
    int idx = blockIdx.x * blockDim.x + threadIdx.x;
    int d = idx & 63;
    int h = (idx >> 6) % H;
    int s = idx / (64 * H);
    float* p = x + (size_t)s * stride + h * DH;
    float x1 = p[d], x2 = p[d + 64];
    float c1 = cs[(size_t)s * DH + d],      s1 = sn[(size_t)s * DH + d];
    float c2 = cs[(size_t)s * DH + d + 64], s2 = sn[(size_t)s * DH + d + 64];
    p[d]      = x1 * c1 - x2 * s1;
    p[d + 64] = x2 * c2 + x1 * s2;
}

// ================= tf32 tensor-core block-sparse flash attention =================
#define ATP 132
#define APP 68
#define AQ_OFF   0
#define AK_OFF   (64*ATP)
#define AV_OFF   (2*64*ATP)
#define AP_OFF   (3*64*ATP)
#define ARM_OFF  (AP_OFF + 64*APP)
#define ARL_OFF  (ARM_OFF + 128)
#define AROWM    (ARL_OFF + 128)
#define AROWL    (AROWM + 64)
#define AALF     (AROWL + 64)
#define ATTN_SM_FLOATS (AALF + 64)

__global__ void __launch_bounds__(256, 1) attn_kernel(
    const float* __restrict__ qkv,
    const unsigned char* __restrict__ keep, __nv_bfloat16* __restrict__ oa2)
{
    extern __shared__ float sm[];
    const uint32_t* smu = (const uint32_t*)sm;

    const int qb = QBN - 1 - blockIdx.x;
    const int h = blockIdx.y;
    const int hk = h >> 2;
    const int tid = threadIdx.x;
    const int lane = tid & 31, wid = tid >> 5;
    const int rw = wid & 3, cw = wid >> 2;
    const int g = lane >> 2, qd = lane & 3;
    const int r0 = rw * 16 + g;
    const int r1 = r0 + 8;

    for (int i = tid; i < 64 * 32; i += 256) {
        int t = i >> 5, d4 = (i & 31) << 2;
        float4 qv = *(const float4*)&qkv[(size_t)(qb * 64 + t) * NQKV + h * DH + d4];
        float* dst = sm + AQ_OFF + t * ATP + d4;
        dst[0] = tf32r(qv.x * SCALE_INV_SQRT_128);
        dst[1] = tf32r(qv.y * SCALE_INV_SQRT_128);
        dst[2] = tf32r(qv.z * SCALE_INV_SQRT_128);
        dst[3] = tf32r(qv.w * SCALE_INV_SQRT_128);
    }
    if (tid < 64) { sm[AROWM + tid] = -1e30f; sm[AROWL + tid] = 0.f; }

    float oacc[8][4];
#pragma unroll
    for (int i = 0; i < 8; i++)
#pragma unroll
        for (int j = 0; j < 4; j++) oacc[i][j] = 0.f;

    const unsigned char* krow = keep + ((size_t)h * QBN + qb) * QBN;

    for (int kb = 0; kb <= qb; kb++) {
        if (!krow[kb]) continue;
        __syncthreads();

        for (int i = tid; i < 64 * 32; i += 256) {
            int t = i >> 5, d4 = (i & 31) << 2;
            size_t gi = (size_t)(kb * 64 + t) * NQKV + hk * DH + d4;
            float4 kvv = *(const float4*)&qkv[gi + 2048];
            float* kd = sm + AK_OFF + t * ATP + d4;
            kd[0] = tf32r(kvv.x); kd[1] = tf32r(kvv.y); kd[2] = tf32r(kvv.z); kd[3] = tf32r(kvv.w);
            float4 vvv = *(const float4*)&qkv[gi + 2560];
            float* vd = sm + AV_OFF + t * ATP + d4;
            vd[0] = tf32r(vvv.x); vd[1] = tf32r(vvv.y); vd[2] = tf32r(vvv.z); vd[3] = tf32r(vvv.w);
        }
        __syncthreads();

        float sacc[4][4];
#pragma unroll
        for (int i = 0; i < 4; i++)
#pragma unroll
            for (int j = 0; j < 4; j++) sacc[i][j] = 0.f;

#pragma unroll
        for (int ks = 0; ks < 16; ks++) {
            const int k0 = ks * 8;
            uint32_t a[4];
            a[0] = smu[AQ_OFF + r0 * ATP + k0 + qd];
            a[1] = smu[AQ_OFF + r1 * ATP + k0 + qd];
            a[2] = smu[AQ_OFF + r0 * ATP + k0 + qd + 4];
            a[3] = smu[AQ_OFF + r1 * ATP + k0 + qd + 4];
#pragma unroll
            for (int nt = 0; nt < 4; nt++) {
                const int n = cw * 32 + nt * 8 + g;
                uint32_t b0 = smu[AK_OFF + n * ATP + k0 + qd];
                uint32_t b1 = smu[AK_OFF + n * ATP + k0 + qd + 4];
                MMATF32(sacc[nt], a, b0, b1);
            }
        }

        if (kb == qb) {
#pragma unroll
            for (int nt = 0; nt < 4; nt++) {
                const int c0 = cw * 32 + nt * 8 + qd * 2;
                if (c0 > r0)     sacc[nt][0] = -1e30f;
                if (c0 + 1 > r0) sacc[nt][1] = -1e30f;
                if (c0 > r1)     sacc[nt][2] = -1e30f;
                if (c0 + 1 > r1) sacc[nt][3] = -1e30f;
            }
        }

        float m0 = -1e30f, m1 = -1e30f;
#pragma unroll
        for (int nt = 0; nt < 4; nt++) {
            m0 = fmaxf(m0, fmaxf(sacc[nt][0], sacc[nt][1]));
            m1 = fmaxf(m1, fmaxf(sacc[nt][2], sacc[nt][3]));
        }
        m0 = fmaxf(m0, __shfl_xor_sync(0xffffffffu, m0, 1));
        m0 = fmaxf(m0, __shfl_xor_sync(0xffffffffu, m0, 2));
        m1 = fmaxf(m1, __shfl_xor_sync(0xffffffffu, m1, 1));
        m1 = fmaxf(m1, __shfl_xor_sync(0xffffffffu, m1, 2));
        if (qd == 0) {
            sm[ARM_OFF + cw * 64 + r0] = m0;
            sm[ARM_OFF + cw * 64 + r1] = m1;
        }
        __syncthreads();

        if (tid < 64) {
            float newm = fmaxf(sm[AROWM + tid],
                               fmaxf(sm[ARM_OFF + tid], sm[ARM_OFF + 64 + tid]));
            sm[AALF + tid] = __expf(sm[AROWM + tid] - newm);
            sm[AROWM + tid] = newm;
        }
        __syncthreads();

        const float nm0 = sm[AROWM + r0];
        const float nm1 = sm[AROWM + r1];
        float l0 = 0.f, l1 = 0.f;
#pragma unroll
        for (int nt = 0; nt < 4; nt++) {
            const int c0 = cw * 32 + nt * 8 + qd * 2;
            float p0 = __expf(sacc[nt][0] - nm0);
            float p1 = __expf(sacc[nt][1] - nm0);
            float p2 = __expf(sacc[nt][2] - nm1);
            float p3 = __expf(sacc[nt][3] - nm1);
            l0 += p0 + p1; l1 += p2 + p3;
            sm[AP_OFF + r0 * APP + c0]     = tf32r(p0);
            sm[AP_OFF + r0 * APP + c0 + 1] = tf32r(p1);
            sm[AP_OFF + r1 * APP + c0]     = tf32r(p2);
            sm[AP_OFF + r1 * APP + c0 + 1] = tf32r(p3);
        }
        l0 += __shfl_xor_sync(0xffffffffu, l0, 1);
        l0 += __shfl_xor_sync(0xffffffffu, l0, 2);
        l1 += __shfl_xor_sync(0xffffffffu, l1, 1);
        l1 += __shfl_xor_sync(0xffffffffu, l1, 2);
        if (qd == 0) {
            sm[ARL_OFF + cw * 64 + r0] = l0;
            sm[ARL_OFF + cw * 64 + r1] = l1;
        }
        const float al0 = sm[AALF + r0];
        const float al1 = sm[AALF + r1];
#pragma unroll
        for (int nt = 0; nt < 8; nt++) {
            oacc[nt][0] *= al0; oacc[nt][1] *= al0;
            oacc[nt][2] *= al1; oacc[nt][3] *= al1;
        }
        __syncthreads();

        if (tid < 64)
            sm[AROWL + tid] = sm[AROWL + tid] * sm[AALF + tid]
                            + sm[ARL_OFF + tid] + sm[ARL_OFF + 64 + tid];

#pragma unroll
        for (int ks = 0; ks < 8; ks++) {
            const int k0 = ks * 8;
            uint32_t a[4];
            a[0] = smu[AP_OFF + r0 * APP + k0 + qd];
            a[1] = smu[AP_OFF + r1 * APP + k0 + qd];
            a[2] = smu[AP_OFF + r0 * APP + k0 + qd + 4];
            a[3] = smu[AP_OFF + r1 * APP + k0 + qd + 4];
#pragma unroll
            for (int nt = 0; nt < 8; nt++) {
                const int n = cw * 64 + nt * 8 + g;
                uint32_t b0 = smu[AV_OFF + (k0 + qd) * ATP + n];
                uint32_t b1 = smu[AV_OFF + (k0 + qd + 4) * ATP + n];
                MMATF32(oacc[nt], a, b0, b1);
            }
        }
    }

    __syncthreads();
    const float inv0 = 1.f / sm[AROWL + r0];
    const float inv1 = 1.f / sm[AROWL + r1];
    const size_t grow0 = (size_t)(qb * 64 + r0);
    const size_t grow1 = (size_t)(qb * 64 + r1);
#pragma unroll
    for (int nt = 0; nt < 8; nt++) {
        const int col = h * DH + cw * 64 + nt * 8 + qd * 2;
#pragma unroll
        for (int j = 0; j < 2; j++) {
            float v0 = oacc[nt][j] * inv0;
            __nv_bfloat16 h0 = __float2bfloat16(v0);
            oa2[grow0 * 4096 + col + j] = h0;
            oa2[grow0 * 4096 + 2048 + col + j] = __float2bfloat16(v0 - __bfloat162float(h0));
            float v1 = oacc[nt][j + 2] * inv1;
            __nv_bfloat16 h1 = __float2bfloat16(v1);
            oa2[grow1 * 4096 + col + j] = h1;
            oa2[grow1 * 4096 + 2048 + col + j] = __float2bfloat16(v1 - __bfloat162float(h1));
        }
    }
}

// ================= SiLU(gate)*up fused with bf16 split conversion ============
__global__ void siluconv_kernel(const float* __restrict__ gu, __nv_bfloat16* __restrict__ y) {
    int s = blockIdx.y;
    int j = blockIdx.x * 256 + threadIdx.x;
    size_t row = (size_t)s * NGU;
    float x = gu[row + j];
    float u = gu[row + INTER + j];
    float v = (x / (1.f + __expf(-x))) * u;
    __nv_bfloat16 hi = __float2bfloat16(v);
    y[row + j] = hi;
    y[row + INTER + j] = __float2bfloat16(v - __bfloat162float(hi));
}

// ================= launch =================
extern "C" void kernel_launch(void* const* d_in, const int* in_sizes, int n_in,
                              void* d_out, int out_size) {
    const float* hidden = (const float*)d_in[0];
    const float* cosp   = (const float*)d_in[1];
    const float* sinp   = (const float*)d_in[2];
    const float* ln1    = (const float*)d_in[3];
    const float* ln2    = (const float*)d_in[4];
    const float* Wq     = (const float*)d_in[5];
    const float* bq     = (const float*)d_in[6];
    const float* Wk     = (const float*)d_in[7];
    const float* bk     = (const float*)d_in[8];
    const float* Wv     = (const float*)d_in[9];
    const float* bv     = (const float*)d_in[10];
    const float* Wo     = (const float*)d_in[11];
    const float* gWq    = (const float*)d_in[12];
    const float* gWk    = (const float*)d_in[13];
    const float* Wgate  = (const float*)d_in[14];
    const float* Wup    = (const float*)d_in[15];
    const float* Wdown  = (const float*)d_in[16];
    float* out = (float*)d_out;

    float *qkv, *qp, *kp, *qg, *kg, *h2, *gu;
    unsigned char* keep;
    __nv_bfloat16 *Wqkv2, *Wo2, *Wgu2, *Wd2, *ha2, *oa2, *h3a2, *gt2;
    cudaGetSymbolAddress((void**)&qkv,  g_qkv);
    cudaGetSymbolAddress((void**)&qp,   g_qp);
    cudaGetSymbolAddress((void**)&kp,   g_kp);
    cudaGetSymbolAddress((void**)&qg,   g_qg);
    cudaGetSymbolAddress((void**)&kg,   g_kg);
    cudaGetSymbolAddress((void**)&keep, g_keep);
    cudaGetSymbolAddress((void**)&h2,   g_h2);
    cudaGetSymbolAddress((void**)&gu,   g_gu);
    cudaGetSymbolAddress((void**)&Wqkv2, g_Wqkv2);
    cudaGetSymbolAddress((void**)&Wo2,  g_Wo2);
    cudaGetSymbolAddress((void**)&Wgu2, g_Wgu2);
    cudaGetSymbolAddress((void**)&Wd2,  g_Wd2);
    cudaGetSymbolAddress((void**)&ha2,  g_ha2);
    cudaGetSymbolAddress((void**)&oa2,  g_oa2);
    cudaGetSymbolAddress((void**)&h3a2, g_h3a2);
    cudaGetSymbolAddress((void**)&gt2,  g_gt2);

    cudaFuncSetAttribute(hgemm_kernel, cudaFuncAttributeMaxDynamicSharedMemorySize, HG_SMEM);
    cudaFuncSetAttribute(attn_kernel, cudaFuncAttributeMaxDynamicSharedMemorySize,
                         ATTN_SM_FLOATS * (int)sizeof(float));

    dim3 w8(32, 8);
    cudaStream_t s2 = g_aux.s2;

    // ---- fork side stream: weight conversions + gate path off critical path ----
    cudaEventRecord(g_aux.root, 0);
    cudaStreamWaitEvent(s2, g_aux.root, 0);
    wconv3_kernel<<<dim3(NQKV/32, HID/32), w8, 0, s2>>>(Wq, Wk, Wv, Wqkv2);
    cudaEventRecord(g_aux.evQKV, s2);
    wconv_kernel<<<dim3(HID/32, HID/32), w8, 0, s2>>>(Wo, Wo2, HID, HID);
    cudaEventRecord(g_aux.evWo, s2);
    wconv_kernel<<<dim3(INTER/32, HID/32), w8, 0, s2>>>(Wgate, Wgu2, HID, INTER);
    wconv_kernel<<<dim3(INTER/32, HID/32), w8, 0, s2>>>(Wup, Wgu2 + (size_t)INTER*4096, HID, INTER);
    cudaEventRecord(g_aux.evGU, s2);
    wconv_kernel<<<dim3(HID/32, INTER/32), w8, 0, s2>>>(Wdown, Wd2, INTER, HID);
    cudaEventRecord(g_aux.evWd, s2);

    // ---- main chain ----
    rmsconv_kernel<<<SEQ, 256>>>(hidden, ln1, ha2);
    cudaStreamWaitEvent(0, g_aux.evQKV, 0);
    hgemm_kernel<<<dim3(SEQ/128, NQKV/256), 256, HG_SMEM>>>(
        ha2, Wqkv2, bq, bk, bv, 2048, 2560, nullptr, qkv, NQKV, HID);

    // pools on main (pre-RoPE values), then gate path on s2 overlapping RoPE
    pool_kernel<<<dim3(QBN, HQ), DH>>>(qkv, NQKV, qp, HQ);
    pool_kernel<<<dim3(QBN, HKV), DH>>>(qkv + 2048, NQKV, kp, HKV);
    cudaEventRecord(g_aux.evPool, 0);
    cudaStreamWaitEvent(s2, g_aux.evPool, 0);
    sgemm_kernel<<<dim3(GHD/128, (QBN*HQ)/128), 256, 0, s2>>>(qp, gWq, qg, QBN*HQ, GHD, DH);
    sgemm_kernel<<<dim3(GHD/128, (QBN*HKV)/128), 256, 0, s2>>>(kp, gWk, kg, QBN*HKV, GHD, DH);
    gate_kernel<<<dim3(HQ, QBN), 32, 0, s2>>>(qg, kg, keep);
    cudaEventRecord(g_aux.evGate, s2);

    rope_kernel<<<(SEQ*HQ*64)/256, 256>>>(qkv, NQKV, cosp, sinp, HQ);
    rope_kernel<<<(SEQ*HKV*64)/256, 256>>>(qkv + 2048, NQKV, cosp, sinp, HKV);

    cudaStreamWaitEvent(0, g_aux.evGate, 0);
    attn_kernel<<<dim3(QBN, HQ), 256, ATTN_SM_FLOATS * (int)sizeof(float)>>>(qkv, keep, oa2);

    cudaStreamWaitEvent(0, g_aux.evWo, 0);
    hgemm_kernel<<<dim3(SEQ/128, HID/256), 256, HG_SMEM>>>(
        oa2, Wo2, nullptr, nullptr, nullptr, HID, HID, hidden, h2, HID, HQ*DH);

    rmsconv_kernel<<<SEQ, 256>>>(h2, ln2, h3a2);

    cudaStreamWaitEvent(0, g_aux.evGU, 0);
    hgemm_kernel<<<dim3(SEQ/128, NGU/256), 256, HG_SMEM>>>(
        h3a2, Wgu2, nullptr, nullptr, nullptr, NGU, NGU, nullptr, gu, NGU, HID);

    siluconv_kernel<<<dim3(INTER/256, SEQ), 256>>>(gu, gt2);

    cudaStreamWaitEvent(0, g_aux.evWd, 0);
    hgemm_kernel<<<dim3(SEQ/128, HID/256), 256, HG_SMEM>>>(
        gt2, Wd2, nullptr, nullptr, nullptr, HID, HID, h2, out, HID, INTER);
}

// round 10
// speedup vs baseline: 3.0404x; 1.4196x over previous
#include <cuda_runtime.h>
#include <cuda_fp16.h>
#include <cuda_bf16.h>
#include <math.h>
#include <stdint.h>

#define SEQ   2048
#define HID   2048
#define HQ    16
#define HKV   4
#define DH    128
#define QBN   32
#define BSZ   64
#define GHD   128
#define INTER 5632
#define NQKV  3072
#define NGU   11264

#define SCALE_INV_SQRT_128 0.08838834764831845f

// ================= helpers =================
__device__ __forceinline__ uint32_t smem_u32(const void* p) {
    uint32_t a;
    asm("{ .reg .u64 t; cvta.to.shared.u64 t, %1; cvt.u32.u64 %0, t; }" : "=r"(a) : "l"(p));
    return a;
}
__device__ __forceinline__ void cp_async16(uint32_t saddr, const void* gptr) {
    asm volatile("cp.async.cg.shared.global [%0], [%1], 16;" :: "r"(saddr), "l"(gptr));
}
__device__ __forceinline__ void cp_commit() { asm volatile("cp.async.commit_group;"); }

#define LDSM_X4(r0, r1, r2, r3, addr) \
    asm volatile("ldmatrix.sync.aligned.m8n8.x4.shared.b16 {%0,%1,%2,%3}, [%4];" \
        : "=r"(r0), "=r"(r1), "=r"(r2), "=r"(r3) : "r"(addr))

#define MMAF16(c, a, b0r, b1r) \
    asm volatile("mma.sync.aligned.m16n8k16.row.col.f32.f16.f16.f32 " \
        "{%0,%1,%2,%3}, {%4,%5,%6,%7}, {%8,%9}, {%0,%1,%2,%3};" \
        : "+f"((c)[0]), "+f"((c)[1]), "+f"((c)[2]), "+f"((c)[3]) \
        : "r"((a)[0]), "r"((a)[1]), "r"((a)[2]), "r"((a)[3]), "r"(b0r), "r"(b1r))

#define MMATF32(c, a, b0r, b1r) \
    asm volatile("mma.sync.aligned.m16n8k8.row.col.f32.tf32.tf32.f32 " \
        "{%0,%1,%2,%3}, {%4,%5,%6,%7}, {%8,%9}, {%0,%1,%2,%3};" \
        : "+f"((c)[0]), "+f"((c)[1]), "+f"((c)[2]), "+f"((c)[3]) \
        : "r"((a)[0]), "r"((a)[1]), "r"((a)[2]), "r"((a)[3]), "r"(b0r), "r"(b1r))

static __device__ __forceinline__ uint32_t sw128(uint32_t o) { return o ^ ((o >> 3) & 0x70); }

__device__ __forceinline__ float tf32r(float v) {
    float r;
    asm("cvt.rna.tf32.f32 %0, %1;" : "=f"(r) : "f"(v));
    return r;
}

// ================= device scratch =================
__device__ float g_qkv [SEQ*NQKV];
__device__ float g_qp  [QBN*HQ*DH];
__device__ float g_kp  [QBN*HKV*DH];
__device__ float g_qg  [QBN*HQ*GHD];
__device__ float g_kg  [QBN*HKV*GHD];
__device__ unsigned char g_keep[HQ*QBN*QBN];
__device__ float g_h2  [SEQ*HID];
__device__ float g_gu  [SEQ*NGU];

// fp16 weights (single limb, K-major [N,K]) and activations (hi|lo, [M,2K])
__device__ __half g_Wqkv2[NQKV*HID];
__device__ __half g_Wo2  [2048*2048];
__device__ __half g_Wgu2 [NGU*HID];
__device__ __half g_Wd2  [2048*INTER];
__device__ __half g_ha2  [SEQ*2*HID];
__device__ __half g_oa2  [SEQ*2*HID];
__device__ __half g_h3a2 [SEQ*2*HID];
__device__ __half g_gt2  [SEQ*2*INTER];

// ===== side-stream resources (created pre-main in static init) =====
struct AuxRes {
    cudaStream_t s2;
    cudaEvent_t root, evQKV, evWo, evGU, evWd, evPool, evGate;
    AuxRes() {
        cudaStreamCreateWithFlags(&s2, cudaStreamNonBlocking);
        cudaEventCreateWithFlags(&root,   cudaEventDisableTiming);
        cudaEventCreateWithFlags(&evQKV,  cudaEventDisableTiming);
        cudaEventCreateWithFlags(&evWo,   cudaEventDisableTiming);
        cudaEventCreateWithFlags(&evGU,   cudaEventDisableTiming);
        cudaEventCreateWithFlags(&evWd,   cudaEventDisableTiming);
        cudaEventCreateWithFlags(&evPool, cudaEventDisableTiming);
        cudaEventCreateWithFlags(&evGate, cudaEventDisableTiming);
    }
};
static AuxRes g_aux;

// ===== fused QKV weight conversion: fp32 [K,N]x3 -> fp16 [3072, K] =====
__global__ void wconv3_kernel(const float* __restrict__ Wq, const float* __restrict__ Wk,
                              const float* __restrict__ Wv, __half* __restrict__ y) {
    __shared__ float tile[32][33];
    int n0 = blockIdx.x * 32, k0 = blockIdx.y * 32;
    const float* W; int sN, c0;
    if (n0 < 2048)      { W = Wq; sN = 2048; c0 = n0; }
    else if (n0 < 2560) { W = Wk; sN = 512;  c0 = n0 - 2048; }
    else                { W = Wv; sN = 512;  c0 = n0 - 2560; }
    for (int i = threadIdx.y; i < 32; i += 8)
        tile[i][threadIdx.x] = W[(size_t)(k0 + i) * sN + c0 + threadIdx.x];
    __syncthreads();
    for (int i = threadIdx.y; i < 32; i += 8) {
        int n = n0 + i, k = k0 + threadIdx.x;
        y[(size_t)n * HID + k] = __float2half_rn(tile[threadIdx.x][i]);
    }
}

// ===== weight conversion: fp32 [K,N] -> fp16 [N,K] =====
__global__ void wconv_kernel(const float* __restrict__ W, __half* __restrict__ y,
                             int K, int N) {
    __shared__ float tile[32][33];
    int n0 = blockIdx.x * 32, k0 = blockIdx.y * 32;
    for (int i = threadIdx.y; i < 32; i += 8)
        tile[i][threadIdx.x] = W[(size_t)(k0 + i) * N + n0 + threadIdx.x];
    __syncthreads();
    for (int i = threadIdx.y; i < 32; i += 8) {
        int n = n0 + i, k = k0 + threadIdx.x;
        y[(size_t)n * K + k] = __float2half_rn(tile[threadIdx.x][i]);
    }
}

// ===== RMSNorm fused with fp16 hi/lo split =====
__global__ void rmsconv_kernel(const float* __restrict__ x, const float* __restrict__ w,
                               __half* __restrict__ y) {
    int row = blockIdx.x;
    const float* xr = x + (size_t)row * HID;
    float s = 0.f;
    for (int i = threadIdx.x; i < HID; i += 256) { float v = xr[i]; s += v * v; }
    __shared__ float red[256];
    red[threadIdx.x] = s; __syncthreads();
    for (int st = 128; st > 0; st >>= 1) {
        if (threadIdx.x < st) red[threadIdx.x] += red[threadIdx.x + st];
        __syncthreads();
    }
    float r = rsqrtf(red[0] / (float)HID + 1e-6f);
    size_t base = (size_t)row * 2 * HID;
    for (int i = threadIdx.x; i < HID; i += 256) {
        float v = w[i] * xr[i] * r;
        __half h = __float2half_rn(v);
        y[base + i] = h;
        y[base + HID + i] = __float2half_rn(v - __half2float(h));
    }
}

// ====== fp16 HMMA GEMM, 2-segment hi/lo-A (C = (Ahi+Alo) x Bhi^T) ======
// A[M,2K] fp16 (hi|lo), B[N,K] fp16. CTA tile 128x128, 8 warps 2x4,
// warp tile 64x32, K-chunk 64, double-buffered cp.async, 2 CTA/SM.
#define HG_SMEM 65536

__global__ void __launch_bounds__(256, 2) hgemm_kernel(
    const __half* __restrict__ A, const __half* __restrict__ B,
    const float* __restrict__ b1, const float* __restrict__ b2, const float* __restrict__ b3,
    int n1, int n2,
    const float* __restrict__ res,
    float* __restrict__ C, int N, int K)
{
    extern __shared__ char smraw[];
    const uint32_t smu = smem_u32(smraw);
    const int tid = threadIdx.x;
    const int lane = tid & 31, wid = tid >> 5;
    const int wm = wid >> 2, wn = wid & 3;
    const size_t ldaA = 2 * (size_t)K;
    const size_t ldaB = (size_t)K;
    const int kpseg = K >> 6;
    const int nch = 2 * kpseg;
    const size_t arow0 = (size_t)blockIdx.x * 128;
    const size_t brow0 = (size_t)blockIdx.y * 128;

    // decomposed swizzle: sw128(row*128+cb) = row*128 + (cb ^ ((lane&7)<<4))
    const uint32_t xm = (uint32_t)((lane & 7) << 4);
    uint32_t kbx[4];
#pragma unroll
    for (int ks = 0; ks < 4; ks++)
        kbx[ks] = ((uint32_t)(ks * 32 + ((lane >> 4) << 4))) ^ xm;
    uint32_t rowA[4], rowB[2];
#pragma unroll
    for (int mt = 0; mt < 4; mt++)
        rowA[mt] = (uint32_t)((wm << 6) + (lane & 15) + (mt << 4)) * 128u;
#pragma unroll
    for (int nt2 = 0; nt2 < 2; nt2++)
        rowB[nt2] = (uint32_t)((wn << 5) + (lane & 15) + (nt2 << 4)) * 128u;

    float acc[4][4][4];
#pragma unroll
    for (int i = 0; i < 4; i++)
#pragma unroll
        for (int j = 0; j < 4; j++)
#pragma unroll
            for (int t = 0; t < 4; t++) acc[i][j][t] = 0.f;

    auto issue = [&](int ch, int b) {
        int seg = ch / kpseg;
        int kk = (ch - seg * kpseg) << 6;
        const __half* Ab = A + (seg == 1 ? K : 0) + kk;
        const __half* Bb = B + kk;
        uint32_t abase = smu + b * 32768;
        uint32_t bbase = abase + 16384;
#pragma unroll
        for (int i = 0; i < 4; i++) {
            int u = i * 256 + tid;
            int r = u >> 3, c = u & 7;
            uint32_t so = sw128((uint32_t)(r * 128 + c * 16));
            cp_async16(abase + so, Ab + (arow0 + r) * ldaA + c * 8);
            cp_async16(bbase + so, Bb + (brow0 + r) * ldaB + c * 8);
        }
        cp_commit();
    };

    issue(0, 0);

    for (int ch = 0; ch < nch; ch++) {
        const int b = ch & 1;
        if (ch + 1 < nch) {
            issue(ch + 1, b ^ 1);
            asm volatile("cp.async.wait_group 1;");
        } else {
            asm volatile("cp.async.wait_group 0;");
        }
        __syncthreads();

        const uint32_t abuf = smu + b * 32768;
        const uint32_t bbuf = abuf + 16384;

#pragma unroll
        for (int ks = 0; ks < 4; ks++) {
            uint32_t a[4][4];
#pragma unroll
            for (int mt = 0; mt < 4; mt++)
                LDSM_X4(a[mt][0], a[mt][1], a[mt][2], a[mt][3],
                        abuf + rowA[mt] + kbx[ks]);
            uint32_t bf[4][2];
#pragma unroll
            for (int nt2 = 0; nt2 < 2; nt2++) {
                uint32_t t0, t1, t2, t3;
                LDSM_X4(t0, t1, t2, t3, bbuf + rowB[nt2] + kbx[ks]);
                bf[nt2 * 2 + 0][0] = t0; bf[nt2 * 2 + 0][1] = t2;
                bf[nt2 * 2 + 1][0] = t1; bf[nt2 * 2 + 1][1] = t3;
            }
#pragma unroll
            for (int mt = 0; mt < 4; mt++)
#pragma unroll
                for (int nt = 0; nt < 4; nt++)
                    MMAF16(acc[mt][nt], a[mt], bf[nt][0], bf[nt][1]);
        }
        __syncthreads();
    }

    const int rbase = (int)arow0 + (wm << 6) + (lane >> 2);
    const int cbase = (int)brow0 + (wn << 5) + ((lane & 3) << 1);
#pragma unroll
    for (int nt = 0; nt < 4; nt++) {
        const int col = cbase + (nt << 3);
        float bv0 = 0.f, bv1 = 0.f;
        if (b1) {
            if (col < n1)       { bv0 = b1[col];      bv1 = b1[col + 1]; }
            else if (col < n2)  { bv0 = b2[col - n1]; bv1 = b2[col - n1 + 1]; }
            else                { bv0 = b3[col - n2]; bv1 = b3[col - n2 + 1]; }
        }
#pragma unroll
        for (int mt = 0; mt < 4; mt++) {
            const int row = rbase + (mt << 4);
            size_t gi = (size_t)row * N + col;
            float v0 = acc[mt][nt][0] + bv0, v1 = acc[mt][nt][1] + bv1;
            if (res) { v0 += res[gi]; v1 += res[gi + 1]; }
            *(float2*)(C + gi) = make_float2(v0, v1);
            size_t gi2 = gi + (size_t)8 * N;
            float v2 = acc[mt][nt][2] + bv0, v3 = acc[mt][nt][3] + bv1;
            if (res) { v2 += res[gi2]; v3 += res[gi2 + 1]; }
            *(float2*)(C + gi2) = make_float2(v2, v3);
        }
    }
}

// ================= small fp32 SGEMM (gate path only) =================
__global__ void __launch_bounds__(256) sgemm_kernel(
    const float* __restrict__ A, const float* __restrict__ B,
    float* __restrict__ C, int M, int N, int K)
{
    __shared__ float As[8][128];
    __shared__ float Bs[8][128];
    const int tid = threadIdx.x;
    const int bx = blockIdx.x * 128;
    const int by = blockIdx.y * 128;
    const int tx = tid & 15;
    const int ty = tid >> 4;
    const int arow = tid >> 1;
    const int acol = (tid & 1) << 2;
    const int brow = tid >> 5;
    const int bcol = (tid & 31) << 2;

    const float* Ap = A + (size_t)(by + arow) * K + acol;
    const float* Bp = B + (size_t)brow * N + bx + bcol;

    float acc[8][8];
#pragma unroll
    for (int i = 0; i < 8; i++)
#pragma unroll
        for (int j = 0; j < 8; j++) acc[i][j] = 0.f;

    for (int k0 = 0; k0 < K; k0 += 8) {
        float4 av = *(const float4*)Ap;
        As[acol + 0][arow] = av.x;
        As[acol + 1][arow] = av.y;
        As[acol + 2][arow] = av.z;
        As[acol + 3][arow] = av.w;
        *(float4*)&Bs[brow][bcol] = *(const float4*)Bp;
        __syncthreads();
#pragma unroll
        for (int kk = 0; kk < 8; kk++) {
            float a[8], bb[8];
            *(float4*)&a[0] = *(const float4*)&As[kk][ty * 8];
            *(float4*)&a[4] = *(const float4*)&As[kk][ty * 8 + 4];
            *(float4*)&bb[0] = *(const float4*)&Bs[kk][tx * 8];
            *(float4*)&bb[4] = *(const float4*)&Bs[kk][tx * 8 + 4];
#pragma unroll
            for (int i = 0; i < 8; i++)
#pragma unroll
                for (int j = 0; j < 8; j++)
                    acc[i][j] += a[i] * bb[j];
        }
        __syncthreads();
        Ap += 8;
        Bp += (size_t)8 * N;
    }

    const int row0 = by + ty * 8;
    const int col0 = bx + tx * 8;
#pragma unroll
    for (int i = 0; i < 8; i++)
#pragma unroll
        for (int j = 0; j < 8; j++)
            C[(size_t)(row0 + i) * N + col0 + j] = acc[i][j];
}

// ================= pooling / gate / rope =================
__global__ void pool_kernel(const float* __restrict__ x, int stride,
                            float* __restrict__ out, int H) {
    int qb = blockIdx.x, h = blockIdx.y, d = threadIdx.x;
    float s = 0.f;
    for (int i = 0; i < BSZ; i++)
        s += x[(size_t)(qb * BSZ + i) * stride + h * DH + d];
    out[((size_t)qb * H + h) * DH + d] = s * (1.f / (float)BSZ);
}

__global__ void gate_kernel(const float* __restrict__ qg, const float* __restrict__ kg,
                            unsigned char* __restrict__ keep) {
    int h = blockIdx.x, qb = blockIdx.y, kb = threadIdx.x;
    const float* qv = qg + ((size_t)qb * HQ + h) * GHD;
    const float* kv = kg + ((size_t)kb * HKV + (h >> 2)) * GHD;
    float s = 0.f;
    for (int d = 0; d < GHD; d++) s += qv[d] * kv[d];
    s *= SCALE_INV_SQRT_128;
    if (kb > qb) s = -1e30f;
    float m = s;
    for (int off = 16; off > 0; off >>= 1)
        m = fmaxf(m, __shfl_xor_sync(0xffffffffu, m, off));
    float e = expf(s - m);
    float sum = e;
    for (int off = 16; off > 0; off >>= 1)
        sum += __shfl_xor_sync(0xffffffffu, sum, off);
    float gate = e / sum;
    bool kp = (kb <= qb) && ((gate >= 0.004f) || (kb == qb));
    keep[((size_t)h * QBN + qb) * QBN + kb] = kp ? 1 : 0;
}

__global__ void rope_kernel(float* __restrict__ x, int stride,
                            const float* __restrict__ cs, const float* __restrict__ sn, int H) {
    int idx = blockIdx.x * blockDim.x + threadIdx.x;
    int d = idx & 63;
    int h = (idx >> 6) % H;
    int s = idx / (64 * H);
    float* p = x + (size_t)s * stride + h * DH;
    float x1 = p[d], x2 = p[d + 64];
    float c1 = cs[(size_t)s * DH + d],      s1 = sn[(size_t)s * DH + d];
    float c2 = cs[(size_t)s * DH + d + 64], s2 = sn[(size_t)s * DH + d + 64];
    p[d]      = x1 * c1 - x2 * s1;
    p[d + 64] = x2 * c2 + x1 * s2;
}

// ================= tf32 tensor-core block-sparse flash attention =================
#define ATP 132
#define APP 68
#define AQ_OFF   0
#define AK_OFF   (64*ATP)
#define AV_OFF   (2*64*ATP)
#define AP_OFF   (3*64*ATP)
#define ARM_OFF  (AP_OFF + 64*APP)
#define ARL_OFF  (ARM_OFF + 128)
#define AROWM    (ARL_OFF + 128)
#define AROWL    (AROWM + 64)
#define AALF     (AROWL + 64)
#define ATTN_SM_FLOATS (AALF + 64)

__global__ void __launch_bounds__(256, 1) attn_kernel(
    const float* __restrict__ qkv,
    const unsigned char* __restrict__ keep, __half* __restrict__ oa2)
{
    extern __shared__ float sm[];
    const uint32_t* smu = (const uint32_t*)sm;

    const int qb = QBN - 1 - blockIdx.x;
    const int h = blockIdx.y;
    const int hk = h >> 2;
    const int tid = threadIdx.x;
    const int lane = tid & 31, wid = tid >> 5;
    const int rw = wid & 3, cw = wid >> 2;
    const int g = lane >> 2, qd = lane & 3;
    const int r0 = rw * 16 + g;
    const int r1 = r0 + 8;

    for (int i = tid; i < 64 * 32; i += 256) {
        int t = i >> 5, d4 = (i & 31) << 2;
        float4 qv = *(const float4*)&qkv[(size_t)(qb * 64 + t) * NQKV + h * DH + d4];
        float* dst = sm + AQ_OFF + t * ATP + d4;
        dst[0] = tf32r(qv.x * SCALE_INV_SQRT_128);
        dst[1] = tf32r(qv.y * SCALE_INV_SQRT_128);
        dst[2] = tf32r(qv.z * SCALE_INV_SQRT_128);
        dst[3] = tf32r(qv.w * SCALE_INV_SQRT_128);
    }
    if (tid < 64) { sm[AROWM + tid] = -1e30f; sm[AROWL + tid] = 0.f; }

    float oacc[8][4];
#pragma unroll
    for (int i = 0; i < 8; i++)
#pragma unroll
        for (int j = 0; j < 4; j++) oacc[i][j] = 0.f;

    const unsigned char* krow = keep + ((size_t)h * QBN + qb) * QBN;

    for (int kb = 0; kb <= qb; kb++) {
        if (!krow[kb]) continue;
        __syncthreads();

        for (int i = tid; i < 64 * 32; i += 256) {
            int t = i >> 5, d4 = (i & 31) << 2;
            size_t gi = (size_t)(kb * 64 + t) * NQKV + hk * DH + d4;
            float4 kvv = *(const float4*)&qkv[gi + 2048];
            float* kd = sm + AK_OFF + t * ATP + d4;
            kd[0] = tf32r(kvv.x); kd[1] = tf32r(kvv.y); kd[2] = tf32r(kvv.z); kd[3] = tf32r(kvv.w);
            float4 vvv = *(const float4*)&qkv[gi + 2560];
            float* vd = sm + AV_OFF + t * ATP + d4;
            vd[0] = tf32r(vvv.x); vd[1] = tf32r(vvv.y); vd[2] = tf32r(vvv.z); vd[3] = tf32r(vvv.w);
        }
        __syncthreads();

        float sacc[4][4];
#pragma unroll
        for (int i = 0; i < 4; i++)
#pragma unroll
            for (int j = 0; j < 4; j++) sacc[i][j] = 0.f;

#pragma unroll
        for (int ks = 0; ks < 16; ks++) {
            const int k0 = ks * 8;
            uint32_t a[4];
            a[0] = smu[AQ_OFF + r0 * ATP + k0 + qd];
            a[1] = smu[AQ_OFF + r1 * ATP + k0 + qd];
            a[2] = smu[AQ_OFF + r0 * ATP + k0 + qd + 4];
            a[3] = smu[AQ_OFF + r1 * ATP + k0 + qd + 4];
#pragma unroll
            for (int nt = 0; nt < 4; nt++) {
                const int n = cw * 32 + nt * 8 + g;
                uint32_t b0 = smu[AK_OFF + n * ATP + k0 + qd];
                uint32_t b1 = smu[AK_OFF + n * ATP + k0 + qd + 4];
                MMATF32(sacc[nt], a, b0, b1);
            }
        }

        if (kb == qb) {
#pragma unroll
            for (int nt = 0; nt < 4; nt++) {
                const int c0 = cw * 32 + nt * 8 + qd * 2;
                if (c0 > r0)     sacc[nt][0] = -1e30f;
                if (c0 + 1 > r0) sacc[nt][1] = -1e30f;
                if (c0 > r1)     sacc[nt][2] = -1e30f;
                if (c0 + 1 > r1) sacc[nt][3] = -1e30f;
            }
        }

        float m0 = -1e30f, m1 = -1e30f;
#pragma unroll
        for (int nt = 0; nt < 4; nt++) {
            m0 = fmaxf(m0, fmaxf(sacc[nt][0], sacc[nt][1]));
            m1 = fmaxf(m1, fmaxf(sacc[nt][2], sacc[nt][3]));
        }
        m0 = fmaxf(m0, __shfl_xor_sync(0xffffffffu, m0, 1));
        m0 = fmaxf(m0, __shfl_xor_sync(0xffffffffu, m0, 2));
        m1 = fmaxf(m1, __shfl_xor_sync(0xffffffffu, m1, 1));
        m1 = fmaxf(m1, __shfl_xor_sync(0xffffffffu, m1, 2));
        if (qd == 0) {
            sm[ARM_OFF + cw * 64 + r0] = m0;
            sm[ARM_OFF + cw * 64 + r1] = m1;
        }
        __syncthreads();

        if (tid < 64) {
            float newm = fmaxf(sm[AROWM + tid],
                               fmaxf(sm[ARM_OFF + tid], sm[ARM_OFF + 64 + tid]));
            sm[AALF + tid] = __expf(sm[AROWM + tid] - newm);
            sm[AROWM + tid] = newm;
        }
        __syncthreads();

        const float nm0 = sm[AROWM + r0];
        const float nm1 = sm[AROWM + r1];
        float l0 = 0.f, l1 = 0.f;
#pragma unroll
        for (int nt = 0; nt < 4; nt++) {
            const int c0 = cw * 32 + nt * 8 + qd * 2;
            float p0 = __expf(sacc[nt][0] - nm0);
            float p1 = __expf(sacc[nt][1] - nm0);
            float p2 = __expf(sacc[nt][2] - nm1);
            float p3 = __expf(sacc[nt][3] - nm1);
            l0 += p0 + p1; l1 += p2 + p3;
            sm[AP_OFF + r0 * APP + c0]     = tf32r(p0);
            sm[AP_OFF + r0 * APP + c0 + 1] = tf32r(p1);
            sm[AP_OFF + r1 * APP + c0]     = tf32r(p2);
            sm[AP_OFF + r1 * APP + c0 + 1] = tf32r(p3);
        }
        l0 += __shfl_xor_sync(0xffffffffu, l0, 1);
        l0 += __shfl_xor_sync(0xffffffffu, l0, 2);
        l1 += __shfl_xor_sync(0xffffffffu, l1, 1);
        l1 += __shfl_xor_sync(0xffffffffu, l1, 2);
        if (qd == 0) {
            sm[ARL_OFF + cw * 64 + r0] = l0;
            sm[ARL_OFF + cw * 64 + r1] = l1;
        }
        const float al0 = sm[AALF + r0];
        const float al1 = sm[AALF + r1];
#pragma unroll
        for (int nt = 0; nt < 8; nt++) {
            oacc[nt][0] *= al0; oacc[nt][1] *= al0;
            oacc[nt][2] *= al1; oacc[nt][3] *= al1;
        }
        __syncthreads();

        if (tid < 64)
            sm[AROWL + tid] = sm[AROWL + tid] * sm[AALF + tid]
                            + sm[ARL_OFF + tid] + sm[ARL_OFF + 64 + tid];

#pragma unroll
        for (int ks = 0; ks < 8; ks++) {
            const int k0 = ks * 8;
            uint32_t a[4];
            a[0] = smu[AP_OFF + r0 * APP + k0 + qd];
            a[1] = smu[AP_OFF + r1 * APP + k0 + qd];
            a[2] = smu[AP_OFF + r0 * APP + k0 + qd + 4];
            a[3] = smu[AP_OFF + r1 * APP + k0 + qd + 4];
#pragma unroll
            for (int nt = 0; nt < 8; nt++) {
                const int n = cw * 64 + nt * 8 + g;
                uint32_t b0 = smu[AV_OFF + (k0 + qd) * ATP + n];
                uint32_t b1 = smu[AV_OFF + (k0 + qd + 4) * ATP + n];
                MMATF32(oacc[nt], a, b0, b1);
            }
        }
    }

    __syncthreads();
    const float inv0 = 1.f / sm[AROWL + r0];
    const float inv1 = 1.f / sm[AROWL + r1];
    const size_t grow0 = (size_t)(qb * 64 + r0);
    const size_t grow1 = (size_t)(qb * 64 + r1);
#pragma unroll
    for (int nt = 0; nt < 8; nt++) {
        const int col = h * DH + cw * 64 + nt * 8 + qd * 2;
#pragma unroll
        for (int j = 0; j < 2; j++) {
            float v0 = oacc[nt][j] * inv0;
            __half h0 = __float2half_rn(v0);
            oa2[grow0 * 4096 + col + j] = h0;
            oa2[grow0 * 4096 + 2048 + col + j] = __float2half_rn(v0 - __half2float(h0));
            float v1 = oacc[nt][j + 2] * inv1;
            __half h1 = __float2half_rn(v1);
            oa2[grow1 * 4096 + col + j] = h1;
            oa2[grow1 * 4096 + 2048 + col + j] = __float2half_rn(v1 - __half2float(h1));
        }
    }
}

// ================= SiLU(gate)*up fused with fp16 hi/lo split ============
__global__ void siluconv_kernel(const float* __restrict__ gu, __half* __restrict__ y) {
    int s = blockIdx.y;
    int j = blockIdx.x * 256 + threadIdx.x;
    size_t row = (size_t)s * NGU;
    float x = gu[row + j];
    float u = gu[row + INTER + j];
    float v = (x / (1.f + __expf(-x))) * u;
    __half hi = __float2half_rn(v);
    y[row + j] = hi;
    y[row + INTER + j] = __float2half_rn(v - __half2float(hi));
}

// ================= launch =================
extern "C" void kernel_launch(void* const* d_in, const int* in_sizes, int n_in,
                              void* d_out, int out_size) {
    const float* hidden = (const float*)d_in[0];
    const float* cosp   = (const float*)d_in[1];
    const float* sinp   = (const float*)d_in[2];
    const float* ln1    = (const float*)d_in[3];
    const float* ln2    = (const float*)d_in[4];
    const float* Wq     = (const float*)d_in[5];
    const float* bq     = (const float*)d_in[6];
    const float* Wk     = (const float*)d_in[7];
    const float* bk     = (const float*)d_in[8];
    const float* Wv     = (const float*)d_in[9];
    const float* bv     = (const float*)d_in[10];
    const float* Wo     = (const float*)d_in[11];
    const float* gWq    = (const float*)d_in[12];
    const float* gWk    = (const float*)d_in[13];
    const float* Wgate  = (const float*)d_in[14];
    const float* Wup    = (const float*)d_in[15];
    const float* Wdown  = (const float*)d_in[16];
    float* out = (float*)d_out;

    float *qkv, *qp, *kp, *qg, *kg, *h2, *gu;
    unsigned char* keep;
    __half *Wqkv2, *Wo2, *Wgu2, *Wd2, *ha2, *oa2, *h3a2, *gt2;
    cudaGetSymbolAddress((void**)&qkv,  g_qkv);
    cudaGetSymbolAddress((void**)&qp,   g_qp);
    cudaGetSymbolAddress((void**)&kp,   g_kp);
    cudaGetSymbolAddress((void**)&qg,   g_qg);
    cudaGetSymbolAddress((void**)&kg,   g_kg);
    cudaGetSymbolAddress((void**)&keep, g_keep);
    cudaGetSymbolAddress((void**)&h2,   g_h2);
    cudaGetSymbolAddress((void**)&gu,   g_gu);
    cudaGetSymbolAddress((void**)&Wqkv2, g_Wqkv2);
    cudaGetSymbolAddress((void**)&Wo2,  g_Wo2);
    cudaGetSymbolAddress((void**)&Wgu2, g_Wgu2);
    cudaGetSymbolAddress((void**)&Wd2,  g_Wd2);
    cudaGetSymbolAddress((void**)&ha2,  g_ha2);
    cudaGetSymbolAddress((void**)&oa2,  g_oa2);
    cudaGetSymbolAddress((void**)&h3a2, g_h3a2);
    cudaGetSymbolAddress((void**)&gt2,  g_gt2);

    cudaFuncSetAttribute(hgemm_kernel, cudaFuncAttributeMaxDynamicSharedMemorySize, HG_SMEM);
    cudaFuncSetAttribute(attn_kernel, cudaFuncAttributeMaxDynamicSharedMemorySize,
                         ATTN_SM_FLOATS * (int)sizeof(float));

    dim3 w8(32, 8);
    cudaStream_t s2 = g_aux.s2;

    // ---- fork side stream: weight conversions + gate path off critical path ----
    cudaEventRecord(g_aux.root, 0);
    cudaStreamWaitEvent(s2, g_aux.root, 0);
    wconv3_kernel<<<dim3(NQKV/32, HID/32), w8, 0, s2>>>(Wq, Wk, Wv, Wqkv2);
    cudaEventRecord(g_aux.evQKV, s2);
    wconv_kernel<<<dim3(HID/32, HID/32), w8, 0, s2>>>(Wo, Wo2, HID, HID);
    cudaEventRecord(g_aux.evWo, s2);
    wconv_kernel<<<dim3(INTER/32, HID/32), w8, 0, s2>>>(Wgate, Wgu2, HID, INTER);
    wconv_kernel<<<dim3(INTER/32, HID/32), w8, 0, s2>>>(Wup, Wgu2 + (size_t)INTER*HID, HID, INTER);
    cudaEventRecord(g_aux.evGU, s2);
    wconv_kernel<<<dim3(HID/32, INTER/32), w8, 0, s2>>>(Wdown, Wd2, INTER, HID);
    cudaEventRecord(g_aux.evWd, s2);

    // ---- main chain ----
    rmsconv_kernel<<<SEQ, 256>>>(hidden, ln1, ha2);
    cudaStreamWaitEvent(0, g_aux.evQKV, 0);
    hgemm_kernel<<<dim3(SEQ/128, NQKV/128), 256, HG_SMEM>>>(
        ha2, Wqkv2, bq, bk, bv, 2048, 2560, nullptr, qkv, NQKV, HID);

    // pools on main (pre-RoPE values), then gate path on s2 overlapping RoPE
    pool_kernel<<<dim3(QBN, HQ), DH>>>(qkv, NQKV, qp, HQ);
    pool_kernel<<<dim3(QBN, HKV), DH>>>(qkv + 2048, NQKV, kp, HKV);
    cudaEventRecord(g_aux.evPool, 0);
    cudaStreamWaitEvent(s2, g_aux.evPool, 0);
    sgemm_kernel<<<dim3(GHD/128, (QBN*HQ)/128), 256, 0, s2>>>(qp, gWq, qg, QBN*HQ, GHD, DH);
    sgemm_kernel<<<dim3(GHD/128, (QBN*HKV)/128), 256, 0, s2>>>(kp, gWk, kg, QBN*HKV, GHD, DH);
    gate_kernel<<<dim3(HQ, QBN), 32, 0, s2>>>(qg, kg, keep);
    cudaEventRecord(g_aux.evGate, s2);

    rope_kernel<<<(SEQ*HQ*64)/256, 256>>>(qkv, NQKV, cosp, sinp, HQ);
    rope_kernel<<<(SEQ*HKV*64)/256, 256>>>(qkv + 2048, NQKV, cosp, sinp, HKV);

    cudaStreamWaitEvent(0, g_aux.evGate, 0);
    attn_kernel<<<dim3(QBN, HQ), 256, ATTN_SM_FLOATS * (int)sizeof(float)>>>(qkv, keep, oa2);

    cudaStreamWaitEvent(0, g_aux.evWo, 0);
    hgemm_kernel<<<dim3(SEQ/128, HID/128), 256, HG_SMEM>>>(
        oa2, Wo2, nullptr, nullptr, nullptr, HID, HID, hidden, h2, HID, HQ*DH);

    rmsconv_kernel<<<SEQ, 256>>>(h2, ln2, h3a2);

    cudaStreamWaitEvent(0, g_aux.evGU, 0);
    hgemm_kernel<<<dim3(SEQ/128, NGU/128), 256, HG_SMEM>>>(
        h3a2, Wgu2, nullptr, nullptr, nullptr, NGU, NGU, nullptr, gu, NGU, HID);

    siluconv_kernel<<<dim3(INTER/256, SEQ), 256>>>(gu, gt2);

    cudaStreamWaitEvent(0, g_aux.evWd, 0);
    hgemm_kernel<<<dim3(SEQ/128, HID/128), 256, HG_SMEM>>>(
        gt2, Wd2, nullptr, nullptr, nullptr, HID, HID, h2, out, HID, INTER);
}

// round 11
// speedup vs baseline: 4.2755x; 1.4063x over previous
#include <cuda_runtime.h>
#include <cuda_fp16.h>
#include <math.h>
#include <stdint.h>

#define SEQ   2048
#define HID   2048
#define HQ    16
#define HKV   4
#define DH    128
#define QBN   32
#define BSZ   64
#define GHD   128
#define INTER 5632
#define NQKV  3072
#define NGU   11264

#define SCALE_INV_SQRT_128 0.08838834764831845f

// ================= helpers =================
__device__ __forceinline__ uint32_t smem_u32(const void* p) {
    uint32_t a;
    asm("{ .reg .u64 t; cvta.to.shared.u64 t, %1; cvt.u32.u64 %0, t; }" : "=r"(a) : "l"(p));
    return a;
}
__device__ __forceinline__ void cp_async16(uint32_t saddr, const void* gptr) {
    asm volatile("cp.async.cg.shared.global [%0], [%1], 16;" :: "r"(saddr), "l"(gptr));
}
__device__ __forceinline__ void cp_commit() { asm volatile("cp.async.commit_group;"); }

#define LDSM_X4(r0, r1, r2, r3, addr) \
    asm volatile("ldmatrix.sync.aligned.m8n8.x4.shared.b16 {%0,%1,%2,%3}, [%4];" \
        : "=r"(r0), "=r"(r1), "=r"(r2), "=r"(r3) : "r"(addr))

#define MMAF16(c, a, b0r, b1r) \
    asm volatile("mma.sync.aligned.m16n8k16.row.col.f32.f16.f16.f32 " \
        "{%0,%1,%2,%3}, {%4,%5,%6,%7}, {%8,%9}, {%0,%1,%2,%3};" \
        : "+f"((c)[0]), "+f"((c)[1]), "+f"((c)[2]), "+f"((c)[3]) \
        : "r"((a)[0]), "r"((a)[1]), "r"((a)[2]), "r"((a)[3]), "r"(b0r), "r"(b1r))

#define MMATF32(c, a, b0r, b1r) \
    asm volatile("mma.sync.aligned.m16n8k8.row.col.f32.tf32.tf32.f32 " \
        "{%0,%1,%2,%3}, {%4,%5,%6,%7}, {%8,%9}, {%0,%1,%2,%3};" \
        : "+f"((c)[0]), "+f"((c)[1]), "+f"((c)[2]), "+f"((c)[3]) \
        : "r"((a)[0]), "r"((a)[1]), "r"((a)[2]), "r"((a)[3]), "r"(b0r), "r"(b1r))

static __device__ __forceinline__ uint32_t sw128(uint32_t o) { return o ^ ((o >> 3) & 0x70); }

__device__ __forceinline__ float tf32r(float v) {
    float r;
    asm("cvt.rna.tf32.f32 %0, %1;" : "=f"(r) : "f"(v));
    return r;
}

// ================= device scratch =================
__device__ float g_qkv [SEQ*NQKV];
__device__ float g_qp  [QBN*HQ*DH];
__device__ float g_kp  [QBN*HKV*DH];
__device__ float g_qg  [QBN*HQ*GHD];
__device__ float g_kg  [QBN*HKV*GHD];
__device__ unsigned char g_keep[HQ*QBN*QBN];
__device__ float g_h2  [SEQ*HID];
__device__ float g_gu  [SEQ*NGU];

// fp16 weights (single limb, K-major [N,K])
__device__ __half g_Wqkv2[NQKV*HID];
__device__ __half g_Wo2  [2048*2048];
__device__ __half g_Wgu2 [NGU*HID];
__device__ __half g_Wd2  [2048*INTER];
// activations: ha2 hi|lo (QKV GEMM is 2-seg); others single-limb
__device__ __half g_ha2  [SEQ*2*HID];
__device__ __half g_oa2  [SEQ*HID];
__device__ __half g_h3a2 [SEQ*HID];
__device__ __half g_gt2  [SEQ*INTER];

// ===== side-stream resources (created pre-main in static init) =====
struct AuxRes {
    cudaStream_t s2;
    cudaEvent_t root, evQKV, evWo, evGU, evWd, evPool, evGate;
    AuxRes() {
        cudaStreamCreateWithFlags(&s2, cudaStreamNonBlocking);
        cudaEventCreateWithFlags(&root,   cudaEventDisableTiming);
        cudaEventCreateWithFlags(&evQKV,  cudaEventDisableTiming);
        cudaEventCreateWithFlags(&evWo,   cudaEventDisableTiming);
        cudaEventCreateWithFlags(&evGU,   cudaEventDisableTiming);
        cudaEventCreateWithFlags(&evWd,   cudaEventDisableTiming);
        cudaEventCreateWithFlags(&evPool, cudaEventDisableTiming);
        cudaEventCreateWithFlags(&evGate, cudaEventDisableTiming);
    }
};
static AuxRes g_aux;

// ===== fused QKV weight conversion: fp32 [K,N]x3 -> fp16 [3072, K] =====
__global__ void wconv3_kernel(const float* __restrict__ Wq, const float* __restrict__ Wk,
                              const float* __restrict__ Wv, __half* __restrict__ y) {
    __shared__ float tile[32][33];
    int n0 = blockIdx.x * 32, k0 = blockIdx.y * 32;
    const float* W; int sN, c0;
    if (n0 < 2048)      { W = Wq; sN = 2048; c0 = n0; }
    else if (n0 < 2560) { W = Wk; sN = 512;  c0 = n0 - 2048; }
    else                { W = Wv; sN = 512;  c0 = n0 - 2560; }
    for (int i = threadIdx.y; i < 32; i += 8)
        tile[i][threadIdx.x] = W[(size_t)(k0 + i) * sN + c0 + threadIdx.x];
    __syncthreads();
    for (int i = threadIdx.y; i < 32; i += 8) {
        int n = n0 + i, k = k0 + threadIdx.x;
        y[(size_t)n * HID + k] = __float2half_rn(tile[threadIdx.x][i]);
    }
}

// ===== weight conversion: fp32 [K,N] -> fp16 [N,K] =====
__global__ void wconv_kernel(const float* __restrict__ W, __half* __restrict__ y,
                             int K, int N) {
    __shared__ float tile[32][33];
    int n0 = blockIdx.x * 32, k0 = blockIdx.y * 32;
    for (int i = threadIdx.y; i < 32; i += 8)
        tile[i][threadIdx.x] = W[(size_t)(k0 + i) * N + n0 + threadIdx.x];
    __syncthreads();
    for (int i = threadIdx.y; i < 32; i += 8) {
        int n = n0 + i, k = k0 + threadIdx.x;
        y[(size_t)n * K + k] = __float2half_rn(tile[threadIdx.x][i]);
    }
}

// ===== RMSNorm fused with fp16 conversion (segs = 1 or 2 limbs) =====
__global__ void rmsconv_kernel(const float* __restrict__ x, const float* __restrict__ w,
                               __half* __restrict__ y, int segs) {
    int row = blockIdx.x;
    const float* xr = x + (size_t)row * HID;
    float s = 0.f;
    for (int i = threadIdx.x; i < HID; i += 256) { float v = xr[i]; s += v * v; }
    __shared__ float red[256];
    red[threadIdx.x] = s; __syncthreads();
    for (int st = 128; st > 0; st >>= 1) {
        if (threadIdx.x < st) red[threadIdx.x] += red[threadIdx.x + st];
        __syncthreads();
    }
    float r = rsqrtf(red[0] / (float)HID + 1e-6f);
    size_t base = (size_t)row * segs * HID;
    for (int i = threadIdx.x; i < HID; i += 256) {
        float v = w[i] * xr[i] * r;
        __half h = __float2half_rn(v);
        y[base + i] = h;
        if (segs == 2)
            y[base + HID + i] = __float2half_rn(v - __half2float(h));
    }
}

// ====== fp16 HMMA GEMM, segs-limb A (C = (Ahi[+Alo]) x B^T) ======
// A[M,segs*K] fp16, B[N,K] fp16. CTA tile 128x128, 8 warps 2x4,
// warp tile 64x32, K-chunk 64, double-buffered cp.async, 2 CTA/SM.
#define HG_SMEM 65536

__global__ void __launch_bounds__(256, 2) hgemm_kernel(
    const __half* __restrict__ A, const __half* __restrict__ B,
    const float* __restrict__ b1, const float* __restrict__ b2, const float* __restrict__ b3,
    int n1, int n2,
    const float* __restrict__ res,
    float* __restrict__ C, int N, int K, int segs)
{
    extern __shared__ char smraw[];
    const uint32_t smu = smem_u32(smraw);
    const int tid = threadIdx.x;
    const int lane = tid & 31, wid = tid >> 5;
    const int wm = wid >> 2, wn = wid & 3;
    const size_t ldaA = (size_t)segs * K;
    const size_t ldaB = (size_t)K;
    const int kpseg = K >> 6;
    const int nch = segs * kpseg;
    const size_t arow0 = (size_t)blockIdx.x * 128;
    const size_t brow0 = (size_t)blockIdx.y * 128;

    const uint32_t xm = (uint32_t)((lane & 7) << 4);
    uint32_t kbx[4];
#pragma unroll
    for (int ks = 0; ks < 4; ks++)
        kbx[ks] = ((uint32_t)(ks * 32 + ((lane >> 4) << 4))) ^ xm;
    uint32_t rowA[4], rowB[2];
#pragma unroll
    for (int mt = 0; mt < 4; mt++)
        rowA[mt] = (uint32_t)((wm << 6) + (lane & 15) + (mt << 4)) * 128u;
#pragma unroll
    for (int nt2 = 0; nt2 < 2; nt2++)
        rowB[nt2] = (uint32_t)((wn << 5) + (lane & 15) + (nt2 << 4)) * 128u;

    float acc[4][4][4];
#pragma unroll
    for (int i = 0; i < 4; i++)
#pragma unroll
        for (int j = 0; j < 4; j++)
#pragma unroll
            for (int t = 0; t < 4; t++) acc[i][j][t] = 0.f;

    auto issue = [&](int ch, int b) {
        int seg = ch / kpseg;
        int kk = (ch - seg * kpseg) << 6;
        const __half* Ab = A + (size_t)seg * K + kk;
        const __half* Bb = B + kk;
        uint32_t abase = smu + b * 32768;
        uint32_t bbase = abase + 16384;
#pragma unroll
        for (int i = 0; i < 4; i++) {
            int u = i * 256 + tid;
            int r = u >> 3, c = u & 7;
            uint32_t so = sw128((uint32_t)(r * 128 + c * 16));
            cp_async16(abase + so, Ab + (arow0 + r) * ldaA + c * 8);
            cp_async16(bbase + so, Bb + (brow0 + r) * ldaB + c * 8);
        }
        cp_commit();
    };

    issue(0, 0);

    for (int ch = 0; ch < nch; ch++) {
        const int b = ch & 1;
        if (ch + 1 < nch) {
            issue(ch + 1, b ^ 1);
            asm volatile("cp.async.wait_group 1;");
        } else {
            asm volatile("cp.async.wait_group 0;");
        }
        __syncthreads();

        const uint32_t abuf = smu + b * 32768;
        const uint32_t bbuf = abuf + 16384;

#pragma unroll
        for (int ks = 0; ks < 4; ks++) {
            uint32_t a[4][4];
#pragma unroll
            for (int mt = 0; mt < 4; mt++)
                LDSM_X4(a[mt][0], a[mt][1], a[mt][2], a[mt][3],
                        abuf + rowA[mt] + kbx[ks]);
            uint32_t bf[4][2];
#pragma unroll
            for (int nt2 = 0; nt2 < 2; nt2++) {
                uint32_t t0, t1, t2, t3;
                LDSM_X4(t0, t1, t2, t3, bbuf + rowB[nt2] + kbx[ks]);
                bf[nt2 * 2 + 0][0] = t0; bf[nt2 * 2 + 0][1] = t2;
                bf[nt2 * 2 + 1][0] = t1; bf[nt2 * 2 + 1][1] = t3;
            }
#pragma unroll
            for (int mt = 0; mt < 4; mt++)
#pragma unroll
                for (int nt = 0; nt < 4; nt++)
                    MMAF16(acc[mt][nt], a[mt], bf[nt][0], bf[nt][1]);
        }
        __syncthreads();
    }

    const int rbase = (int)arow0 + (wm << 6) + (lane >> 2);
    const int cbase = (int)brow0 + (wn << 5) + ((lane & 3) << 1);
#pragma unroll
    for (int nt = 0; nt < 4; nt++) {
        const int col = cbase + (nt << 3);
        float bv0 = 0.f, bv1 = 0.f;
        if (b1) {
            if (col < n1)       { bv0 = b1[col];      bv1 = b1[col + 1]; }
            else if (col < n2)  { bv0 = b2[col - n1]; bv1 = b2[col - n1 + 1]; }
            else                { bv0 = b3[col - n2]; bv1 = b3[col - n2 + 1]; }
        }
#pragma unroll
        for (int mt = 0; mt < 4; mt++) {
            const int row = rbase + (mt << 4);
            size_t gi = (size_t)row * N + col;
            float v0 = acc[mt][nt][0] + bv0, v1 = acc[mt][nt][1] + bv1;
            if (res) { v0 += res[gi]; v1 += res[gi + 1]; }
            *(float2*)(C + gi) = make_float2(v0, v1);
            size_t gi2 = gi + (size_t)8 * N;
            float v2 = acc[mt][nt][2] + bv0, v3 = acc[mt][nt][3] + bv1;
            if (res) { v2 += res[gi2]; v3 += res[gi2 + 1]; }
            *(float2*)(C + gi2) = make_float2(v2, v3);
        }
    }
}

// ================= small fp32 SGEMM (gate path only) =================
__global__ void __launch_bounds__(256) sgemm_kernel(
    const float* __restrict__ A, const float* __restrict__ B,
    float* __restrict__ C, int M, int N, int K)
{
    __shared__ float As[8][128];
    __shared__ float Bs[8][128];
    const int tid = threadIdx.x;
    const int bx = blockIdx.x * 128;
    const int by = blockIdx.y * 128;
    const int tx = tid & 15;
    const int ty = tid >> 4;
    const int arow = tid >> 1;
    const int acol = (tid & 1) << 2;
    const int brow = tid >> 5;
    const int bcol = (tid & 31) << 2;

    const float* Ap = A + (size_t)(by + arow) * K + acol;
    const float* Bp = B + (size_t)brow * N + bx + bcol;

    float acc[8][8];
#pragma unroll
    for (int i = 0; i < 8; i++)
#pragma unroll
        for (int j = 0; j < 8; j++) acc[i][j] = 0.f;

    for (int k0 = 0; k0 < K; k0 += 8) {
        float4 av = *(const float4*)Ap;
        As[acol + 0][arow] = av.x;
        As[acol + 1][arow] = av.y;
        As[acol + 2][arow] = av.z;
        As[acol + 3][arow] = av.w;
        *(float4*)&Bs[brow][bcol] = *(const float4*)Bp;
        __syncthreads();
#pragma unroll
        for (int kk = 0; kk < 8; kk++) {
            float a[8], bb[8];
            *(float4*)&a[0] = *(const float4*)&As[kk][ty * 8];
            *(float4*)&a[4] = *(const float4*)&As[kk][ty * 8 + 4];
            *(float4*)&bb[0] = *(const float4*)&Bs[kk][tx * 8];
            *(float4*)&bb[4] = *(const float4*)&Bs[kk][tx * 8 + 4];
#pragma unroll
            for (int i = 0; i < 8; i++)
#pragma unroll
                for (int j = 0; j < 8; j++)
                    acc[i][j] += a[i] * bb[j];
        }
        __syncthreads();
        Ap += 8;
        Bp += (size_t)8 * N;
    }

    const int row0 = by + ty * 8;
    const int col0 = bx + tx * 8;
#pragma unroll
    for (int i = 0; i < 8; i++)
#pragma unroll
        for (int j = 0; j < 8; j++)
            C[(size_t)(row0 + i) * N + col0 + j] = acc[i][j];
}

// ================= pooling / gate / rope =================
__global__ void pool_kernel(const float* __restrict__ x, int stride,
                            float* __restrict__ out, int H) {
    int qb = blockIdx.x, h = blockIdx.y, d = threadIdx.x;
    float s = 0.f;
    for (int i = 0; i < BSZ; i++)
        s += x[(size_t)(qb * BSZ + i) * stride + h * DH + d];
    out[((size_t)qb * H + h) * DH + d] = s * (1.f / (float)BSZ);
}

__global__ void gate_kernel(const float* __restrict__ qg, const float* __restrict__ kg,
                            unsigned char* __restrict__ keep) {
    int h = blockIdx.x, qb = blockIdx.y, kb = threadIdx.x;
    const float* qv = qg + ((size_t)qb * HQ + h) * GHD;
    const float* kv = kg + ((size_t)kb * HKV + (h >> 2)) * GHD;
    float s = 0.f;
    for (int d = 0; d < GHD; d++) s += qv[d] * kv[d];
    s *= SCALE_INV_SQRT_128;
    if (kb > qb) s = -1e30f;
    float m = s;
    for (int off = 16; off > 0; off >>= 1)
        m = fmaxf(m, __shfl_xor_sync(0xffffffffu, m, off));
    float e = expf(s - m);
    float sum = e;
    for (int off = 16; off > 0; off >>= 1)
        sum += __shfl_xor_sync(0xffffffffu, sum, off);
    float gate = e / sum;
    bool kp = (kb <= qb) && ((gate >= 0.004f) || (kb == qb));
    keep[((size_t)h * QBN + qb) * QBN + kb] = kp ? 1 : 0;
}

__global__ void rope_kernel(float* __restrict__ x, int stride,
                            const float* __restrict__ cs, const float* __restrict__ sn, int H) {
    int idx = blockIdx.x * blockDim.x + threadIdx.x;
    int d = idx & 63;
    int h = (idx >> 6) % H;
    int s = idx / (64 * H);
    float* p = x + (size_t)s * stride + h * DH;
    float x1 = p[d], x2 = p[d + 64];
    float c1 = cs[(size_t)s * DH + d],      s1 = sn[(size_t)s * DH + d];
    float c2 = cs[(size_t)s * DH + d + 64], s2 = sn[(size_t)s * DH + d + 64];
    p[d]      = x1 * c1 - x2 * s1;
    p[d + 64] = x2 * c2 + x1 * s2;
}

// ================= tf32 tensor-core block-sparse flash attention =================
#define ATP 132
#define APP 68
#define AQ_OFF   0
#define AK_OFF   (64*ATP)
#define AV_OFF   (2*64*ATP)
#define AP_OFF   (3*64*ATP)
#define ARM_OFF  (AP_OFF + 64*APP)
#define ARL_OFF  (ARM_OFF + 128)
#define AROWM    (ARL_OFF + 128)
#define AROWL    (AROWM + 64)
#define AALF     (AROWL + 64)
#define ATTN_SM_FLOATS (AALF + 64)

__global__ void __launch_bounds__(256, 1) attn_kernel(
    const float* __restrict__ qkv,
    const unsigned char* __restrict__ keep, __half* __restrict__ oa2)
{
    extern __shared__ float sm[];
    const uint32_t* smu = (const uint32_t*)sm;

    const int qb = QBN - 1 - blockIdx.x;
    const int h = blockIdx.y;
    const int hk = h >> 2;
    const int tid = threadIdx.x;
    const int lane = tid & 31, wid = tid >> 5;
    const int rw = wid & 3, cw = wid >> 2;
    const int g = lane >> 2, qd = lane & 3;
    const int r0 = rw * 16 + g;
    const int r1 = r0 + 8;

    for (int i = tid; i < 64 * 32; i += 256) {
        int t = i >> 5, d4 = (i & 31) << 2;
        float4 qv = *(const float4*)&qkv[(size_t)(qb * 64 + t) * NQKV + h * DH + d4];
        float* dst = sm + AQ_OFF + t * ATP + d4;
        dst[0] = tf32r(qv.x * SCALE_INV_SQRT_128);
        dst[1] = tf32r(qv.y * SCALE_INV_SQRT_128);
        dst[2] = tf32r(qv.z * SCALE_INV_SQRT_128);
        dst[3] = tf32r(qv.w * SCALE_INV_SQRT_128);
    }
    if (tid < 64) { sm[AROWM + tid] = -1e30f; sm[AROWL + tid] = 0.f; }

    float oacc[8][4];
#pragma unroll
    for (int i = 0; i < 8; i++)
#pragma unroll
        for (int j = 0; j < 4; j++) oacc[i][j] = 0.f;

    const unsigned char* krow = keep + ((size_t)h * QBN + qb) * QBN;

    for (int kb = 0; kb <= qb; kb++) {
        if (!krow[kb]) continue;
        __syncthreads();

        for (int i = tid; i < 64 * 32; i += 256) {
            int t = i >> 5, d4 = (i & 31) << 2;
            size_t gi = (size_t)(kb * 64 + t) * NQKV + hk * DH + d4;
            float4 kvv = *(const float4*)&qkv[gi + 2048];
            float* kd = sm + AK_OFF + t * ATP + d4;
            kd[0] = tf32r(kvv.x); kd[1] = tf32r(kvv.y); kd[2] = tf32r(kvv.z); kd[3] = tf32r(kvv.w);
            float4 vvv = *(const float4*)&qkv[gi + 2560];
            float* vd = sm + AV_OFF + t * ATP + d4;
            vd[0] = tf32r(vvv.x); vd[1] = tf32r(vvv.y); vd[2] = tf32r(vvv.z); vd[3] = tf32r(vvv.w);
        }
        __syncthreads();

        float sacc[4][4];
#pragma unroll
        for (int i = 0; i < 4; i++)
#pragma unroll
            for (int j = 0; j < 4; j++) sacc[i][j] = 0.f;

#pragma unroll
        for (int ks = 0; ks < 16; ks++) {
            const int k0 = ks * 8;
            uint32_t a[4];
            a[0] = smu[AQ_OFF + r0 * ATP + k0 + qd];
            a[1] = smu[AQ_OFF + r1 * ATP + k0 + qd];
            a[2] = smu[AQ_OFF + r0 * ATP + k0 + qd + 4];
            a[3] = smu[AQ_OFF + r1 * ATP + k0 + qd + 4];
#pragma unroll
            for (int nt = 0; nt < 4; nt++) {
                const int n = cw * 32 + nt * 8 + g;
                uint32_t b0 = smu[AK_OFF + n * ATP + k0 + qd];
                uint32_t b1 = smu[AK_OFF + n * ATP + k0 + qd + 4];
                MMATF32(sacc[nt], a, b0, b1);
            }
        }

        if (kb == qb) {
#pragma unroll
            for (int nt = 0; nt < 4; nt++) {
                const int c0 = cw * 32 + nt * 8 + qd * 2;
                if (c0 > r0)     sacc[nt][0] = -1e30f;
                if (c0 + 1 > r0) sacc[nt][1] = -1e30f;
                if (c0 > r1)     sacc[nt][2] = -1e30f;
                if (c0 + 1 > r1) sacc[nt][3] = -1e30f;
            }
        }

        float m0 = -1e30f, m1 = -1e30f;
#pragma unroll
        for (int nt = 0; nt < 4; nt++) {
            m0 = fmaxf(m0, fmaxf(sacc[nt][0], sacc[nt][1]));
            m1 = fmaxf(m1, fmaxf(sacc[nt][2], sacc[nt][3]));
        }
        m0 = fmaxf(m0, __shfl_xor_sync(0xffffffffu, m0, 1));
        m0 = fmaxf(m0, __shfl_xor_sync(0xffffffffu, m0, 2));
        m1 = fmaxf(m1, __shfl_xor_sync(0xffffffffu, m1, 1));
        m1 = fmaxf(m1, __shfl_xor_sync(0xffffffffu, m1, 2));
        if (qd == 0) {
            sm[ARM_OFF + cw * 64 + r0] = m0;
            sm[ARM_OFF + cw * 64 + r1] = m1;
        }
        __syncthreads();

        if (tid < 64) {
            float newm = fmaxf(sm[AROWM + tid],
                               fmaxf(sm[ARM_OFF + tid], sm[ARM_OFF + 64 + tid]));
            sm[AALF + tid] = __expf(sm[AROWM + tid] - newm);
            sm[AROWM + tid] = newm;
        }
        __syncthreads();

        const float nm0 = sm[AROWM + r0];
        const float nm1 = sm[AROWM + r1];
        float l0 = 0.f, l1 = 0.f;
#pragma unroll
        for (int nt = 0; nt < 4; nt++) {
            const int c0 = cw * 32 + nt * 8 + qd * 2;
            float p0 = __expf(sacc[nt][0] - nm0);
            float p1 = __expf(sacc[nt][1] - nm0);
            float p2 = __expf(sacc[nt][2] - nm1);
            float p3 = __expf(sacc[nt][3] - nm1);
            l0 += p0 + p1; l1 += p2 + p3;
            sm[AP_OFF + r0 * APP + c0]     = tf32r(p0);
            sm[AP_OFF + r0 * APP + c0 + 1] = tf32r(p1);
            sm[AP_OFF + r1 * APP + c0]     = tf32r(p2);
            sm[AP_OFF + r1 * APP + c0 + 1] = tf32r(p3);
        }
        l0 += __shfl_xor_sync(0xffffffffu, l0, 1);
        l0 += __shfl_xor_sync(0xffffffffu, l0, 2);
        l1 += __shfl_xor_sync(0xffffffffu, l1, 1);
        l1 += __shfl_xor_sync(0xffffffffu, l1, 2);
        if (qd == 0) {
            sm[ARL_OFF + cw * 64 + r0] = l0;
            sm[ARL_OFF + cw * 64 + r1] = l1;
        }
        const float al0 = sm[AALF + r0];
        const float al1 = sm[AALF + r1];
#pragma unroll
        for (int nt = 0; nt < 8; nt++) {
            oacc[nt][0] *= al0; oacc[nt][1] *= al0;
            oacc[nt][2] *= al1; oacc[nt][3] *= al1;
        }
        __syncthreads();

        if (tid < 64)
            sm[AROWL + tid] = sm[AROWL + tid] * sm[AALF + tid]
                            + sm[ARL_OFF + tid] + sm[ARL_OFF + 64 + tid];

#pragma unroll
        for (int ks = 0; ks < 8; ks++) {
            const int k0 = ks * 8;
            uint32_t a[4];
            a[0] = smu[AP_OFF + r0 * APP + k0 + qd];
            a[1] = smu[AP_OFF + r1 * APP + k0 + qd];
            a[2] = smu[AP_OFF + r0 * APP + k0 + qd + 4];
            a[3] = smu[AP_OFF + r1 * APP + k0 + qd + 4];
#pragma unroll
            for (int nt = 0; nt < 8; nt++) {
                const int n = cw * 64 + nt * 8 + g;
                uint32_t b0 = smu[AV_OFF + (k0 + qd) * ATP + n];
                uint32_t b1 = smu[AV_OFF + (k0 + qd + 4) * ATP + n];
                MMATF32(oacc[nt], a, b0, b1);
            }
        }
    }

    __syncthreads();
    const float inv0 = 1.f / sm[AROWL + r0];
    const float inv1 = 1.f / sm[AROWL + r1];
    const size_t grow0 = (size_t)(qb * 64 + r0);
    const size_t grow1 = (size_t)(qb * 64 + r1);
#pragma unroll
    for (int nt = 0; nt < 8; nt++) {
        const int col = h * DH + cw * 64 + nt * 8 + qd * 2;
        __half2 v0 = __floats2half2_rn(oacc[nt][0] * inv0, oacc[nt][1] * inv0);
        *(__half2*)(oa2 + grow0 * HID + col) = v0;
        __half2 v1 = __floats2half2_rn(oacc[nt][2] * inv1, oacc[nt][3] * inv1);
        *(__half2*)(oa2 + grow1 * HID + col) = v1;
    }
}

// ================= SiLU(gate)*up fused with fp16 conversion ============
__global__ void siluconv_kernel(const float* __restrict__ gu, __half* __restrict__ y) {
    int s = blockIdx.y;
    int j = blockIdx.x * 256 + threadIdx.x;
    size_t row = (size_t)s * NGU;
    float x = gu[row + j];
    float u = gu[row + INTER + j];
    float v = (x / (1.f + __expf(-x))) * u;
    y[(size_t)s * INTER + j] = __float2half_rn(v);
}

// ================= launch =================
extern "C" void kernel_launch(void* const* d_in, const int* in_sizes, int n_in,
                              void* d_out, int out_size) {
    const float* hidden = (const float*)d_in[0];
    const float* cosp   = (const float*)d_in[1];
    const float* sinp   = (const float*)d_in[2];
    const float* ln1    = (const float*)d_in[3];
    const float* ln2    = (const float*)d_in[4];
    const float* Wq     = (const float*)d_in[5];
    const float* bq     = (const float*)d_in[6];
    const float* Wk     = (const float*)d_in[7];
    const float* bk     = (const float*)d_in[8];
    const float* Wv     = (const float*)d_in[9];
    const float* bv     = (const float*)d_in[10];
    const float* Wo     = (const float*)d_in[11];
    const float* gWq    = (const float*)d_in[12];
    const float* gWk    = (const float*)d_in[13];
    const float* Wgate  = (const float*)d_in[14];
    const float* Wup    = (const float*)d_in[15];
    const float* Wdown  = (const float*)d_in[16];
    float* out = (float*)d_out;

    float *qkv, *qp, *kp, *qg, *kg, *h2, *gu;
    unsigned char* keep;
    __half *Wqkv2, *Wo2, *Wgu2, *Wd2, *ha2, *oa2, *h3a2, *gt2;
    cudaGetSymbolAddress((void**)&qkv,  g_qkv);
    cudaGetSymbolAddress((void**)&qp,   g_qp);
    cudaGetSymbolAddress((void**)&kp,   g_kp);
    cudaGetSymbolAddress((void**)&qg,   g_qg);
    cudaGetSymbolAddress((void**)&kg,   g_kg);
    cudaGetSymbolAddress((void**)&keep, g_keep);
    cudaGetSymbolAddress((void**)&h2,   g_h2);
    cudaGetSymbolAddress((void**)&gu,   g_gu);
    cudaGetSymbolAddress((void**)&Wqkv2, g_Wqkv2);
    cudaGetSymbolAddress((void**)&Wo2,  g_Wo2);
    cudaGetSymbolAddress((void**)&Wgu2, g_Wgu2);
    cudaGetSymbolAddress((void**)&Wd2,  g_Wd2);
    cudaGetSymbolAddress((void**)&ha2,  g_ha2);
    cudaGetSymbolAddress((void**)&oa2,  g_oa2);
    cudaGetSymbolAddress((void**)&h3a2, g_h3a2);
    cudaGetSymbolAddress((void**)&gt2,  g_gt2);

    cudaFuncSetAttribute(hgemm_kernel, cudaFuncAttributeMaxDynamicSharedMemorySize, HG_SMEM);
    cudaFuncSetAttribute(attn_kernel, cudaFuncAttributeMaxDynamicSharedMemorySize,
                         ATTN_SM_FLOATS * (int)sizeof(float));

    dim3 w8(32, 8);
    cudaStream_t s2 = g_aux.s2;

    // ---- fork side stream: weight conversions + gate path off critical path ----
    cudaEventRecord(g_aux.root, 0);
    cudaStreamWaitEvent(s2, g_aux.root, 0);
    wconv3_kernel<<<dim3(NQKV/32, HID/32), w8, 0, s2>>>(Wq, Wk, Wv, Wqkv2);
    cudaEventRecord(g_aux.evQKV, s2);
    wconv_kernel<<<dim3(HID/32, HID/32), w8, 0, s2>>>(Wo, Wo2, HID, HID);
    cudaEventRecord(g_aux.evWo, s2);
    wconv_kernel<<<dim3(INTER/32, HID/32), w8, 0, s2>>>(Wgate, Wgu2, HID, INTER);
    wconv_kernel<<<dim3(INTER/32, HID/32), w8, 0, s2>>>(Wup, Wgu2 + (size_t)INTER*HID, HID, INTER);
    cudaEventRecord(g_aux.evGU, s2);
    wconv_kernel<<<dim3(HID/32, INTER/32), w8, 0, s2>>>(Wdown, Wd2, INTER, HID);
    cudaEventRecord(g_aux.evWd, s2);

    // ---- main chain ----
    rmsconv_kernel<<<SEQ, 256>>>(hidden, ln1, ha2, 2);
    cudaStreamWaitEvent(0, g_aux.evQKV, 0);
    hgemm_kernel<<<dim3(SEQ/128, NQKV/128), 256, HG_SMEM>>>(
        ha2, Wqkv2, bq, bk, bv, 2048, 2560, nullptr, qkv, NQKV, HID, 2);

    // pools on main (pre-RoPE values), then gate path on s2 overlapping RoPE
    pool_kernel<<<dim3(QBN, HQ), DH>>>(qkv, NQKV, qp, HQ);
    pool_kernel<<<dim3(QBN, HKV), DH>>>(qkv + 2048, NQKV, kp, HKV);
    cudaEventRecord(g_aux.evPool, 0);
    cudaStreamWaitEvent(s2, g_aux.evPool, 0);
    sgemm_kernel<<<dim3(GHD/128, (QBN*HQ)/128), 256, 0, s2>>>(qp, gWq, qg, QBN*HQ, GHD, DH);
    sgemm_kernel<<<dim3(GHD/128, (QBN*HKV)/128), 256, 0, s2>>>(kp, gWk, kg, QBN*HKV, GHD, DH);
    gate_kernel<<<dim3(HQ, QBN), 32, 0, s2>>>(qg, kg, keep);
    cudaEventRecord(g_aux.evGate, s2);

    rope_kernel<<<(SEQ*HQ*64)/256, 256>>>(qkv, NQKV, cosp, sinp, HQ);
    rope_kernel<<<(SEQ*HKV*64)/256, 256>>>(qkv + 2048, NQKV, cosp, sinp, HKV);

    cudaStreamWaitEvent(0, g_aux.evGate, 0);
    attn_kernel<<<dim3(QBN, HQ), 256, ATTN_SM_FLOATS * (int)sizeof(float)>>>(qkv, keep, oa2);

    cudaStreamWaitEvent(0, g_aux.evWo, 0);
    hgemm_kernel<<<dim3(SEQ/128, HID/128), 256, HG_SMEM>>>(
        oa2, Wo2, nullptr, nullptr, nullptr, HID, HID, hidden, h2, HID, HQ*DH, 1);

    rmsconv_kernel<<<SEQ, 256>>>(h2, ln2, h3a2, 1);

    cudaStreamWaitEvent(0, g_aux.evGU, 0);
    hgemm_kernel<<<dim3(SEQ/128, NGU/128), 256, HG_SMEM>>>(
        h3a2, Wgu2, nullptr, nullptr, nullptr, NGU, NGU, nullptr, gu, NGU, HID, 1);

    siluconv_kernel<<<dim3(INTER/256, SEQ), 256>>>(gu, gt2);

    cudaStreamWaitEvent(0, g_aux.evWd, 0);
    hgemm_kernel<<<dim3(SEQ/128, HID/128), 256, HG_SMEM>>>(
        gt2, Wd2, nullptr, nullptr, nullptr, HID, HID, h2, out, HID, INTER, 1);
}

// round 12
// speedup vs baseline: 4.7470x; 1.1103x over previous
#include <cuda_runtime.h>
#include <cuda_fp16.h>
#include <math.h>
#include <stdint.h>

#define SEQ   2048
#define HID   2048
#define HQ    16
#define HKV   4
#define DH    128
#define QBN   32
#define BSZ   64
#define GHD   128
#define INTER 5632
#define NQKV  3072
#define NGU   11264

#define SCALE_INV_SQRT_128 0.08838834764831845f

// ================= helpers =================
__device__ __forceinline__ uint32_t smem_u32(const void* p) {
    uint32_t a;
    asm("{ .reg .u64 t; cvta.to.shared.u64 t, %1; cvt.u32.u64 %0, t; }" : "=r"(a) : "l"(p));
    return a;
}
__device__ __forceinline__ void cp_async16(uint32_t saddr, const void* gptr) {
    asm volatile("cp.async.cg.shared.global [%0], [%1], 16;" :: "r"(saddr), "l"(gptr));
}
__device__ __forceinline__ void cp_commit() { asm volatile("cp.async.commit_group;"); }

#define LDSM_X4(r0, r1, r2, r3, addr) \
    asm volatile("ldmatrix.sync.aligned.m8n8.x4.shared.b16 {%0,%1,%2,%3}, [%4];" \
        : "=r"(r0), "=r"(r1), "=r"(r2), "=r"(r3) : "r"(addr))

#define MMAF16(c, a, b0r, b1r) \
    asm volatile("mma.sync.aligned.m16n8k16.row.col.f32.f16.f16.f32 " \
        "{%0,%1,%2,%3}, {%4,%5,%6,%7}, {%8,%9}, {%0,%1,%2,%3};" \
        : "+f"((c)[0]), "+f"((c)[1]), "+f"((c)[2]), "+f"((c)[3]) \
        : "r"((a)[0]), "r"((a)[1]), "r"((a)[2]), "r"((a)[3]), "r"(b0r), "r"(b1r))

static __device__ __forceinline__ uint32_t sw128(uint32_t o) { return o ^ ((o >> 3) & 0x70); }

// ================= device scratch =================
__device__ float g_qkv [SEQ*NQKV];
__device__ float g_qp  [QBN*HQ*DH];
__device__ float g_kp  [QBN*HKV*DH];
__device__ float g_qg  [QBN*HQ*GHD];
__device__ float g_kg  [QBN*HKV*GHD];
__device__ unsigned char g_keep[HQ*QBN*QBN];
__device__ float g_h2  [SEQ*HID];
__device__ float g_gu  [SEQ*NGU];

__device__ __half g_Wqkv2[NQKV*HID];
__device__ __half g_Wo2  [2048*2048];
__device__ __half g_Wgu2 [NGU*HID];
__device__ __half g_Wd2  [2048*INTER];
__device__ __half g_ha2  [SEQ*2*HID];
__device__ __half g_oa2  [SEQ*HID];
__device__ __half g_h3a2 [SEQ*HID];
__device__ __half g_gt2  [SEQ*INTER];
// fp16 attention operands (RoPE applied; V transposed)
__device__ __half g_qf16 [SEQ*HQ*DH];
__device__ __half g_kf16 [SEQ*HKV*DH];
__device__ __half g_vt16 [HKV*DH*SEQ];

// ===== side-stream resources (created pre-main in static init) =====
struct AuxRes {
    cudaStream_t s2;
    cudaEvent_t root, evQKV, evWo, evGU, evWd, evPool, evGate;
    AuxRes() {
        cudaStreamCreateWithFlags(&s2, cudaStreamNonBlocking);
        cudaEventCreateWithFlags(&root,   cudaEventDisableTiming);
        cudaEventCreateWithFlags(&evQKV,  cudaEventDisableTiming);
        cudaEventCreateWithFlags(&evWo,   cudaEventDisableTiming);
        cudaEventCreateWithFlags(&evGU,   cudaEventDisableTiming);
        cudaEventCreateWithFlags(&evWd,   cudaEventDisableTiming);
        cudaEventCreateWithFlags(&evPool, cudaEventDisableTiming);
        cudaEventCreateWithFlags(&evGate, cudaEventDisableTiming);
    }
};
static AuxRes g_aux;

// ===== fused QKV weight conversion: fp32 [K,N]x3 -> fp16 [3072, K] =====
__global__ void wconv3_kernel(const float* __restrict__ Wq, const float* __restrict__ Wk,
                              const float* __restrict__ Wv, __half* __restrict__ y) {
    __shared__ float tile[32][33];
    int n0 = blockIdx.x * 32, k0 = blockIdx.y * 32;
    const float* W; int sN, c0;
    if (n0 < 2048)      { W = Wq; sN = 2048; c0 = n0; }
    else if (n0 < 2560) { W = Wk; sN = 512;  c0 = n0 - 2048; }
    else                { W = Wv; sN = 512;  c0 = n0 - 2560; }
    for (int i = threadIdx.y; i < 32; i += 8)
        tile[i][threadIdx.x] = W[(size_t)(k0 + i) * sN + c0 + threadIdx.x];
    __syncthreads();
    for (int i = threadIdx.y; i < 32; i += 8) {
        int n = n0 + i, k = k0 + threadIdx.x;
        y[(size_t)n * HID + k] = __float2half_rn(tile[threadIdx.x][i]);
    }
}

// ===== weight conversion: fp32 [K,N] -> fp16 [N,K] =====
__global__ void wconv_kernel(const float* __restrict__ W, __half* __restrict__ y,
                             int K, int N) {
    __shared__ float tile[32][33];
    int n0 = blockIdx.x * 32, k0 = blockIdx.y * 32;
    for (int i = threadIdx.y; i < 32; i += 8)
        tile[i][threadIdx.x] = W[(size_t)(k0 + i) * N + n0 + threadIdx.x];
    __syncthreads();
    for (int i = threadIdx.y; i < 32; i += 8) {
        int n = n0 + i, k = k0 + threadIdx.x;
        y[(size_t)n * K + k] = __float2half_rn(tile[threadIdx.x][i]);
    }
}

// ===== RMSNorm fused with fp16 conversion (segs = 1 or 2 limbs) =====
__global__ void rmsconv_kernel(const float* __restrict__ x, const float* __restrict__ w,
                               __half* __restrict__ y, int segs) {
    int row = blockIdx.x;
    const float* xr = x + (size_t)row * HID;
    float s = 0.f;
    for (int i = threadIdx.x; i < HID; i += 256) { float v = xr[i]; s += v * v; }
    __shared__ float red[256];
    red[threadIdx.x] = s; __syncthreads();
    for (int st = 128; st > 0; st >>= 1) {
        if (threadIdx.x < st) red[threadIdx.x] += red[threadIdx.x + st];
        __syncthreads();
    }
    float r = rsqrtf(red[0] / (float)HID + 1e-6f);
    size_t base = (size_t)row * segs * HID;
    for (int i = threadIdx.x; i < HID; i += 256) {
        float v = w[i] * xr[i] * r;
        __half h = __float2half_rn(v);
        y[base + i] = h;
        if (segs == 2)
            y[base + HID + i] = __float2half_rn(v - __half2float(h));
    }
}

// ====== fp16 HMMA GEMM, segs-limb A ======
#define HG_SMEM 65536

__global__ void __launch_bounds__(256, 2) hgemm_kernel(
    const __half* __restrict__ A, const __half* __restrict__ B,
    const float* __restrict__ b1, const float* __restrict__ b2, const float* __restrict__ b3,
    int n1, int n2,
    const float* __restrict__ res,
    float* __restrict__ C, int N, int K, int segs)
{
    extern __shared__ char smraw[];
    const uint32_t smu = smem_u32(smraw);
    const int tid = threadIdx.x;
    const int lane = tid & 31, wid = tid >> 5;
    const int wm = wid >> 2, wn = wid & 3;
    const size_t ldaA = (size_t)segs * K;
    const size_t ldaB = (size_t)K;
    const int kpseg = K >> 6;
    const int nch = segs * kpseg;
    const size_t arow0 = (size_t)blockIdx.x * 128;
    const size_t brow0 = (size_t)blockIdx.y * 128;

    const uint32_t xm = (uint32_t)((lane & 7) << 4);
    uint32_t kbx[4];
#pragma unroll
    for (int ks = 0; ks < 4; ks++)
        kbx[ks] = ((uint32_t)(ks * 32 + ((lane >> 4) << 4))) ^ xm;
    uint32_t rowA[4], rowB[2];
#pragma unroll
    for (int mt = 0; mt < 4; mt++)
        rowA[mt] = (uint32_t)((wm << 6) + (lane & 15) + (mt << 4)) * 128u;
#pragma unroll
    for (int nt2 = 0; nt2 < 2; nt2++)
        rowB[nt2] = (uint32_t)((wn << 5) + (lane & 15) + (nt2 << 4)) * 128u;

    float acc[4][4][4];
#pragma unroll
    for (int i = 0; i < 4; i++)
#pragma unroll
        for (int j = 0; j < 4; j++)
#pragma unroll
            for (int t = 0; t < 4; t++) acc[i][j][t] = 0.f;

    auto issue = [&](int ch, int b) {
        int seg = ch / kpseg;
        int kk = (ch - seg * kpseg) << 6;
        const __half* Ab = A + (size_t)seg * K + kk;
        const __half* Bb = B + kk;
        uint32_t abase = smu + b * 32768;
        uint32_t bbase = abase + 16384;
#pragma unroll
        for (int i = 0; i < 4; i++) {
            int u = i * 256 + tid;
            int r = u >> 3, c = u & 7;
            uint32_t so = sw128((uint32_t)(r * 128 + c * 16));
            cp_async16(abase + so, Ab + (arow0 + r) * ldaA + c * 8);
            cp_async16(bbase + so, Bb + (brow0 + r) * ldaB + c * 8);
        }
        cp_commit();
    };

    issue(0, 0);

    for (int ch = 0; ch < nch; ch++) {
        const int b = ch & 1;
        if (ch + 1 < nch) {
            issue(ch + 1, b ^ 1);
            asm volatile("cp.async.wait_group 1;");
        } else {
            asm volatile("cp.async.wait_group 0;");
        }
        __syncthreads();

        const uint32_t abuf = smu + b * 32768;
        const uint32_t bbuf = abuf + 16384;

#pragma unroll
        for (int ks = 0; ks < 4; ks++) {
            uint32_t a[4][4];
#pragma unroll
            for (int mt = 0; mt < 4; mt++)
                LDSM_X4(a[mt][0], a[mt][1], a[mt][2], a[mt][3],
                        abuf + rowA[mt] + kbx[ks]);
            uint32_t bf[4][2];
#pragma unroll
            for (int nt2 = 0; nt2 < 2; nt2++) {
                uint32_t t0, t1, t2, t3;
                LDSM_X4(t0, t1, t2, t3, bbuf + rowB[nt2] + kbx[ks]);
                bf[nt2 * 2 + 0][0] = t0; bf[nt2 * 2 + 0][1] = t2;
                bf[nt2 * 2 + 1][0] = t1; bf[nt2 * 2 + 1][1] = t3;
            }
#pragma unroll
            for (int mt = 0; mt < 4; mt++)
#pragma unroll
                for (int nt = 0; nt < 4; nt++)
                    MMAF16(acc[mt][nt], a[mt], bf[nt][0], bf[nt][1]);
        }
        __syncthreads();
    }

    const int rbase = (int)arow0 + (wm << 6) + (lane >> 2);
    const int cbase = (int)brow0 + (wn << 5) + ((lane & 3) << 1);
#pragma unroll
    for (int nt = 0; nt < 4; nt++) {
        const int col = cbase + (nt << 3);
        float bv0 = 0.f, bv1 = 0.f;
        if (b1) {
            if (col < n1)       { bv0 = b1[col];      bv1 = b1[col + 1]; }
            else if (col < n2)  { bv0 = b2[col - n1]; bv1 = b2[col - n1 + 1]; }
            else                { bv0 = b3[col - n2]; bv1 = b3[col - n2 + 1]; }
        }
#pragma unroll
        for (int mt = 0; mt < 4; mt++) {
            const int row = rbase + (mt << 4);
            size_t gi = (size_t)row * N + col;
            float v0 = acc[mt][nt][0] + bv0, v1 = acc[mt][nt][1] + bv1;
            if (res) { v0 += res[gi]; v1 += res[gi + 1]; }
            *(float2*)(C + gi) = make_float2(v0, v1);
            size_t gi2 = gi + (size_t)8 * N;
            float v2 = acc[mt][nt][2] + bv0, v3 = acc[mt][nt][3] + bv1;
            if (res) { v2 += res[gi2]; v3 += res[gi2 + 1]; }
            *(float2*)(C + gi2) = make_float2(v2, v3);
        }
    }
}

// ================= small fp32 SGEMM (gate path only) =================
__global__ void __launch_bounds__(256) sgemm_kernel(
    const float* __restrict__ A, const float* __restrict__ B,
    float* __restrict__ C, int M, int N, int K)
{
    __shared__ float As[8][128];
    __shared__ float Bs[8][128];
    const int tid = threadIdx.x;
    const int bx = blockIdx.x * 128;
    const int by = blockIdx.y * 128;
    const int tx = tid & 15;
    const int ty = tid >> 4;
    const int arow = tid >> 1;
    const int acol = (tid & 1) << 2;
    const int brow = tid >> 5;
    const int bcol = (tid & 31) << 2;

    const float* Ap = A + (size_t)(by + arow) * K + acol;
    const float* Bp = B + (size_t)brow * N + bx + bcol;

    float acc[8][8];
#pragma unroll
    for (int i = 0; i < 8; i++)
#pragma unroll
        for (int j = 0; j < 8; j++) acc[i][j] = 0.f;

    for (int k0 = 0; k0 < K; k0 += 8) {
        float4 av = *(const float4*)Ap;
        As[acol + 0][arow] = av.x;
        As[acol + 1][arow] = av.y;
        As[acol + 2][arow] = av.z;
        As[acol + 3][arow] = av.w;
        *(float4*)&Bs[brow][bcol] = *(const float4*)Bp;
        __syncthreads();
#pragma unroll
        for (int kk = 0; kk < 8; kk++) {
            float a[8], bb[8];
            *(float4*)&a[0] = *(const float4*)&As[kk][ty * 8];
            *(float4*)&a[4] = *(const float4*)&As[kk][ty * 8 + 4];
            *(float4*)&bb[0] = *(const float4*)&Bs[kk][tx * 8];
            *(float4*)&bb[4] = *(const float4*)&Bs[kk][tx * 8 + 4];
#pragma unroll
            for (int i = 0; i < 8; i++)
#pragma unroll
                for (int j = 0; j < 8; j++)
                    acc[i][j] += a[i] * bb[j];
        }
        __syncthreads();
        Ap += 8;
        Bp += (size_t)8 * N;
    }

    const int row0 = by + ty * 8;
    const int col0 = bx + tx * 8;
#pragma unroll
    for (int i = 0; i < 8; i++)
#pragma unroll
        for (int j = 0; j < 8; j++)
            C[(size_t)(row0 + i) * N + col0 + j] = acc[i][j];
}

// ================= pooling / gate =================
__global__ void pool_kernel(const float* __restrict__ x, int stride,
                            float* __restrict__ out, int H) {
    int qb = blockIdx.x, h = blockIdx.y, d = threadIdx.x;
    float s = 0.f;
    for (int i = 0; i < BSZ; i++)
        s += x[(size_t)(qb * BSZ + i) * stride + h * DH + d];
    out[((size_t)qb * H + h) * DH + d] = s * (1.f / (float)BSZ);
}

__global__ void gate_kernel(const float* __restrict__ qg, const float* __restrict__ kg,
                            unsigned char* __restrict__ keep) {
    int h = blockIdx.x, qb = blockIdx.y, kb = threadIdx.x;
    const float* qv = qg + ((size_t)qb * HQ + h) * GHD;
    const float* kv = kg + ((size_t)kb * HKV + (h >> 2)) * GHD;
    float s = 0.f;
    for (int d = 0; d < GHD; d++) s += qv[d] * kv[d];
    s *= SCALE_INV_SQRT_128;
    if (kb > qb) s = -1e30f;
    float m = s;
    for (int off = 16; off > 0; off >>= 1)
        m = fmaxf(m, __shfl_xor_sync(0xffffffffu, m, off));
    float e = expf(s - m);
    float sum = e;
    for (int off = 16; off > 0; off >>= 1)
        sum += __shfl_xor_sync(0xffffffffu, sum, off);
    float gate = e / sum;
    bool kp = (kb <= qb) && ((gate >= 0.004f) || (kb == qb));
    keep[((size_t)h * QBN + qb) * QBN + kb] = kp ? 1 : 0;
}

// ===== RoPE + fp16 conversion: qkv fp32 -> qf16 (scaled), kf16 =====
__global__ void ropeconv_kernel(const float* __restrict__ qkv,
                                const float* __restrict__ cs, const float* __restrict__ sn,
                                __half* __restrict__ qf, __half* __restrict__ kf) {
    int t = blockIdx.x;
    const float* row = qkv + (size_t)t * NQKV;
    const float* c = cs + (size_t)t * DH;
    const float* s = sn + (size_t)t * DH;
    for (int i = threadIdx.x; i < HQ * 64; i += 256) {
        int hh = i >> 6, d = i & 63;
        float x1 = row[hh * DH + d], x2 = row[hh * DH + d + 64];
        qf[(size_t)t * (HQ*DH) + hh * DH + d] =
            __float2half_rn((x1 * c[d] - x2 * s[d]) * SCALE_INV_SQRT_128);
        qf[(size_t)t * (HQ*DH) + hh * DH + d + 64] =
            __float2half_rn((x2 * c[d + 64] + x1 * s[d + 64]) * SCALE_INV_SQRT_128);
    }
    for (int i = threadIdx.x; i < HKV * 64; i += 256) {
        int hh = i >> 6, d = i & 63;
        float x1 = row[2048 + hh * DH + d], x2 = row[2048 + hh * DH + d + 64];
        kf[(size_t)t * (HKV*DH) + hh * DH + d] =
            __float2half_rn(x1 * c[d] - x2 * s[d]);
        kf[(size_t)t * (HKV*DH) + hh * DH + d + 64] =
            __float2half_rn(x2 * c[d + 64] + x1 * s[d + 64]);
    }
}

// ===== V transpose + fp16: qkv v-part -> vt[(hk*DH+d)*SEQ + t] =====
__global__ void vconvt_kernel(const float* __restrict__ qkv, __half* __restrict__ vt) {
    __shared__ float tile[32][33];
    int t0 = blockIdx.x * 32, d0 = blockIdx.y * 32, hk = blockIdx.z;
    for (int i = threadIdx.y; i < 32; i += 8)
        tile[i][threadIdx.x] = qkv[(size_t)(t0 + i) * NQKV + 2560 + hk * DH + d0 + threadIdx.x];
    __syncthreads();
    for (int i = threadIdx.y; i < 32; i += 8) {
        int d = d0 + i, t = t0 + threadIdx.x;
        vt[((size_t)hk * DH + d) * SEQ + t] = __float2half_rn(tile[threadIdx.x][i]);
    }
}

// ================= fp16 tensor-core block-sparse flash attention =================
// smem (halves): QS 64x136, KS 64x136, VT 128x72, PS 64x72; fp32 reductions after.
#define QKP 136
#define VTP 72
#define PSP 72
#define FS_OFF 62464   // bytes: (64*136 + 64*136 + 128*72 + 64*72) * 2
#define ATTN_SMEM (FS_OFF + 448*4)

__global__ void __launch_bounds__(256, 2) attn_kernel(
    const __half* __restrict__ qf, const __half* __restrict__ kf,
    const __half* __restrict__ vt,
    const unsigned char* __restrict__ keep, __half* __restrict__ oa2)
{
    extern __shared__ char smc[];
    __half* QS = (__half*)smc;
    __half* KS = QS + 64 * QKP;
    __half* VT = KS + 64 * QKP;
    __half* PS = VT + 128 * VTP;
    float* fs = (float*)(smc + FS_OFF);
    float* ARM = fs; float* ARL = fs + 128;
    float* ROWM = fs + 256; float* ROWL = fs + 320; float* ALF = fs + 384;

    const int qb = QBN - 1 - blockIdx.x;
    const int h = blockIdx.y;
    const int hk = h >> 2;
    const int tid = threadIdx.x;
    const int lane = tid & 31, wid = tid >> 5;
    const int rw = wid & 3, cw = wid >> 2;
    const int g = lane >> 2, qd = lane & 3;
    const int r0 = rw * 16 + g;
    const int r1 = r0 + 8;
    const int q2 = qd * 2;

    // load Q tile (rope+scale already applied)
    for (int i = tid; i < 64 * 16; i += 256) {
        int r = i >> 4, c = i & 15;
        *(uint4*)&QS[r * QKP + c * 8] =
            *(const uint4*)&qf[(size_t)(qb * 64 + r) * (HQ*DH) + h * DH + c * 8];
    }
    if (tid < 64) { ROWM[tid] = -1e30f; ROWL[tid] = 0.f; }

    float oacc[8][4];
#pragma unroll
    for (int i = 0; i < 8; i++)
#pragma unroll
        for (int j = 0; j < 4; j++) oacc[i][j] = 0.f;

    const unsigned char* krow = keep + ((size_t)h * QBN + qb) * QBN;

    for (int kb = 0; kb <= qb; kb++) {
        if (!krow[kb]) continue;
        __syncthreads();

        for (int i = tid; i < 64 * 16; i += 256) {
            int r = i >> 4, c = i & 15;
            *(uint4*)&KS[r * QKP + c * 8] =
                *(const uint4*)&kf[(size_t)(kb * 64 + r) * (HKV*DH) + hk * DH + c * 8];
        }
        for (int i = tid; i < 128 * 8; i += 256) {
            int d = i >> 3, c = i & 7;
            *(uint4*)&VT[d * VTP + c * 8] =
                *(const uint4*)&vt[((size_t)hk * DH + d) * SEQ + kb * 64 + c * 8];
        }
        __syncthreads();

        // S = Q @ K^T (fp16 mma, 8 K-chunks of 16)
        float sacc[4][4];
#pragma unroll
        for (int i = 0; i < 4; i++)
#pragma unroll
            for (int j = 0; j < 4; j++) sacc[i][j] = 0.f;

#pragma unroll
        for (int kc = 0; kc < 8; kc++) {
            const int k0 = kc * 16;
            uint32_t a[4];
            a[0] = *(const uint32_t*)&QS[r0 * QKP + k0 + q2];
            a[1] = *(const uint32_t*)&QS[r1 * QKP + k0 + q2];
            a[2] = *(const uint32_t*)&QS[r0 * QKP + k0 + q2 + 8];
            a[3] = *(const uint32_t*)&QS[r1 * QKP + k0 + q2 + 8];
#pragma unroll
            for (int nt = 0; nt < 4; nt++) {
                const int n = cw * 32 + nt * 8 + g;
                uint32_t b0 = *(const uint32_t*)&KS[n * QKP + k0 + q2];
                uint32_t b1 = *(const uint32_t*)&KS[n * QKP + k0 + q2 + 8];
                MMAF16(sacc[nt], a, b0, b1);
            }
        }

        if (kb == qb) {
#pragma unroll
            for (int nt = 0; nt < 4; nt++) {
                const int c0 = cw * 32 + nt * 8 + q2;
                if (c0 > r0)     sacc[nt][0] = -1e30f;
                if (c0 + 1 > r0) sacc[nt][1] = -1e30f;
                if (c0 > r1)     sacc[nt][2] = -1e30f;
                if (c0 + 1 > r1) sacc[nt][3] = -1e30f;
            }
        }

        float m0 = -1e30f, m1 = -1e30f;
#pragma unroll
        for (int nt = 0; nt < 4; nt++) {
            m0 = fmaxf(m0, fmaxf(sacc[nt][0], sacc[nt][1]));
            m1 = fmaxf(m1, fmaxf(sacc[nt][2], sacc[nt][3]));
        }
        m0 = fmaxf(m0, __shfl_xor_sync(0xffffffffu, m0, 1));
        m0 = fmaxf(m0, __shfl_xor_sync(0xffffffffu, m0, 2));
        m1 = fmaxf(m1, __shfl_xor_sync(0xffffffffu, m1, 1));
        m1 = fmaxf(m1, __shfl_xor_sync(0xffffffffu, m1, 2));
        if (qd == 0) {
            ARM[cw * 64 + r0] = m0;
            ARM[cw * 64 + r1] = m1;
        }
        __syncthreads();

        if (tid < 64) {
            float newm = fmaxf(ROWM[tid], fmaxf(ARM[tid], ARM[64 + tid]));
            ALF[tid] = __expf(ROWM[tid] - newm);
            ROWM[tid] = newm;
        }
        __syncthreads();

        const float nm0 = ROWM[r0];
        const float nm1 = ROWM[r1];
        float l0 = 0.f, l1 = 0.f;
#pragma unroll
        for (int nt = 0; nt < 4; nt++) {
            const int c0 = cw * 32 + nt * 8 + q2;
            float p0 = __expf(sacc[nt][0] - nm0);
            float p1 = __expf(sacc[nt][1] - nm0);
            float p2 = __expf(sacc[nt][2] - nm1);
            float p3 = __expf(sacc[nt][3] - nm1);
            l0 += p0 + p1; l1 += p2 + p3;
            *(__half2*)&PS[r0 * PSP + c0] = __floats2half2_rn(p0, p1);
            *(__half2*)&PS[r1 * PSP + c0] = __floats2half2_rn(p2, p3);
        }
        l0 += __shfl_xor_sync(0xffffffffu, l0, 1);
        l0 += __shfl_xor_sync(0xffffffffu, l0, 2);
        l1 += __shfl_xor_sync(0xffffffffu, l1, 1);
        l1 += __shfl_xor_sync(0xffffffffu, l1, 2);
        if (qd == 0) {
            ARL[cw * 64 + r0] = l0;
            ARL[cw * 64 + r1] = l1;
        }
        const float al0 = ALF[r0];
        const float al1 = ALF[r1];
#pragma unroll
        for (int nt = 0; nt < 8; nt++) {
            oacc[nt][0] *= al0; oacc[nt][1] *= al0;
            oacc[nt][2] *= al1; oacc[nt][3] *= al1;
        }
        __syncthreads();

        if (tid < 64)
            ROWL[tid] = ROWL[tid] * ALF[tid] + ARL[tid] + ARL[64 + tid];

        // O += P @ V (fp16 mma, 4 K-chunks of 16 tokens)
#pragma unroll
        for (int kc = 0; kc < 4; kc++) {
            const int k0 = kc * 16;
            uint32_t a[4];
            a[0] = *(const uint32_t*)&PS[r0 * PSP + k0 + q2];
            a[1] = *(const uint32_t*)&PS[r1 * PSP + k0 + q2];
            a[2] = *(const uint32_t*)&PS[r0 * PSP + k0 + q2 + 8];
            a[3] = *(const uint32_t*)&PS[r1 * PSP + k0 + q2 + 8];
#pragma unroll
            for (int nt = 0; nt < 8; nt++) {
                const int n = cw * 64 + nt * 8 + g;
                uint32_t b0 = *(const uint32_t*)&VT[n * VTP + k0 + q2];
                uint32_t b1 = *(const uint32_t*)&VT[n * VTP + k0 + q2 + 8];
                MMAF16(oacc[nt], a, b0, b1);
            }
        }
    }

    __syncthreads();
    const float inv0 = 1.f / ROWL[r0];
    const float inv1 = 1.f / ROWL[r1];
    const size_t grow0 = (size_t)(qb * 64 + r0);
    const size_t grow1 = (size_t)(qb * 64 + r1);
#pragma unroll
    for (int nt = 0; nt < 8; nt++) {
        const int col = h * DH + cw * 64 + nt * 8 + q2;
        *(__half2*)(oa2 + grow0 * HID + col) =
            __floats2half2_rn(oacc[nt][0] * inv0, oacc[nt][1] * inv0);
        *(__half2*)(oa2 + grow1 * HID + col) =
            __floats2half2_rn(oacc[nt][2] * inv1, oacc[nt][3] * inv1);
    }
}

// ================= SiLU(gate)*up fused with fp16 conversion ============
__global__ void siluconv_kernel(const float* __restrict__ gu, __half* __restrict__ y) {
    int s = blockIdx.y;
    int j = blockIdx.x * 256 + threadIdx.x;
    size_t row = (size_t)s * NGU;
    float x = gu[row + j];
    float u = gu[row + INTER + j];
    float v = (x / (1.f + __expf(-x))) * u;
    y[(size_t)s * INTER + j] = __float2half_rn(v);
}

// ================= launch =================
extern "C" void kernel_launch(void* const* d_in, const int* in_sizes, int n_in,
                              void* d_out, int out_size) {
    const float* hidden = (const float*)d_in[0];
    const float* cosp   = (const float*)d_in[1];
    const float* sinp   = (const float*)d_in[2];
    const float* ln1    = (const float*)d_in[3];
    const float* ln2    = (const float*)d_in[4];
    const float* Wq     = (const float*)d_in[5];
    const float* bq     = (const float*)d_in[6];
    const float* Wk     = (const float*)d_in[7];
    const float* bk     = (const float*)d_in[8];
    const float* Wv     = (const float*)d_in[9];
    const float* bv     = (const float*)d_in[10];
    const float* Wo     = (const float*)d_in[11];
    const float* gWq    = (const float*)d_in[12];
    const float* gWk    = (const float*)d_in[13];
    const float* Wgate  = (const float*)d_in[14];
    const float* Wup    = (const float*)d_in[15];
    const float* Wdown  = (const float*)d_in[16];
    float* out = (float*)d_out;

    float *qkv, *qp, *kp, *qg, *kg, *h2, *gu;
    unsigned char* keep;
    __half *Wqkv2, *Wo2, *Wgu2, *Wd2, *ha2, *oa2, *h3a2, *gt2, *qf16, *kf16, *vt16;
    cudaGetSymbolAddress((void**)&qkv,  g_qkv);
    cudaGetSymbolAddress((void**)&qp,   g_qp);
    cudaGetSymbolAddress((void**)&kp,   g_kp);
    cudaGetSymbolAddress((void**)&qg,   g_qg);
    cudaGetSymbolAddress((void**)&kg,   g_kg);
    cudaGetSymbolAddress((void**)&keep, g_keep);
    cudaGetSymbolAddress((void**)&h2,   g_h2);
    cudaGetSymbolAddress((void**)&gu,   g_gu);
    cudaGetSymbolAddress((void**)&Wqkv2, g_Wqkv2);
    cudaGetSymbolAddress((void**)&Wo2,  g_Wo2);
    cudaGetSymbolAddress((void**)&Wgu2, g_Wgu2);
    cudaGetSymbolAddress((void**)&Wd2,  g_Wd2);
    cudaGetSymbolAddress((void**)&ha2,  g_ha2);
    cudaGetSymbolAddress((void**)&oa2,  g_oa2);
    cudaGetSymbolAddress((void**)&h3a2, g_h3a2);
    cudaGetSymbolAddress((void**)&gt2,  g_gt2);
    cudaGetSymbolAddress((void**)&qf16, g_qf16);
    cudaGetSymbolAddress((void**)&kf16, g_kf16);
    cudaGetSymbolAddress((void**)&vt16, g_vt16);

    cudaFuncSetAttribute(hgemm_kernel, cudaFuncAttributeMaxDynamicSharedMemorySize, HG_SMEM);
    cudaFuncSetAttribute(attn_kernel, cudaFuncAttributeMaxDynamicSharedMemorySize, ATTN_SMEM);

    dim3 w8(32, 8);
    cudaStream_t s2 = g_aux.s2;

    // ---- fork side stream: weight conversions + gate path off critical path ----
    cudaEventRecord(g_aux.root, 0);
    cudaStreamWaitEvent(s2, g_aux.root, 0);
    wconv3_kernel<<<dim3(NQKV/32, HID/32), w8, 0, s2>>>(Wq, Wk, Wv, Wqkv2);
    cudaEventRecord(g_aux.evQKV, s2);
    wconv_kernel<<<dim3(HID/32, HID/32), w8, 0, s2>>>(Wo, Wo2, HID, HID);
    cudaEventRecord(g_aux.evWo, s2);
    wconv_kernel<<<dim3(INTER/32, HID/32), w8, 0, s2>>>(Wgate, Wgu2, HID, INTER);
    wconv_kernel<<<dim3(INTER/32, HID/32), w8, 0, s2>>>(Wup, Wgu2 + (size_t)INTER*HID, HID, INTER);
    cudaEventRecord(g_aux.evGU, s2);
    wconv_kernel<<<dim3(HID/32, INTER/32), w8, 0, s2>>>(Wdown, Wd2, INTER, HID);
    cudaEventRecord(g_aux.evWd, s2);

    // ---- main chain ----
    rmsconv_kernel<<<SEQ, 256>>>(hidden, ln1, ha2, 2);
    cudaStreamWaitEvent(0, g_aux.evQKV, 0);
    hgemm_kernel<<<dim3(SEQ/128, NQKV/128), 256, HG_SMEM>>>(
        ha2, Wqkv2, bq, bk, bv, 2048, 2560, nullptr, qkv, NQKV, HID, 2);

    // gate path on s2 overlapping rope/V conversions (qkv is never mutated)
    pool_kernel<<<dim3(QBN, HQ), DH>>>(qkv, NQKV, qp, HQ);
    pool_kernel<<<dim3(QBN, HKV), DH>>>(qkv + 2048, NQKV, kp, HKV);
    cudaEventRecord(g_aux.evPool, 0);
    cudaStreamWaitEvent(s2, g_aux.evPool, 0);
    sgemm_kernel<<<dim3(GHD/128, (QBN*HQ)/128), 256, 0, s2>>>(qp, gWq, qg, QBN*HQ, GHD, DH);
    sgemm_kernel<<<dim3(GHD/128, (QBN*HKV)/128), 256, 0, s2>>>(kp, gWk, kg, QBN*HKV, GHD, DH);
    gate_kernel<<<dim3(HQ, QBN), 32, 0, s2>>>(qg, kg, keep);
    cudaEventRecord(g_aux.evGate, s2);

    ropeconv_kernel<<<SEQ, 256>>>(qkv, cosp, sinp, qf16, kf16);
    vconvt_kernel<<<dim3(SEQ/32, DH/32, HKV), w8>>>(qkv, vt16);

    cudaStreamWaitEvent(0, g_aux.evGate, 0);
    attn_kernel<<<dim3(QBN, HQ), 256, ATTN_SMEM>>>(qf16, kf16, vt16, keep, oa2);

    cudaStreamWaitEvent(0, g_aux.evWo, 0);
    hgemm_kernel<<<dim3(SEQ/128, HID/128), 256, HG_SMEM>>>(
        oa2, Wo2, nullptr, nullptr, nullptr, HID, HID, hidden, h2, HID, HQ*DH, 1);

    rmsconv_kernel<<<SEQ, 256>>>(h2, ln2, h3a2, 1);

    cudaStreamWaitEvent(0, g_aux.evGU, 0);
    hgemm_kernel<<<dim3(SEQ/128, NGU/128), 256, HG_SMEM>>>(
        h3a2, Wgu2, nullptr, nullptr, nullptr, NGU, NGU, nullptr, gu, NGU, HID, 1);

    siluconv_kernel<<<dim3(INTER/256, SEQ), 256>>>(gu, gt2);

    cudaStreamWaitEvent(0, g_aux.evWd, 0);
    hgemm_kernel<<<dim3(SEQ/128, HID/128), 256, HG_SMEM>>>(
        gt2, Wd2, nullptr, nullptr, nullptr, HID, HID, h2, out, HID, INTER, 1);
}

// round 13
// speedup vs baseline: 4.9823x; 1.0496x over previous
#include <cuda_runtime.h>
#include <cuda_fp16.h>
#include <math.h>
#include <stdint.h>

#define SEQ   2048
#define HID   2048
#define HQ    16
#define HKV   4
#define DH    128
#define QBN   32
#define BSZ   64
#define GHD   128
#define INTER 5632
#define NQKV  3072
#define NGU   11264

#define SCALE_INV_SQRT_128 0.08838834764831845f

// ================= helpers =================
__device__ __forceinline__ uint32_t smem_u32(const void* p) {
    uint32_t a;
    asm("{ .reg .u64 t; cvta.to.shared.u64 t, %1; cvt.u32.u64 %0, t; }" : "=r"(a) : "l"(p));
    return a;
}
__device__ __forceinline__ void cp_async16(uint32_t saddr, const void* gptr) {
    asm volatile("cp.async.cg.shared.global [%0], [%1], 16;" :: "r"(saddr), "l"(gptr));
}
__device__ __forceinline__ void cp_commit() { asm volatile("cp.async.commit_group;"); }

#define LDSM_X4(r0, r1, r2, r3, addr) \
    asm volatile("ldmatrix.sync.aligned.m8n8.x4.shared.b16 {%0,%1,%2,%3}, [%4];" \
        : "=r"(r0), "=r"(r1), "=r"(r2), "=r"(r3) : "r"(addr))

#define MMAF16(c, a, b0r, b1r) \
    asm volatile("mma.sync.aligned.m16n8k16.row.col.f32.f16.f16.f32 " \
        "{%0,%1,%2,%3}, {%4,%5,%6,%7}, {%8,%9}, {%0,%1,%2,%3};" \
        : "+f"((c)[0]), "+f"((c)[1]), "+f"((c)[2]), "+f"((c)[3]) \
        : "r"((a)[0]), "r"((a)[1]), "r"((a)[2]), "r"((a)[3]), "r"(b0r), "r"(b1r))

static __device__ __forceinline__ uint32_t sw128(uint32_t o) { return o ^ ((o >> 3) & 0x70); }

__device__ __forceinline__ float siluf(float x) { return x / (1.f + __expf(-x)); }

// ================= device scratch =================
__device__ float g_qkv [SEQ*NQKV];
__device__ float g_qp  [QBN*HQ*DH];
__device__ float g_kp  [QBN*HKV*DH];
__device__ float g_qg  [QBN*HQ*GHD];
__device__ float g_kg  [QBN*HKV*GHD];
__device__ unsigned char g_keep[HQ*QBN*QBN];
__device__ float g_h2  [SEQ*HID];

__device__ __half g_Wqkv2[NQKV*HID];
__device__ __half g_Wo2  [2048*2048];
__device__ __half g_Wgu2 [NGU*HID];      // interleaved: row 2j = gate_j, 2j+1 = up_j
__device__ __half g_Wd2  [2048*INTER];
__device__ __half g_ha2  [SEQ*2*HID];
__device__ __half g_oa2  [SEQ*HID];
__device__ __half g_h3a2 [SEQ*HID];
__device__ __half g_gt2  [SEQ*INTER];
__device__ __half g_qf16 [SEQ*HQ*DH];
__device__ __half g_kf16 [SEQ*HKV*DH];
__device__ __half g_vt16 [HKV*DH*SEQ];

// ===== side-stream resources (created pre-main in static init) =====
struct AuxRes {
    cudaStream_t s2;
    cudaEvent_t root, evQKV, evWo, evGU, evWd, evPool, evGate;
    AuxRes() {
        cudaStreamCreateWithFlags(&s2, cudaStreamNonBlocking);
        cudaEventCreateWithFlags(&root,   cudaEventDisableTiming);
        cudaEventCreateWithFlags(&evQKV,  cudaEventDisableTiming);
        cudaEventCreateWithFlags(&evWo,   cudaEventDisableTiming);
        cudaEventCreateWithFlags(&evGU,   cudaEventDisableTiming);
        cudaEventCreateWithFlags(&evWd,   cudaEventDisableTiming);
        cudaEventCreateWithFlags(&evPool, cudaEventDisableTiming);
        cudaEventCreateWithFlags(&evGate, cudaEventDisableTiming);
    }
};
static AuxRes g_aux;

// ===== fused QKV weight conversion: fp32 [K,N]x3 -> fp16 [3072, K] =====
__global__ void wconv3_kernel(const float* __restrict__ Wq, const float* __restrict__ Wk,
                              const float* __restrict__ Wv, __half* __restrict__ y) {
    __shared__ float tile[32][33];
    int n0 = blockIdx.x * 32, k0 = blockIdx.y * 32;
    const float* W; int sN, c0;
    if (n0 < 2048)      { W = Wq; sN = 2048; c0 = n0; }
    else if (n0 < 2560) { W = Wk; sN = 512;  c0 = n0 - 2048; }
    else                { W = Wv; sN = 512;  c0 = n0 - 2560; }
    for (int i = threadIdx.y; i < 32; i += 8)
        tile[i][threadIdx.x] = W[(size_t)(k0 + i) * sN + c0 + threadIdx.x];
    __syncthreads();
    for (int i = threadIdx.y; i < 32; i += 8) {
        int n = n0 + i, k = k0 + threadIdx.x;
        y[(size_t)n * HID + k] = __float2half_rn(tile[threadIdx.x][i]);
    }
}

// ===== weight conversion: fp32 [K,N] -> fp16 [N,K] =====
__global__ void wconv_kernel(const float* __restrict__ W, __half* __restrict__ y,
                             int K, int N) {
    __shared__ float tile[32][33];
    int n0 = blockIdx.x * 32, k0 = blockIdx.y * 32;
    for (int i = threadIdx.y; i < 32; i += 8)
        tile[i][threadIdx.x] = W[(size_t)(k0 + i) * N + n0 + threadIdx.x];
    __syncthreads();
    for (int i = threadIdx.y; i < 32; i += 8) {
        int n = n0 + i, k = k0 + threadIdx.x;
        y[(size_t)n * K + k] = __float2half_rn(tile[threadIdx.x][i]);
    }
}

// ===== interleaved gate/up weight conversion: rows 2j=gate_j, 2j+1=up_j =====
__global__ void wconvGU_kernel(const float* __restrict__ Wg, const float* __restrict__ Wu,
                               __half* __restrict__ y) {
    __shared__ float tg[32][33];
    __shared__ float tu[32][33];
    int j0 = blockIdx.x * 32, k0 = blockIdx.y * 32;
    for (int i = threadIdx.y; i < 32; i += 8) {
        tg[i][threadIdx.x] = Wg[(size_t)(k0 + i) * INTER + j0 + threadIdx.x];
        tu[i][threadIdx.x] = Wu[(size_t)(k0 + i) * INTER + j0 + threadIdx.x];
    }
    __syncthreads();
    for (int i = threadIdx.y; i < 32; i += 8) {
        int j = j0 + i, k = k0 + threadIdx.x;
        y[(size_t)(2 * j)     * HID + k] = __float2half_rn(tg[threadIdx.x][i]);
        y[(size_t)(2 * j + 1) * HID + k] = __float2half_rn(tu[threadIdx.x][i]);
    }
}

// ===== RMSNorm fused with fp16 conversion (segs = 1 or 2 limbs) =====
__global__ void rmsconv_kernel(const float* __restrict__ x, const float* __restrict__ w,
                               __half* __restrict__ y, int segs) {
    int row = blockIdx.x;
    const float* xr = x + (size_t)row * HID;
    float s = 0.f;
    for (int i = threadIdx.x; i < HID; i += 256) { float v = xr[i]; s += v * v; }
    __shared__ float red[256];
    red[threadIdx.x] = s; __syncthreads();
    for (int st = 128; st > 0; st >>= 1) {
        if (threadIdx.x < st) red[threadIdx.x] += red[threadIdx.x + st];
        __syncthreads();
    }
    float r = rsqrtf(red[0] / (float)HID + 1e-6f);
    size_t base = (size_t)row * segs * HID;
    for (int i = threadIdx.x; i < HID; i += 256) {
        float v = w[i] * xr[i] * r;
        __half h = __float2half_rn(v);
        y[base + i] = h;
        if (segs == 2)
            y[base + HID + i] = __float2half_rn(v - __half2float(h));
    }
}

// ====== fp16 HMMA GEMM, segs-limb A; optional fused SiLU(g)*u fp16 output ======
#define HG_SMEM 65536

__global__ void __launch_bounds__(256, 2) hgemm_kernel(
    const __half* __restrict__ A, const __half* __restrict__ B,
    const float* __restrict__ b1, const float* __restrict__ b2, const float* __restrict__ b3,
    int n1, int n2,
    const float* __restrict__ res,
    float* __restrict__ C, __half* __restrict__ Chalf,
    int N, int K, int segs)
{
    extern __shared__ char smraw[];
    const uint32_t smu = smem_u32(smraw);
    const int tid = threadIdx.x;
    const int lane = tid & 31, wid = tid >> 5;
    const int wm = wid >> 2, wn = wid & 3;
    const size_t ldaA = (size_t)segs * K;
    const size_t ldaB = (size_t)K;
    const int kpseg = K >> 6;
    const int nch = segs * kpseg;
    const size_t arow0 = (size_t)blockIdx.x * 128;
    const size_t brow0 = (size_t)blockIdx.y * 128;

    const uint32_t xm = (uint32_t)((lane & 7) << 4);
    uint32_t kbx[4];
#pragma unroll
    for (int ks = 0; ks < 4; ks++)
        kbx[ks] = ((uint32_t)(ks * 32 + ((lane >> 4) << 4))) ^ xm;
    uint32_t rowA[4], rowB[2];
#pragma unroll
    for (int mt = 0; mt < 4; mt++)
        rowA[mt] = (uint32_t)((wm << 6) + (lane & 15) + (mt << 4)) * 128u;
#pragma unroll
    for (int nt2 = 0; nt2 < 2; nt2++)
        rowB[nt2] = (uint32_t)((wn << 5) + (lane & 15) + (nt2 << 4)) * 128u;

    float acc[4][4][4];
#pragma unroll
    for (int i = 0; i < 4; i++)
#pragma unroll
        for (int j = 0; j < 4; j++)
#pragma unroll
            for (int t = 0; t < 4; t++) acc[i][j][t] = 0.f;

    auto issue = [&](int ch, int b) {
        int seg = ch / kpseg;
        int kk = (ch - seg * kpseg) << 6;
        const __half* Ab = A + (size_t)seg * K + kk;
        const __half* Bb = B + kk;
        uint32_t abase = smu + b * 32768;
        uint32_t bbase = abase + 16384;
#pragma unroll
        for (int i = 0; i < 4; i++) {
            int u = i * 256 + tid;
            int r = u >> 3, c = u & 7;
            uint32_t so = sw128((uint32_t)(r * 128 + c * 16));
            cp_async16(abase + so, Ab + (arow0 + r) * ldaA + c * 8);
            cp_async16(bbase + so, Bb + (brow0 + r) * ldaB + c * 8);
        }
        cp_commit();
    };

    issue(0, 0);

    for (int ch = 0; ch < nch; ch++) {
        const int b = ch & 1;
        if (ch + 1 < nch) {
            issue(ch + 1, b ^ 1);
            asm volatile("cp.async.wait_group 1;");
        } else {
            asm volatile("cp.async.wait_group 0;");
        }
        __syncthreads();

        const uint32_t abuf = smu + b * 32768;
        const uint32_t bbuf = abuf + 16384;

#pragma unroll
        for (int ks = 0; ks < 4; ks++) {
            uint32_t a[4][4];
#pragma unroll
            for (int mt = 0; mt < 4; mt++)
                LDSM_X4(a[mt][0], a[mt][1], a[mt][2], a[mt][3],
                        abuf + rowA[mt] + kbx[ks]);
            uint32_t bf[4][2];
#pragma unroll
            for (int nt2 = 0; nt2 < 2; nt2++) {
                uint32_t t0, t1, t2, t3;
                LDSM_X4(t0, t1, t2, t3, bbuf + rowB[nt2] + kbx[ks]);
                bf[nt2 * 2 + 0][0] = t0; bf[nt2 * 2 + 0][1] = t2;
                bf[nt2 * 2 + 1][0] = t1; bf[nt2 * 2 + 1][1] = t3;
            }
#pragma unroll
            for (int mt = 0; mt < 4; mt++)
#pragma unroll
                for (int nt = 0; nt < 4; nt++)
                    MMAF16(acc[mt][nt], a[mt], bf[nt][0], bf[nt][1]);
        }
        __syncthreads();
    }

    const int rbase = (int)arow0 + (wm << 6) + (lane >> 2);
    const int cbase = (int)brow0 + (wn << 5) + ((lane & 3) << 1);

    if (Chalf) {
        // fused SiLU: B rows interleaved (even=gate, odd=up); out col = col/2
        const int No = N >> 1;
#pragma unroll
        for (int nt = 0; nt < 4; nt++) {
            const int col = cbase + (nt << 3);
            const int oc = col >> 1;
#pragma unroll
            for (int mt = 0; mt < 4; mt++) {
                const int row = rbase + (mt << 4);
                float v0 = siluf(acc[mt][nt][0]) * acc[mt][nt][1];
                Chalf[(size_t)row * No + oc] = __float2half_rn(v0);
                float v1 = siluf(acc[mt][nt][2]) * acc[mt][nt][3];
                Chalf[(size_t)(row + 8) * No + oc] = __float2half_rn(v1);
            }
        }
        return;
    }

#pragma unroll
    for (int nt = 0; nt < 4; nt++) {
        const int col = cbase + (nt << 3);
        float bv0 = 0.f, bv1 = 0.f;
        if (b1) {
            if (col < n1)       { bv0 = b1[col];      bv1 = b1[col + 1]; }
            else if (col < n2)  { bv0 = b2[col - n1]; bv1 = b2[col - n1 + 1]; }
            else                { bv0 = b3[col - n2]; bv1 = b3[col - n2 + 1]; }
        }
#pragma unroll
        for (int mt = 0; mt < 4; mt++) {
            const int row = rbase + (mt << 4);
            size_t gi = (size_t)row * N + col;
            float v0 = acc[mt][nt][0] + bv0, v1 = acc[mt][nt][1] + bv1;
            if (res) { v0 += res[gi]; v1 += res[gi + 1]; }
            *(float2*)(C + gi) = make_float2(v0, v1);
            size_t gi2 = gi + (size_t)8 * N;
            float v2 = acc[mt][nt][2] + bv0, v3 = acc[mt][nt][3] + bv1;
            if (res) { v2 += res[gi2]; v3 += res[gi2 + 1]; }
            *(float2*)(C + gi2) = make_float2(v2, v3);
        }
    }
}

// ================= small fp32 SGEMM (gate path only) =================
__global__ void __launch_bounds__(256) sgemm_kernel(
    const float* __restrict__ A, const float* __restrict__ B,
    float* __restrict__ C, int M, int N, int K)
{
    __shared__ float As[8][128];
    __shared__ float Bs[8][128];
    const int tid = threadIdx.x;
    const int bx = blockIdx.x * 128;
    const int by = blockIdx.y * 128;
    const int tx = tid & 15;
    const int ty = tid >> 4;
    const int arow = tid >> 1;
    const int acol = (tid & 1) << 2;
    const int brow = tid >> 5;
    const int bcol = (tid & 31) << 2;

    const float* Ap = A + (size_t)(by + arow) * K + acol;
    const float* Bp = B + (size_t)brow * N + bx + bcol;

    float acc[8][8];
#pragma unroll
    for (int i = 0; i < 8; i++)
#pragma unroll
        for (int j = 0; j < 8; j++) acc[i][j] = 0.f;

    for (int k0 = 0; k0 < K; k0 += 8) {
        float4 av = *(const float4*)Ap;
        As[acol + 0][arow] = av.x;
        As[acol + 1][arow] = av.y;
        As[acol + 2][arow] = av.z;
        As[acol + 3][arow] = av.w;
        *(float4*)&Bs[brow][bcol] = *(const float4*)Bp;
        __syncthreads();
#pragma unroll
        for (int kk = 0; kk < 8; kk++) {
            float a[8], bb[8];
            *(float4*)&a[0] = *(const float4*)&As[kk][ty * 8];
            *(float4*)&a[4] = *(const float4*)&As[kk][ty * 8 + 4];
            *(float4*)&bb[0] = *(const float4*)&Bs[kk][tx * 8];
            *(float4*)&bb[4] = *(const float4*)&Bs[kk][tx * 8 + 4];
#pragma unroll
            for (int i = 0; i < 8; i++)
#pragma unroll
                for (int j = 0; j < 8; j++)
                    acc[i][j] += a[i] * bb[j];
        }
        __syncthreads();
        Ap += 8;
        Bp += (size_t)8 * N;
    }

    const int row0 = by + ty * 8;
    const int col0 = bx + tx * 8;
#pragma unroll
    for (int i = 0; i < 8; i++)
#pragma unroll
        for (int j = 0; j < 8; j++)
            C[(size_t)(row0 + i) * N + col0 + j] = acc[i][j];
}

// ================= pooling / gate =================
__global__ void pool_kernel(const float* __restrict__ x, int stride,
                            float* __restrict__ out, int H) {
    int qb = blockIdx.x, h = blockIdx.y, d = threadIdx.x;
    float s = 0.f;
    for (int i = 0; i < BSZ; i++)
        s += x[(size_t)(qb * BSZ + i) * stride + h * DH + d];
    out[((size_t)qb * H + h) * DH + d] = s * (1.f / (float)BSZ);
}

__global__ void gate_kernel(const float* __restrict__ qg, const float* __restrict__ kg,
                            unsigned char* __restrict__ keep) {
    int h = blockIdx.x, qb = blockIdx.y, kb = threadIdx.x;
    const float* qv = qg + ((size_t)qb * HQ + h) * GHD;
    const float* kv = kg + ((size_t)kb * HKV + (h >> 2)) * GHD;
    float s = 0.f;
    for (int d = 0; d < GHD; d++) s += qv[d] * kv[d];
    s *= SCALE_INV_SQRT_128;
    if (kb > qb) s = -1e30f;
    float m = s;
    for (int off = 16; off > 0; off >>= 1)
        m = fmaxf(m, __shfl_xor_sync(0xffffffffu, m, off));
    float e = expf(s - m);
    float sum = e;
    for (int off = 16; off > 0; off >>= 1)
        sum += __shfl_xor_sync(0xffffffffu, sum, off);
    float gate = e / sum;
    bool kp = (kb <= qb) && ((gate >= 0.004f) || (kb == qb));
    keep[((size_t)h * QBN + qb) * QBN + kb] = kp ? 1 : 0;
}

// ===== RoPE + fp16 conversion =====
__global__ void ropeconv_kernel(const float* __restrict__ qkv,
                                const float* __restrict__ cs, const float* __restrict__ sn,
                                __half* __restrict__ qf, __half* __restrict__ kf) {
    int t = blockIdx.x;
    const float* row = qkv + (size_t)t * NQKV;
    const float* c = cs + (size_t)t * DH;
    const float* s = sn + (size_t)t * DH;
    for (int i = threadIdx.x; i < HQ * 64; i += 256) {
        int hh = i >> 6, d = i & 63;
        float x1 = row[hh * DH + d], x2 = row[hh * DH + d + 64];
        qf[(size_t)t * (HQ*DH) + hh * DH + d] =
            __float2half_rn((x1 * c[d] - x2 * s[d]) * SCALE_INV_SQRT_128);
        qf[(size_t)t * (HQ*DH) + hh * DH + d + 64] =
            __float2half_rn((x2 * c[d + 64] + x1 * s[d + 64]) * SCALE_INV_SQRT_128);
    }
    for (int i = threadIdx.x; i < HKV * 64; i += 256) {
        int hh = i >> 6, d = i & 63;
        float x1 = row[2048 + hh * DH + d], x2 = row[2048 + hh * DH + d + 64];
        kf[(size_t)t * (HKV*DH) + hh * DH + d] =
            __float2half_rn(x1 * c[d] - x2 * s[d]);
        kf[(size_t)t * (HKV*DH) + hh * DH + d + 64] =
            __float2half_rn(x2 * c[d + 64] + x1 * s[d + 64]);
    }
}

// ===== V transpose + fp16 =====
__global__ void vconvt_kernel(const float* __restrict__ qkv, __half* __restrict__ vt) {
    __shared__ float tile[32][33];
    int t0 = blockIdx.x * 32, d0 = blockIdx.y * 32, hk = blockIdx.z;
    for (int i = threadIdx.y; i < 32; i += 8)
        tile[i][threadIdx.x] = qkv[(size_t)(t0 + i) * NQKV + 2560 + hk * DH + d0 + threadIdx.x];
    __syncthreads();
    for (int i = threadIdx.y; i < 32; i += 8) {
        int d = d0 + i, t = t0 + threadIdx.x;
        vt[((size_t)hk * DH + d) * SEQ + t] = __float2half_rn(tile[threadIdx.x][i]);
    }
}

// ================= fp16 tensor-core block-sparse flash attention =================
#define QKP 136
#define VTP 72
#define PSP 72
#define FS_OFF 62464
#define ATTN_SMEM (FS_OFF + 448*4)

__global__ void __launch_bounds__(256, 2) attn_kernel(
    const __half* __restrict__ qf, const __half* __restrict__ kf,
    const __half* __restrict__ vt,
    const unsigned char* __restrict__ keep, __half* __restrict__ oa2)
{
    extern __shared__ char smc[];
    __half* QS = (__half*)smc;
    __half* KS = QS + 64 * QKP;
    __half* VT = KS + 64 * QKP;
    __half* PS = VT + 128 * VTP;
    float* fs = (float*)(smc + FS_OFF);
    float* ARM = fs; float* ARL = fs + 128;
    float* ROWM = fs + 256; float* ROWL = fs + 320; float* ALF = fs + 384;

    const int qb = QBN - 1 - blockIdx.x;
    const int h = blockIdx.y;
    const int hk = h >> 2;
    const int tid = threadIdx.x;
    const int lane = tid & 31, wid = tid >> 5;
    const int rw = wid & 3, cw = wid >> 2;
    const int g = lane >> 2, qd = lane & 3;
    const int r0 = rw * 16 + g;
    const int r1 = r0 + 8;
    const int q2 = qd * 2;

    for (int i = tid; i < 64 * 16; i += 256) {
        int r = i >> 4, c = i & 15;
        *(uint4*)&QS[r * QKP + c * 8] =
            *(const uint4*)&qf[(size_t)(qb * 64 + r) * (HQ*DH) + h * DH + c * 8];
    }
    if (tid < 64) { ROWM[tid] = -1e30f; ROWL[tid] = 0.f; }

    float oacc[8][4];
#pragma unroll
    for (int i = 0; i < 8; i++)
#pragma unroll
        for (int j = 0; j < 4; j++) oacc[i][j] = 0.f;

    const unsigned char* krow = keep + ((size_t)h * QBN + qb) * QBN;

    for (int kb = 0; kb <= qb; kb++) {
        if (!krow[kb]) continue;
        __syncthreads();

        for (int i = tid; i < 64 * 16; i += 256) {
            int r = i >> 4, c = i & 15;
            *(uint4*)&KS[r * QKP + c * 8] =
                *(const uint4*)&kf[(size_t)(kb * 64 + r) * (HKV*DH) + hk * DH + c * 8];
        }
        for (int i = tid; i < 128 * 8; i += 256) {
            int d = i >> 3, c = i & 7;
            *(uint4*)&VT[d * VTP + c * 8] =
                *(const uint4*)&vt[((size_t)hk * DH + d) * SEQ + kb * 64 + c * 8];
        }
        __syncthreads();

        float sacc[4][4];
#pragma unroll
        for (int i = 0; i < 4; i++)
#pragma unroll
            for (int j = 0; j < 4; j++) sacc[i][j] = 0.f;

#pragma unroll
        for (int kc = 0; kc < 8; kc++) {
            const int k0 = kc * 16;
            uint32_t a[4];
            a[0] = *(const uint32_t*)&QS[r0 * QKP + k0 + q2];
            a[1] = *(const uint32_t*)&QS[r1 * QKP + k0 + q2];
            a[2] = *(const uint32_t*)&QS[r0 * QKP + k0 + q2 + 8];
            a[3] = *(const uint32_t*)&QS[r1 * QKP + k0 + q2 + 8];
#pragma unroll
            for (int nt = 0; nt < 4; nt++) {
                const int n = cw * 32 + nt * 8 + g;
                uint32_t b0 = *(const uint32_t*)&KS[n * QKP + k0 + q2];
                uint32_t b1 = *(const uint32_t*)&KS[n * QKP + k0 + q2 + 8];
                MMAF16(sacc[nt], a, b0, b1);
            }
        }

        if (kb == qb) {
#pragma unroll
            for (int nt = 0; nt < 4; nt++) {
                const int c0 = cw * 32 + nt * 8 + q2;
                if (c0 > r0)     sacc[nt][0] = -1e30f;
                if (c0 + 1 > r0) sacc[nt][1] = -1e30f;
                if (c0 > r1)     sacc[nt][2] = -1e30f;
                if (c0 + 1 > r1) sacc[nt][3] = -1e30f;
            }
        }

        float m0 = -1e30f, m1 = -1e30f;
#pragma unroll
        for (int nt = 0; nt < 4; nt++) {
            m0 = fmaxf(m0, fmaxf(sacc[nt][0], sacc[nt][1]));
            m1 = fmaxf(m1, fmaxf(sacc[nt][2], sacc[nt][3]));
        }
        m0 = fmaxf(m0, __shfl_xor_sync(0xffffffffu, m0, 1));
        m0 = fmaxf(m0, __shfl_xor_sync(0xffffffffu, m0, 2));
        m1 = fmaxf(m1, __shfl_xor_sync(0xffffffffu, m1, 1));
        m1 = fmaxf(m1, __shfl_xor_sync(0xffffffffu, m1, 2));
        if (qd == 0) {
            ARM[cw * 64 + r0] = m0;
            ARM[cw * 64 + r1] = m1;
        }
        __syncthreads();

        if (tid < 64) {
            float newm = fmaxf(ROWM[tid], fmaxf(ARM[tid], ARM[64 + tid]));
            ALF[tid] = __expf(ROWM[tid] - newm);
            ROWM[tid] = newm;
        }
        __syncthreads();

        const float nm0 = ROWM[r0];
        const float nm1 = ROWM[r1];
        float l0 = 0.f, l1 = 0.f;
#pragma unroll
        for (int nt = 0; nt < 4; nt++) {
            const int c0 = cw * 32 + nt * 8 + q2;
            float p0 = __expf(sacc[nt][0] - nm0);
            float p1 = __expf(sacc[nt][1] - nm0);
            float p2 = __expf(sacc[nt][2] - nm1);
            float p3 = __expf(sacc[nt][3] - nm1);
            l0 += p0 + p1; l1 += p2 + p3;
            *(__half2*)&PS[r0 * PSP + c0] = __floats2half2_rn(p0, p1);
            *(__half2*)&PS[r1 * PSP + c0] = __floats2half2_rn(p2, p3);
        }
        l0 += __shfl_xor_sync(0xffffffffu, l0, 1);
        l0 += __shfl_xor_sync(0xffffffffu, l0, 2);
        l1 += __shfl_xor_sync(0xffffffffu, l1, 1);
        l1 += __shfl_xor_sync(0xffffffffu, l1, 2);
        if (qd == 0) {
            ARL[cw * 64 + r0] = l0;
            ARL[cw * 64 + r1] = l1;
        }
        const float al0 = ALF[r0];
        const float al1 = ALF[r1];
#pragma unroll
        for (int nt = 0; nt < 8; nt++) {
            oacc[nt][0] *= al0; oacc[nt][1] *= al0;
            oacc[nt][2] *= al1; oacc[nt][3] *= al1;
        }
        __syncthreads();

        if (tid < 64)
            ROWL[tid] = ROWL[tid] * ALF[tid] + ARL[tid] + ARL[64 + tid];

#pragma unroll
        for (int kc = 0; kc < 4; kc++) {
            const int k0 = kc * 16;
            uint32_t a[4];
            a[0] = *(const uint32_t*)&PS[r0 * PSP + k0 + q2];
            a[1] = *(const uint32_t*)&PS[r1 * PSP + k0 + q2];
            a[2] = *(const uint32_t*)&PS[r0 * PSP + k0 + q2 + 8];
            a[3] = *(const uint32_t*)&PS[r1 * PSP + k0 + q2 + 8];
#pragma unroll
            for (int nt = 0; nt < 8; nt++) {
                const int n = cw * 64 + nt * 8 + g;
                uint32_t b0 = *(const uint32_t*)&VT[n * VTP + k0 + q2];
                uint32_t b1 = *(const uint32_t*)&VT[n * VTP + k0 + q2 + 8];
                MMAF16(oacc[nt], a, b0, b1);
            }
        }
    }

    __syncthreads();
    const float inv0 = 1.f / ROWL[r0];
    const float inv1 = 1.f / ROWL[r1];
    const size_t grow0 = (size_t)(qb * 64 + r0);
    const size_t grow1 = (size_t)(qb * 64 + r1);
#pragma unroll
    for (int nt = 0; nt < 8; nt++) {
        const int col = h * DH + cw * 64 + nt * 8 + q2;
        *(__half2*)(oa2 + grow0 * HID + col) =
            __floats2half2_rn(oacc[nt][0] * inv0, oacc[nt][1] * inv0);
        *(__half2*)(oa2 + grow1 * HID + col) =
            __floats2half2_rn(oacc[nt][2] * inv1, oacc[nt][3] * inv1);
    }
}

// ================= launch =================
extern "C" void kernel_launch(void* const* d_in, const int* in_sizes, int n_in,
                              void* d_out, int out_size) {
    const float* hidden = (const float*)d_in[0];
    const float* cosp   = (const float*)d_in[1];
    const float* sinp   = (const float*)d_in[2];
    const float* ln1    = (const float*)d_in[3];
    const float* ln2    = (const float*)d_in[4];
    const float* Wq     = (const float*)d_in[5];
    const float* bq     = (const float*)d_in[6];
    const float* Wk     = (const float*)d_in[7];
    const float* bk     = (const float*)d_in[8];
    const float* Wv     = (const float*)d_in[9];
    const float* bv     = (const float*)d_in[10];
    const float* Wo     = (const float*)d_in[11];
    const float* gWq    = (const float*)d_in[12];
    const float* gWk    = (const float*)d_in[13];
    const float* Wgate  = (const float*)d_in[14];
    const float* Wup    = (const float*)d_in[15];
    const float* Wdown  = (const float*)d_in[16];
    float* out = (float*)d_out;

    float *qkv, *qp, *kp, *qg, *kg, *h2;
    unsigned char* keep;
    __half *Wqkv2, *Wo2, *Wgu2, *Wd2, *ha2, *oa2, *h3a2, *gt2, *qf16, *kf16, *vt16;
    cudaGetSymbolAddress((void**)&qkv,  g_qkv);
    cudaGetSymbolAddress((void**)&qp,   g_qp);
    cudaGetSymbolAddress((void**)&kp,   g_kp);
    cudaGetSymbolAddress((void**)&qg,   g_qg);
    cudaGetSymbolAddress((void**)&kg,   g_kg);
    cudaGetSymbolAddress((void**)&keep, g_keep);
    cudaGetSymbolAddress((void**)&h2,   g_h2);
    cudaGetSymbolAddress((void**)&Wqkv2, g_Wqkv2);
    cudaGetSymbolAddress((void**)&Wo2,  g_Wo2);
    cudaGetSymbolAddress((void**)&Wgu2, g_Wgu2);
    cudaGetSymbolAddress((void**)&Wd2,  g_Wd2);
    cudaGetSymbolAddress((void**)&ha2,  g_ha2);
    cudaGetSymbolAddress((void**)&oa2,  g_oa2);
    cudaGetSymbolAddress((void**)&h3a2, g_h3a2);
    cudaGetSymbolAddress((void**)&gt2,  g_gt2);
    cudaGetSymbolAddress((void**)&qf16, g_qf16);
    cudaGetSymbolAddress((void**)&kf16, g_kf16);
    cudaGetSymbolAddress((void**)&vt16, g_vt16);

    cudaFuncSetAttribute(hgemm_kernel, cudaFuncAttributeMaxDynamicSharedMemorySize, HG_SMEM);
    cudaFuncSetAttribute(attn_kernel, cudaFuncAttributeMaxDynamicSharedMemorySize, ATTN_SMEM);

    dim3 w8(32, 8);
    cudaStream_t s2 = g_aux.s2;

    // ---- fork side stream: weight conversions + gate path off critical path ----
    cudaEventRecord(g_aux.root, 0);
    cudaStreamWaitEvent(s2, g_aux.root, 0);
    wconv3_kernel<<<dim3(NQKV/32, HID/32), w8, 0, s2>>>(Wq, Wk, Wv, Wqkv2);
    cudaEventRecord(g_aux.evQKV, s2);
    wconv_kernel<<<dim3(HID/32, HID/32), w8, 0, s2>>>(Wo, Wo2, HID, HID);
    cudaEventRecord(g_aux.evWo, s2);
    wconvGU_kernel<<<dim3(INTER/32, HID/32), w8, 0, s2>>>(Wgate, Wup, Wgu2);
    cudaEventRecord(g_aux.evGU, s2);
    wconv_kernel<<<dim3(HID/32, INTER/32), w8, 0, s2>>>(Wdown, Wd2, INTER, HID);
    cudaEventRecord(g_aux.evWd, s2);

    // ---- main chain ----
    rmsconv_kernel<<<SEQ, 256>>>(hidden, ln1, ha2, 2);
    cudaStreamWaitEvent(0, g_aux.evQKV, 0);
    hgemm_kernel<<<dim3(SEQ/128, NQKV/128), 256, HG_SMEM>>>(
        ha2, Wqkv2, bq, bk, bv, 2048, 2560, nullptr, qkv, nullptr, NQKV, HID, 2);

    // gate path on s2 overlapping rope/V conversions (qkv is never mutated)
    pool_kernel<<<dim3(QBN, HQ), DH>>>(qkv, NQKV, qp, HQ);
    pool_kernel<<<dim3(QBN, HKV), DH>>>(qkv + 2048, NQKV, kp, HKV);
    cudaEventRecord(g_aux.evPool, 0);
    cudaStreamWaitEvent(s2, g_aux.evPool, 0);
    sgemm_kernel<<<dim3(GHD/128, (QBN*HQ)/128), 256, 0, s2>>>(qp, gWq, qg, QBN*HQ, GHD, DH);
    sgemm_kernel<<<dim3(GHD/128, (QBN*HKV)/128), 256, 0, s2>>>(kp, gWk, kg, QBN*HKV, GHD, DH);
    gate_kernel<<<dim3(HQ, QBN), 32, 0, s2>>>(qg, kg, keep);
    cudaEventRecord(g_aux.evGate, s2);

    ropeconv_kernel<<<SEQ, 256>>>(qkv, cosp, sinp, qf16, kf16);
    vconvt_kernel<<<dim3(SEQ/32, DH/32, HKV), w8>>>(qkv, vt16);

    cudaStreamWaitEvent(0, g_aux.evGate, 0);
    attn_kernel<<<dim3(QBN, HQ), 256, ATTN_SMEM>>>(qf16, kf16, vt16, keep, oa2);

    cudaStreamWaitEvent(0, g_aux.evWo, 0);
    hgemm_kernel<<<dim3(SEQ/128, HID/128), 256, HG_SMEM>>>(
        oa2, Wo2, nullptr, nullptr, nullptr, HID, HID, hidden, h2, nullptr, HID, HQ*DH, 1);

    rmsconv_kernel<<<SEQ, 256>>>(h2, ln2, h3a2, 1);

    // gate|up GEMM with fused SiLU epilogue -> gt2 fp16
    cudaStreamWaitEvent(0, g_aux.evGU, 0);
    hgemm_kernel<<<dim3(SEQ/128, NGU/128), 256, HG_SMEM>>>(
        h3a2, Wgu2, nullptr, nullptr, nullptr, NGU, NGU, nullptr, nullptr, gt2, NGU, HID, 1);

    cudaStreamWaitEvent(0, g_aux.evWd, 0);
    hgemm_kernel<<<dim3(SEQ/128, HID/128), 256, HG_SMEM>>>(
        gt2, Wd2, nullptr, nullptr, nullptr, HID, HID, h2, out, nullptr, HID, INTER, 1);
}